// round 10
// baseline (speedup 1.0000x reference)
#include <cuda_runtime.h>
#include <cuda_bf16.h>
#include <math.h>
#include <stdint.h>

#define Nn   20000
#define Ee   320000
#define F_IN 512
#define HID  128
#define OUT  128
#define Hh   4
#define Cc   64
#define HC   256
#define TT   (Ee + Nn)   // edges incl. self loops

// ---------------- scratch (static device globals; no allocation) -------------
__device__ __align__(16) __nv_bfloat16 g_h1hi[Nn * HID];
__device__ __align__(16) __nv_bfloat16 g_h1lo[Nn * HID];
__device__ __align__(16) __nv_bfloat16 g_h2hi[Nn * OUT];
__device__ __align__(16) __nv_bfloat16 g_h2lo[Nn * OUT];
__device__ __align__(16) __nv_bfloat16 g_w1thi[HID * F_IN];
__device__ __align__(16) __nv_bfloat16 g_w1tlo[HID * F_IN];
__device__ __align__(16) __nv_bfloat16 g_w2thi[OUT * HID];
__device__ __align__(16) __nv_bfloat16 g_w2tlo[OUT * HID];
__device__ __align__(16) __nv_bfloat16 g_wgthi[HC * OUT];
__device__ __align__(16) __nv_bfloat16 g_wgtlo[HC * OUT];
__device__ __align__(16) float g_xg[Nn * HC];
__device__ __align__(16) float g_asrc[Nn * Hh];
__device__ __align__(16) float g_adst[Nn * Hh];
__device__ __align__(16) float g_alpha[TT * Hh];
__device__ int g_cnt[Nn];
__device__ int g_off[Nn];
__device__ int g_cur[Nn];
__device__ int g_csr[TT];

// ---------------- mma / ldmatrix helpers ---------------------------------------
__device__ __forceinline__ uint32_t s2u(const void* p) {
    return (uint32_t)__cvta_generic_to_shared(p);
}

__device__ __forceinline__ void ldm_x4(uint32_t* r, uint32_t addr) {
    asm volatile("ldmatrix.sync.aligned.m8n8.x4.shared.b16 {%0,%1,%2,%3}, [%4];"
                 : "=r"(r[0]), "=r"(r[1]), "=r"(r[2]), "=r"(r[3]) : "r"(addr));
}
__device__ __forceinline__ void ldm_x2(uint32_t* r, uint32_t addr) {
    asm volatile("ldmatrix.sync.aligned.m8n8.x2.shared.b16 {%0,%1}, [%2];"
                 : "=r"(r[0]), "=r"(r[1]) : "r"(addr));
}

__device__ __forceinline__ void mma_bf16(float* c, const uint32_t* a, const uint32_t* b) {
    asm volatile("mma.sync.aligned.m16n8k16.row.col.f32.bf16.bf16.f32 "
                 "{%0,%1,%2,%3}, {%4,%5,%6,%7}, {%8,%9}, {%0,%1,%2,%3};"
                 : "+f"(c[0]), "+f"(c[1]), "+f"(c[2]), "+f"(c[3])
                 : "r"(a[0]), "r"(a[1]), "r"(a[2]), "r"(a[3]), "r"(b[0]), "r"(b[1]));
}

// split 8 fp32 -> 8 bf16 hi + 8 bf16 lo (packed into uint4 each)
__device__ __forceinline__ void split8(float4 a, float4 b, uint4& vh, uint4& vl) {
    const float f[8] = {a.x, a.y, a.z, a.w, b.x, b.y, b.z, b.w};
    uint32_t hw[4], lw[4];
#pragma unroll
    for (int i = 0; i < 4; i++) {
        const __nv_bfloat16 h0 = __float2bfloat16(f[2 * i]);
        const __nv_bfloat16 h1 = __float2bfloat16(f[2 * i + 1]);
        __nv_bfloat162 hp = __halves2bfloat162(h0, h1);
        hw[i] = *(uint32_t*)&hp;
        __nv_bfloat162 lp = __halves2bfloat162(
            __float2bfloat16(f[2 * i]     - __bfloat162float(h0)),
            __float2bfloat16(f[2 * i + 1] - __bfloat162float(h1)));
        lw[i] = *(uint32_t*)&lp;
    }
    vh = make_uint4(hw[0], hw[1], hw[2], hw[3]);
    vl = make_uint4(lw[0], lw[1], lw[2], lw[3]);
}

// ============ bf16x3 GEMM: C = op(A @ B^T + bias), fp32-class accuracy =========
// ASPLIT: A fp32, split hi/lo inline during tile fill (same bytes per thread).
template<bool RELU, bool HAS_BIAS, bool OSPLIT, bool ASPLIT>
__global__ __launch_bounds__(256)
void bf16gemm(const float* __restrict__ Af,
              const __nv_bfloat16* __restrict__ Ahi,
              const __nv_bfloat16* __restrict__ Alo,
              const __nv_bfloat16* __restrict__ Bhi,
              const __nv_bfloat16* __restrict__ Blo,
              const float* __restrict__ bias,
              float* __restrict__ Cf,
              __nv_bfloat16* __restrict__ Chi,
              __nv_bfloat16* __restrict__ Clo,
              int M, int Nc, int K) {
    __shared__ __nv_bfloat16 Ash[128][40];   // +8 pad
    __shared__ __nv_bfloat16 Asl[128][40];
    __shared__ __nv_bfloat16 Bsh[128][40];
    __shared__ __nv_bfloat16 Bsl[128][40];

    const int tid  = threadIdx.x;
    const int lane = tid & 31;
    const int warp = tid >> 5;
    const int wm = warp & 1;          // 0..1 -> 64 rows
    const int wn = warp >> 1;         // 0..3 -> 32 cols
    const int g  = lane >> 2;         // 0..7
    const int t  = lane & 3;          // 0..3

    const int rowBase = blockIdx.y * 128;
    const int colBase = blockIdx.x * 128;

    float acc[4][4][4];
#pragma unroll
    for (int i = 0; i < 4; i++)
#pragma unroll
        for (int j = 0; j < 4; j++)
#pragma unroll
            for (int q = 0; q < 4; q++) acc[i][j][q] = 0.f;

    const int a_row = (lane & 7) + ((lane >> 3) & 1) * 8;   // 0..15
    const int a_kof = (lane >> 4) * 8;                      // 0 or 8
    const int b_row = lane & 7;
    const int b_kof = ((lane >> 3) & 1) * 8;

    for (int kt = 0; kt < K; kt += 32) {
#pragma unroll
        for (int c = 0; c < 2; c++) {
            const int id   = tid + c * 256;
            const int row  = id >> 2;
            const int part = (id & 3) * 8;
            const int gr   = rowBase + row;
            uint4 vh = make_uint4(0u, 0u, 0u, 0u), vl = vh;
            if (gr < M) {
                if (ASPLIT) {
                    const float* ap = Af + (size_t)gr * K + kt + part;
                    split8(*(const float4*)ap, *(const float4*)(ap + 4), vh, vl);
                } else {
                    vh = *(const uint4*)(Ahi + (size_t)gr * K + kt + part);
                    vl = *(const uint4*)(Alo + (size_t)gr * K + kt + part);
                }
            }
            *(uint4*)&Ash[row][part] = vh;
            *(uint4*)&Asl[row][part] = vl;
            const int gn = colBase + row;
            *(uint4*)&Bsh[row][part] = *(const uint4*)(Bhi + (size_t)gn * K + kt + part);
            *(uint4*)&Bsl[row][part] = *(const uint4*)(Blo + (size_t)gn * K + kt + part);
        }
        __syncthreads();

#pragma unroll
        for (int ka = 0; ka < 2; ka++) {
            const int k0 = ka * 16;
            uint32_t bhi[4][2], blo[4][2];
#pragma unroll
            for (int na = 0; na < 4; na++) {
                const int n0 = wn * 32 + na * 8;
                ldm_x2(bhi[na], s2u(&Bsh[n0 + b_row][k0 + b_kof]));
                ldm_x2(blo[na], s2u(&Bsl[n0 + b_row][k0 + b_kof]));
            }
#pragma unroll
            for (int ma = 0; ma < 4; ma++) {
                const int m0 = wm * 64 + ma * 16;
                uint32_t ahi[4], alo[4];
                ldm_x4(ahi, s2u(&Ash[m0 + a_row][k0 + a_kof]));
                ldm_x4(alo, s2u(&Asl[m0 + a_row][k0 + a_kof]));
#pragma unroll
                for (int na = 0; na < 4; na++) {
                    mma_bf16(acc[ma][na], ahi, bhi[na]);
                    mma_bf16(acc[ma][na], alo, bhi[na]);
                    mma_bf16(acc[ma][na], ahi, blo[na]);
                }
            }
        }
        __syncthreads();
    }

    // ---- epilogue: c0,c1 -> (row g, col 2t), c2,c3 -> (row g+8, col 2t) ----
#pragma unroll
    for (int na = 0; na < 4; na++) {
        const int c = colBase + wn * 32 + na * 8 + 2 * t;
        float2 bb = make_float2(0.f, 0.f);
        if (HAS_BIAS) bb = *(const float2*)(bias + c);
#pragma unroll
        for (int ma = 0; ma < 4; ma++) {
            const int r0 = rowBase + wm * 64 + ma * 16 + g;
            float v0 = acc[ma][na][0] + bb.x;
            float v1 = acc[ma][na][1] + bb.y;
            float v2 = acc[ma][na][2] + bb.x;
            float v3 = acc[ma][na][3] + bb.y;
            if (RELU) {
                v0 = fmaxf(v0, 0.f); v1 = fmaxf(v1, 0.f);
                v2 = fmaxf(v2, 0.f); v3 = fmaxf(v3, 0.f);
            }
            if (OSPLIT) {
                if (r0 < M) {
                    const __nv_bfloat16 h0 = __float2bfloat16(v0);
                    const __nv_bfloat16 h1 = __float2bfloat16(v1);
                    *(__nv_bfloat162*)(Chi + (size_t)r0 * Nc + c) = __halves2bfloat162(h0, h1);
                    *(__nv_bfloat162*)(Clo + (size_t)r0 * Nc + c) =
                        __halves2bfloat162(__float2bfloat16(v0 - __bfloat162float(h0)),
                                           __float2bfloat16(v1 - __bfloat162float(h1)));
                }
                if (r0 + 8 < M) {
                    const __nv_bfloat16 h2 = __float2bfloat16(v2);
                    const __nv_bfloat16 h3 = __float2bfloat16(v3);
                    *(__nv_bfloat162*)(Chi + (size_t)(r0 + 8) * Nc + c) = __halves2bfloat162(h2, h3);
                    *(__nv_bfloat162*)(Clo + (size_t)(r0 + 8) * Nc + c) =
                        __halves2bfloat162(__float2bfloat16(v2 - __bfloat162float(h2)),
                                           __float2bfloat16(v3 - __bfloat162float(h3)));
                }
            } else {
                if (r0 < M)     *(float2*)(Cf + (size_t)r0 * Nc + c)       = make_float2(v0, v1);
                if (r0 + 8 < M) *(float2*)(Cf + (size_t)(r0 + 8) * Nc + c) = make_float2(v2, v3);
            }
        }
    }
}

// ---------------- mega prep: edge count + all weight transposes/splits --------
__device__ __forceinline__ void wt_split_one(const float* __restrict__ W,
                                             __nv_bfloat16* __restrict__ thi,
                                             __nv_bfloat16* __restrict__ tlo,
                                             int K, int N, int i) {
    const int n = i / K, k = i % K;
    const float v = W[(size_t)k * N + n];
    const __nv_bfloat16 h = __float2bfloat16(v);
    thi[i] = h;
    tlo[i] = __float2bfloat16(v - __bfloat162float(h));
}

#define PREP_W1  (F_IN * HID)   // 65536
#define PREP_W2  (HID * OUT)    // 16384
#define PREP_WG  (OUT * HC)     // 32768
#define PREP_TOTAL (Ee + PREP_W1 + PREP_W2 + PREP_WG)

__global__ void mega_prep_kernel(const int* __restrict__ ei,
                                 const float* __restrict__ W1,
                                 const float* __restrict__ W2,
                                 const float* __restrict__ Wg) {
    int i = blockIdx.x * blockDim.x + threadIdx.x;
    if (i < Ee) { atomicAdd(&g_cnt[ei[Ee + i]], 1); return; }
    i -= Ee;
    if (i < PREP_W1) { wt_split_one(W1, g_w1thi, g_w1tlo, F_IN, HID, i); return; }
    i -= PREP_W1;
    if (i < PREP_W2) { wt_split_one(W2, g_w2thi, g_w2tlo, HID, OUT, i); return; }
    i -= PREP_W2;
    if (i < PREP_WG) { wt_split_one(Wg, g_wgthi, g_wgtlo, OUT, HC, i); }
}

// ---------------- scan: off = exclusive_sum(cnt+1); cnt <- cnt+1 ---------------
__global__ __launch_bounds__(1024)
void scan_kernel() {
    __shared__ int part[1024];
    const int t = threadIdx.x;
    const int CH = (Nn + 1023) / 1024;   // 20
    const int base = t * CH;
    int s = 0;
    for (int i = 0; i < CH; i++) {
        const int idx = base + i;
        if (idx < Nn) s += g_cnt[idx] + 1;   // +1 self loop
    }
    part[t] = s;
    __syncthreads();
    for (int off = 1; off < 1024; off <<= 1) {
        int v = 0;
        if (t >= off) v = part[t - off];
        __syncthreads();
        if (t >= off) part[t] += v;
        __syncthreads();
    }
    int run = (t == 0) ? 0 : part[t - 1];
    for (int i = 0; i < CH; i++) {
        const int idx = base + i;
        if (idx < Nn) {
            const int c = g_cnt[idx] + 1;
            g_off[idx] = run;
            g_cur[idx] = run;
            g_cnt[idx] = c;          // final degree
            run += c;
        }
    }
}

__global__ void scatter_kernel(const int* __restrict__ ei) {
    const int e = blockIdx.x * blockDim.x + threadIdx.x;
    if (e >= TT) return;
    int src, dst;
    if (e < Ee) { src = ei[e]; dst = ei[Ee + e]; }
    else        { src = dst = e - Ee; }
    const int pos = atomicAdd(&g_cur[dst], 1);
    g_csr[pos] = src;
}

// ---------------- attention coefficients --------------------------------------
__global__ void att_kernel(const float* __restrict__ att_src,
                           const float* __restrict__ att_dst) {
    const int warp = (blockIdx.x * blockDim.x + threadIdx.x) >> 5;
    const int lane = threadIdx.x & 31;
    if (warp >= Nn * Hh) return;
    const int n = warp >> 2;
    const int h = warp & 3;
    const float* xr = g_xg + (size_t)n * HC + h * Cc;
    const float v0 = xr[lane];
    const float v1 = xr[lane + 32];
    float ss = v0 * __ldg(att_src + h * Cc + lane) + v1 * __ldg(att_src + h * Cc + lane + 32);
    float sd = v0 * __ldg(att_dst + h * Cc + lane) + v1 * __ldg(att_dst + h * Cc + lane + 32);
#pragma unroll
    for (int o = 16; o > 0; o >>= 1) {
        ss += __shfl_down_sync(0xffffffffu, ss, o);
        sd += __shfl_down_sync(0xffffffffu, sd, o);
    }
    if (lane == 0) {
        g_asrc[n * Hh + h] = ss;
        g_adst[n * Hh + h] = sd;
    }
}

// ---------------- fused GAT softmax + aggregation: one warp per dst -----------
__global__ void gat_agg_kernel(float* __restrict__ out,
                               const float* __restrict__ bias_g) {
    const int d    = (blockIdx.x * blockDim.x + threadIdx.x) >> 5;
    const int lane = threadIdx.x & 31;
    if (d >= Nn) return;

    const int start = g_off[d];
    const int deg   = g_cnt[d];

    const float4 ad = *(const float4*)(g_adst + d * 4);

    // --- pass 1: exp cache + denominators ---
    float4 sum = make_float4(0.f, 0.f, 0.f, 0.f);
    for (int k = lane; k < deg; k += 32) {
        const int s = g_csr[start + k];
        const float4 as = *(const float4*)(g_asrc + s * 4);
        float ex = as.x + ad.x, ey = as.y + ad.y, ez = as.z + ad.z, ew = as.w + ad.w;
        ex = ex > 0.f ? ex : 0.2f * ex;
        ey = ey > 0.f ? ey : 0.2f * ey;
        ez = ez > 0.f ? ez : 0.2f * ez;
        ew = ew > 0.f ? ew : 0.2f * ew;
        const float4 exv = make_float4(__expf(ex), __expf(ey), __expf(ez), __expf(ew));
        *(float4*)(g_alpha + (size_t)(start + k) * 4) = exv;
        sum.x += exv.x; sum.y += exv.y; sum.z += exv.z; sum.w += exv.w;
    }
#pragma unroll
    for (int o = 16; o > 0; o >>= 1) {
        sum.x += __shfl_down_sync(0xffffffffu, sum.x, o);
        sum.y += __shfl_down_sync(0xffffffffu, sum.y, o);
        sum.z += __shfl_down_sync(0xffffffffu, sum.z, o);
        sum.w += __shfl_down_sync(0xffffffffu, sum.w, o);
    }
    const float dx = __shfl_sync(0xffffffffu, sum.x, 0) + 1e-16f;
    const float dy = __shfl_sync(0xffffffffu, sum.y, 0) + 1e-16f;
    const float dz = __shfl_sync(0xffffffffu, sum.z, 0) + 1e-16f;
    const float dw = __shfl_sync(0xffffffffu, sum.w, 0) + 1e-16f;

    const int h = lane >> 3;   // 8 lanes per head
    const float denom = (h == 0) ? dx : (h == 1) ? dy : (h == 2) ? dz : dw;
    const float rden  = 1.f / denom;

    float acc[8];
#pragma unroll
    for (int i = 0; i < 8; i++) acc[i] = 0.f;

    // --- pass 2: pure gather + FMA, 4x unrolled ---
    const float* al = g_alpha + (size_t)start * 4;
    int k = 0;
    for (; k + 4 <= deg; k += 4) {
        const int s0 = g_csr[start + k];
        const int s1 = g_csr[start + k + 1];
        const int s2 = g_csr[start + k + 2];
        const int s3 = g_csr[start + k + 3];
        const float a0 = al[(k    ) * 4 + h] * rden;
        const float a1 = al[(k + 1) * 4 + h] * rden;
        const float a2 = al[(k + 2) * 4 + h] * rden;
        const float a3 = al[(k + 3) * 4 + h] * rden;
        const float4* x0 = (const float4*)(g_xg + (size_t)s0 * HC + lane * 8);
        const float4* x1 = (const float4*)(g_xg + (size_t)s1 * HC + lane * 8);
        const float4* x2 = (const float4*)(g_xg + (size_t)s2 * HC + lane * 8);
        const float4* x3 = (const float4*)(g_xg + (size_t)s3 * HC + lane * 8);
        const float4 p0 = x0[0], q0 = x0[1];
        const float4 p1 = x1[0], q1 = x1[1];
        const float4 p2 = x2[0], q2 = x2[1];
        const float4 p3 = x3[0], q3 = x3[1];
        acc[0] = fmaf(a0, p0.x, fmaf(a1, p1.x, fmaf(a2, p2.x, fmaf(a3, p3.x, acc[0]))));
        acc[1] = fmaf(a0, p0.y, fmaf(a1, p1.y, fmaf(a2, p2.y, fmaf(a3, p3.y, acc[1]))));
        acc[2] = fmaf(a0, p0.z, fmaf(a1, p1.z, fmaf(a2, p2.z, fmaf(a3, p3.z, acc[2]))));
        acc[3] = fmaf(a0, p0.w, fmaf(a1, p1.w, fmaf(a2, p2.w, fmaf(a3, p3.w, acc[3]))));
        acc[4] = fmaf(a0, q0.x, fmaf(a1, q1.x, fmaf(a2, q2.x, fmaf(a3, q3.x, acc[4]))));
        acc[5] = fmaf(a0, q0.y, fmaf(a1, q1.y, fmaf(a2, q2.y, fmaf(a3, q3.y, acc[5]))));
        acc[6] = fmaf(a0, q0.z, fmaf(a1, q1.z, fmaf(a2, q2.z, fmaf(a3, q3.z, acc[6]))));
        acc[7] = fmaf(a0, q0.w, fmaf(a1, q1.w, fmaf(a2, q2.w, fmaf(a3, q3.w, acc[7]))));
    }
    for (; k < deg; k++) {
        const int s = g_csr[start + k];
        const float a = al[k * 4 + h] * rden;
        const float4* xr = (const float4*)(g_xg + (size_t)s * HC + lane * 8);
        const float4 v0 = xr[0];
        const float4 v1 = xr[1];
        acc[0] = fmaf(a, v0.x, acc[0]);
        acc[1] = fmaf(a, v0.y, acc[1]);
        acc[2] = fmaf(a, v0.z, acc[2]);
        acc[3] = fmaf(a, v0.w, acc[3]);
        acc[4] = fmaf(a, v1.x, acc[4]);
        acc[5] = fmaf(a, v1.y, acc[5]);
        acc[6] = fmaf(a, v1.z, acc[6]);
        acc[7] = fmaf(a, v1.w, acc[7]);
    }

    const float4 bg0 = *(const float4*)(bias_g + lane * 8);
    const float4 bg1 = *(const float4*)(bias_g + lane * 8 + 4);
    float* op = out + (size_t)d * HC + lane * 8;
    *(float4*)op       = make_float4(acc[0] + bg0.x, acc[1] + bg0.y,
                                     acc[2] + bg0.z, acc[3] + bg0.w);
    *(float4*)(op + 4) = make_float4(acc[4] + bg1.x, acc[5] + bg1.y,
                                     acc[6] + bg1.z, acc[7] + bg1.w);
}

// ---------------- launch --------------------------------------------------------
extern "C" void kernel_launch(void* const* d_in, const int* in_sizes, int n_in,
                              void* d_out, int out_size) {
    const float* x   = (const float*)d_in[0];
    const int*   ei  = (const int*)d_in[1];
    const float* W1  = (const float*)d_in[2];
    const float* b1  = (const float*)d_in[3];
    const float* W2  = (const float*)d_in[4];
    const float* b2  = (const float*)d_in[5];
    const float* Wg  = (const float*)d_in[6];
    const float* att_src = (const float*)d_in[7];
    const float* att_dst = (const float*)d_in[8];
    const float* bias_g  = (const float*)d_in[9];
    float* out = (float*)d_out;

    __nv_bfloat16 *h1hi, *h1lo, *h2hi, *h2lo;
    __nv_bfloat16 *w1thi, *w1tlo, *w2thi, *w2tlo, *wgthi, *wgtlo;
    float* xg;
    int* cntp;
    cudaGetSymbolAddress((void**)&h1hi, g_h1hi);
    cudaGetSymbolAddress((void**)&h1lo, g_h1lo);
    cudaGetSymbolAddress((void**)&h2hi, g_h2hi);
    cudaGetSymbolAddress((void**)&h2lo, g_h2lo);
    cudaGetSymbolAddress((void**)&w1thi, g_w1thi);
    cudaGetSymbolAddress((void**)&w1tlo, g_w1tlo);
    cudaGetSymbolAddress((void**)&w2thi, g_w2thi);
    cudaGetSymbolAddress((void**)&w2tlo, g_w2tlo);
    cudaGetSymbolAddress((void**)&wgthi, g_wgthi);
    cudaGetSymbolAddress((void**)&wgtlo, g_wgtlo);
    cudaGetSymbolAddress((void**)&xg, g_xg);
    cudaGetSymbolAddress((void**)&cntp, g_cnt);

    const int mblk = (Nn + 127) / 128;   // 157

    // counts <- 0 (memset node), then edge-count + weight-splits in one kernel
    cudaMemsetAsync(cntp, 0, Nn * sizeof(int));
    mega_prep_kernel<<<(PREP_TOTAL + 255) / 256, 256>>>(ei, W1, W2, Wg);
    scan_kernel<<<1, 1024>>>();
    scatter_kernel<<<(TT + 255) / 256, 256>>>(ei);

    // GEMM chain (bf16x3 on mma.sync.m16n8k16); G1 splits x inline
    bf16gemm<true,  true,  true,  true ><<<dim3(1, mblk), 256>>>(
        x, nullptr, nullptr, w1thi, w1tlo, b1,
        nullptr, h1hi, h1lo, Nn, HID, F_IN);
    bf16gemm<false, true,  true,  false><<<dim3(1, mblk), 256>>>(
        nullptr, h1hi, h1lo, w2thi, w2tlo, b2,
        nullptr, h2hi, h2lo, Nn, OUT, HID);
    bf16gemm<false, false, false, false><<<dim3(2, mblk), 256>>>(
        nullptr, h2hi, h2lo, wgthi, wgtlo, nullptr,
        xg, nullptr, nullptr, Nn, HC, OUT);

    // attention coefficients
    att_kernel<<<(Nn * Hh + 7) / 8, 256>>>(att_src, att_dst);

    // fused softmax + aggregation
    gat_agg_kernel<<<(Nn + 7) / 8, 256>>>(out, bias_g);
}

// round 11
// speedup vs baseline: 1.2115x; 1.2115x over previous
#include <cuda_runtime.h>
#include <cuda_bf16.h>
#include <math.h>
#include <stdint.h>

#define Nn   20000
#define Ee   320000
#define F_IN 512
#define HID  128
#define OUT  128
#define Hh   4
#define Cc   64
#define HC   256
#define TT   (Ee + Nn)   // edges incl. self loops

// ---------------- scratch (static device globals; no allocation) -------------
__device__ __align__(16) __nv_bfloat16 g_xhi[Nn * F_IN];
__device__ __align__(16) __nv_bfloat16 g_xlo[Nn * F_IN];
__device__ __align__(16) __nv_bfloat16 g_h1hi[Nn * HID];
__device__ __align__(16) __nv_bfloat16 g_h1lo[Nn * HID];
__device__ __align__(16) __nv_bfloat16 g_h2hi[Nn * OUT];
__device__ __align__(16) __nv_bfloat16 g_h2lo[Nn * OUT];
__device__ __align__(16) __nv_bfloat16 g_w1thi[HID * F_IN];
__device__ __align__(16) __nv_bfloat16 g_w1tlo[HID * F_IN];
__device__ __align__(16) __nv_bfloat16 g_w2thi[OUT * HID];
__device__ __align__(16) __nv_bfloat16 g_w2tlo[OUT * HID];
__device__ __align__(16) __nv_bfloat16 g_wgthi[HC * OUT];
__device__ __align__(16) __nv_bfloat16 g_wgtlo[HC * OUT];
__device__ __align__(16) float g_xg[Nn * HC];
__device__ __align__(16) float g_asrc[Nn * Hh];
__device__ __align__(16) float g_adst[Nn * Hh];
__device__ __align__(16) float g_alpha[TT * Hh];
__device__ int g_cnt[Nn];
__device__ int g_off[Nn];
__device__ int g_cur[Nn];
__device__ int g_csr[TT];

// ---------------- helpers -------------------------------------------------------
__device__ __forceinline__ uint32_t s2u(const void* p) {
    return (uint32_t)__cvta_generic_to_shared(p);
}

__device__ __forceinline__ void cp16(uint32_t dst, const void* src, int bytes) {
    asm volatile("cp.async.cg.shared.global [%0], [%1], 16, %2;"
                 :: "r"(dst), "l"(src), "r"(bytes) : "memory");
}

__device__ __forceinline__ void ldm_x4(uint32_t* r, uint32_t addr) {
    asm volatile("ldmatrix.sync.aligned.m8n8.x4.shared.b16 {%0,%1,%2,%3}, [%4];"
                 : "=r"(r[0]), "=r"(r[1]), "=r"(r[2]), "=r"(r[3]) : "r"(addr));
}
__device__ __forceinline__ void ldm_x2(uint32_t* r, uint32_t addr) {
    asm volatile("ldmatrix.sync.aligned.m8n8.x2.shared.b16 {%0,%1}, [%2];"
                 : "=r"(r[0]), "=r"(r[1]) : "r"(addr));
}

__device__ __forceinline__ void mma_bf16(float* c, const uint32_t* a, const uint32_t* b) {
    asm volatile("mma.sync.aligned.m16n8k16.row.col.f32.bf16.bf16.f32 "
                 "{%0,%1,%2,%3}, {%4,%5,%6,%7}, {%8,%9}, {%0,%1,%2,%3};"
                 : "+f"(c[0]), "+f"(c[1]), "+f"(c[2]), "+f"(c[3])
                 : "r"(a[0]), "r"(a[1]), "r"(a[2]), "r"(a[3]), "r"(b[0]), "r"(b[1]));
}

// ============ bf16x3 GEMM, cp.async double-buffered pipeline ===================
// A pre-split bf16 hi/lo [M,K]; B pre-split+transposed [Nc,K].
// Block 128x128, BK=32; 8 warps 2(M)x4(N); warp tile 64x32.
// Dynamic smem: 2 stages x 4 matrices x 128 rows x 40 (padded) bf16 = 80 KB.
template<bool RELU, bool HAS_BIAS, bool OSPLIT>
__global__ __launch_bounds__(256)
void bf16gemm(const __nv_bfloat16* __restrict__ Ahi,
              const __nv_bfloat16* __restrict__ Alo,
              const __nv_bfloat16* __restrict__ Bhi,
              const __nv_bfloat16* __restrict__ Blo,
              const float* __restrict__ bias,
              float* __restrict__ Cf,
              __nv_bfloat16* __restrict__ Chi,
              __nv_bfloat16* __restrict__ Clo,
              int M, int Nc, int K) {
    extern __shared__ __nv_bfloat16 sm[];
    constexpr int PAD   = 40;
    constexpr int MATS  = 128 * PAD;     // elems per matrix tile
    constexpr int STAGE = 4 * MATS;      // elems per stage

    const int tid  = threadIdx.x;
    const int lane = tid & 31;
    const int warp = tid >> 5;
    const int wm = warp & 1;
    const int wn = warp >> 1;
    const int g  = lane >> 2;
    const int t  = lane & 3;

    const int rowBase = blockIdx.y * 128;
    const int colBase = blockIdx.x * 128;

    float acc[4][4][4];
#pragma unroll
    for (int i = 0; i < 4; i++)
#pragma unroll
        for (int j = 0; j < 4; j++)
#pragma unroll
            for (int q = 0; q < 4; q++) acc[i][j][q] = 0.f;

    const int a_row = (lane & 7) + ((lane >> 3) & 1) * 8;
    const int a_kof = (lane >> 4) * 8;
    const int b_row = lane & 7;
    const int b_kof = ((lane >> 3) & 1) * 8;

    // per-thread fill coordinates (2 ids per thread)
    const int id0_row = tid >> 2;
    const int id0_prt = (tid & 3) * 8;
    const int id1_row = (tid + 256) >> 2;
    const int id1_prt = ((tid + 256) & 3) * 8;

    auto fill = [&](int c, int b) {
        const int kt = c << 5;
        __nv_bfloat16* s0 = sm + b * STAGE;
#pragma unroll
        for (int q = 0; q < 2; q++) {
            const int row  = q ? id1_row : id0_row;
            const int part = q ? id1_prt : id0_prt;
            const int off  = row * PAD + part;
            const int gr   = rowBase + row;
            const int pr   = gr < M ? gr : M - 1;
            const int nb   = gr < M ? 16 : 0;
            cp16(s2u(s0 + off),            Ahi + (size_t)pr * K + kt + part, nb);
            cp16(s2u(s0 + MATS + off),     Alo + (size_t)pr * K + kt + part, nb);
            const int gn = colBase + row;
            cp16(s2u(s0 + 2 * MATS + off), Bhi + (size_t)gn * K + kt + part, 16);
            cp16(s2u(s0 + 3 * MATS + off), Blo + (size_t)gn * K + kt + part, 16);
        }
        asm volatile("cp.async.commit_group;" ::: "memory");
    };

    const int nch = K >> 5;
    fill(0, 0);

    for (int c = 0; c < nch; c++) {
        const int b = c & 1;
        if (c + 1 < nch) {
            fill(c + 1, b ^ 1);
            asm volatile("cp.async.wait_group 1;" ::: "memory");
        } else {
            asm volatile("cp.async.wait_group 0;" ::: "memory");
        }
        __syncthreads();

        const __nv_bfloat16* Ash = sm + b * STAGE;
        const __nv_bfloat16* Asl = Ash + MATS;
        const __nv_bfloat16* Bsh = Ash + 2 * MATS;
        const __nv_bfloat16* Bsl = Ash + 3 * MATS;

#pragma unroll
        for (int ka = 0; ka < 2; ka++) {
            const int k0 = ka * 16;
            uint32_t bhi[4][2], blo[4][2];
#pragma unroll
            for (int na = 0; na < 4; na++) {
                const int n0 = wn * 32 + na * 8;
                ldm_x2(bhi[na], s2u(Bsh + (n0 + b_row) * PAD + k0 + b_kof));
                ldm_x2(blo[na], s2u(Bsl + (n0 + b_row) * PAD + k0 + b_kof));
            }
#pragma unroll
            for (int ma = 0; ma < 4; ma++) {
                const int m0 = wm * 64 + ma * 16;
                uint32_t ahi[4], alo[4];
                ldm_x4(ahi, s2u(Ash + (m0 + a_row) * PAD + k0 + a_kof));
                ldm_x4(alo, s2u(Asl + (m0 + a_row) * PAD + k0 + a_kof));
#pragma unroll
                for (int na = 0; na < 4; na++) {
                    mma_bf16(acc[ma][na], ahi, bhi[na]);
                    mma_bf16(acc[ma][na], alo, bhi[na]);
                    mma_bf16(acc[ma][na], ahi, blo[na]);
                }
            }
        }
        __syncthreads();
    }

    // ---- epilogue ----
#pragma unroll
    for (int na = 0; na < 4; na++) {
        const int c = colBase + wn * 32 + na * 8 + 2 * t;
        float2 bb = make_float2(0.f, 0.f);
        if (HAS_BIAS) bb = *(const float2*)(bias + c);
#pragma unroll
        for (int ma = 0; ma < 4; ma++) {
            const int r0 = rowBase + wm * 64 + ma * 16 + g;
            float v0 = acc[ma][na][0] + bb.x;
            float v1 = acc[ma][na][1] + bb.y;
            float v2 = acc[ma][na][2] + bb.x;
            float v3 = acc[ma][na][3] + bb.y;
            if (RELU) {
                v0 = fmaxf(v0, 0.f); v1 = fmaxf(v1, 0.f);
                v2 = fmaxf(v2, 0.f); v3 = fmaxf(v3, 0.f);
            }
            if (OSPLIT) {
                if (r0 < M) {
                    const __nv_bfloat16 h0 = __float2bfloat16(v0);
                    const __nv_bfloat16 h1 = __float2bfloat16(v1);
                    *(__nv_bfloat162*)(Chi + (size_t)r0 * Nc + c) = __halves2bfloat162(h0, h1);
                    *(__nv_bfloat162*)(Clo + (size_t)r0 * Nc + c) =
                        __halves2bfloat162(__float2bfloat16(v0 - __bfloat162float(h0)),
                                           __float2bfloat16(v1 - __bfloat162float(h1)));
                }
                if (r0 + 8 < M) {
                    const __nv_bfloat16 h2 = __float2bfloat16(v2);
                    const __nv_bfloat16 h3 = __float2bfloat16(v3);
                    *(__nv_bfloat162*)(Chi + (size_t)(r0 + 8) * Nc + c) = __halves2bfloat162(h2, h3);
                    *(__nv_bfloat162*)(Clo + (size_t)(r0 + 8) * Nc + c) =
                        __halves2bfloat162(__float2bfloat16(v2 - __bfloat162float(h2)),
                                           __float2bfloat16(v3 - __bfloat162float(h3)));
                }
            } else {
                if (r0 < M)     *(float2*)(Cf + (size_t)r0 * Nc + c)       = make_float2(v0, v1);
                if (r0 + 8 < M) *(float2*)(Cf + (size_t)(r0 + 8) * Nc + c) = make_float2(v2, v3);
            }
        }
    }
}

// ---------------- prep: fp32 -> bf16 hi/lo split (x) ---------------------------
__global__ void split_kernel(const float* __restrict__ src,
                             __nv_bfloat16* __restrict__ hi,
                             __nv_bfloat16* __restrict__ lo, int n4) {
    const int i = blockIdx.x * blockDim.x + threadIdx.x;
    if (i >= n4) return;
    const float4 v = *(const float4*)(src + (size_t)i * 4);
    const __nv_bfloat16 h0 = __float2bfloat16(v.x), h1 = __float2bfloat16(v.y);
    const __nv_bfloat16 h2 = __float2bfloat16(v.z), h3 = __float2bfloat16(v.w);
    __nv_bfloat162* hp = (__nv_bfloat162*)(hi + (size_t)i * 4);
    hp[0] = __halves2bfloat162(h0, h1);
    hp[1] = __halves2bfloat162(h2, h3);
    __nv_bfloat162* lp = (__nv_bfloat162*)(lo + (size_t)i * 4);
    lp[0] = __halves2bfloat162(__float2bfloat16(v.x - __bfloat162float(h0)),
                               __float2bfloat16(v.y - __bfloat162float(h1)));
    lp[1] = __halves2bfloat162(__float2bfloat16(v.z - __bfloat162float(h2)),
                               __float2bfloat16(v.w - __bfloat162float(h3)));
}

// ---------------- mega prep: edge count + weight transposes/splits -------------
__device__ __forceinline__ void wt_split_one(const float* __restrict__ W,
                                             __nv_bfloat16* __restrict__ thi,
                                             __nv_bfloat16* __restrict__ tlo,
                                             int K, int N, int i) {
    const int n = i / K, k = i % K;
    const float v = W[(size_t)k * N + n];
    const __nv_bfloat16 h = __float2bfloat16(v);
    thi[i] = h;
    tlo[i] = __float2bfloat16(v - __bfloat162float(h));
}

#define PREP_W1  (F_IN * HID)
#define PREP_W2  (HID * OUT)
#define PREP_WG  (OUT * HC)
#define PREP_TOTAL (Ee + PREP_W1 + PREP_W2 + PREP_WG)

__global__ void mega_prep_kernel(const int* __restrict__ ei,
                                 const float* __restrict__ W1,
                                 const float* __restrict__ W2,
                                 const float* __restrict__ Wg) {
    int i = blockIdx.x * blockDim.x + threadIdx.x;
    if (i < Ee) { atomicAdd(&g_cnt[ei[Ee + i]], 1); return; }
    i -= Ee;
    if (i < PREP_W1) { wt_split_one(W1, g_w1thi, g_w1tlo, F_IN, HID, i); return; }
    i -= PREP_W1;
    if (i < PREP_W2) { wt_split_one(W2, g_w2thi, g_w2tlo, HID, OUT, i); return; }
    i -= PREP_W2;
    if (i < PREP_WG) { wt_split_one(Wg, g_wgthi, g_wgtlo, OUT, HC, i); }
}

// ---------------- scan: off = exclusive_sum(cnt+1); cnt <- cnt+1 ---------------
__global__ __launch_bounds__(1024)
void scan_kernel() {
    __shared__ int part[1024];
    const int t = threadIdx.x;
    const int CH = (Nn + 1023) / 1024;
    const int base = t * CH;
    int s = 0;
    for (int i = 0; i < CH; i++) {
        const int idx = base + i;
        if (idx < Nn) s += g_cnt[idx] + 1;
    }
    part[t] = s;
    __syncthreads();
    for (int off = 1; off < 1024; off <<= 1) {
        int v = 0;
        if (t >= off) v = part[t - off];
        __syncthreads();
        if (t >= off) part[t] += v;
        __syncthreads();
    }
    int run = (t == 0) ? 0 : part[t - 1];
    for (int i = 0; i < CH; i++) {
        const int idx = base + i;
        if (idx < Nn) {
            const int c = g_cnt[idx] + 1;
            g_off[idx] = run;
            g_cur[idx] = run;
            g_cnt[idx] = c;
            run += c;
        }
    }
}

__global__ void scatter_kernel(const int* __restrict__ ei) {
    const int e = blockIdx.x * blockDim.x + threadIdx.x;
    if (e >= TT) return;
    int src, dst;
    if (e < Ee) { src = ei[e]; dst = ei[Ee + e]; }
    else        { src = dst = e - Ee; }
    const int pos = atomicAdd(&g_cur[dst], 1);
    g_csr[pos] = src;
}

// ---------------- attention coefficients --------------------------------------
__global__ void att_kernel(const float* __restrict__ att_src,
                           const float* __restrict__ att_dst) {
    const int warp = (blockIdx.x * blockDim.x + threadIdx.x) >> 5;
    const int lane = threadIdx.x & 31;
    if (warp >= Nn * Hh) return;
    const int n = warp >> 2;
    const int h = warp & 3;
    const float* xr = g_xg + (size_t)n * HC + h * Cc;
    const float v0 = xr[lane];
    const float v1 = xr[lane + 32];
    float ss = v0 * __ldg(att_src + h * Cc + lane) + v1 * __ldg(att_src + h * Cc + lane + 32);
    float sd = v0 * __ldg(att_dst + h * Cc + lane) + v1 * __ldg(att_dst + h * Cc + lane + 32);
#pragma unroll
    for (int o = 16; o > 0; o >>= 1) {
        ss += __shfl_down_sync(0xffffffffu, ss, o);
        sd += __shfl_down_sync(0xffffffffu, sd, o);
    }
    if (lane == 0) {
        g_asrc[n * Hh + h] = ss;
        g_adst[n * Hh + h] = sd;
    }
}

// ---------------- fused GAT softmax + aggregation: one warp per dst -----------
__global__ void gat_agg_kernel(float* __restrict__ out,
                               const float* __restrict__ bias_g) {
    const int d    = (blockIdx.x * blockDim.x + threadIdx.x) >> 5;
    const int lane = threadIdx.x & 31;
    if (d >= Nn) return;

    const int start = g_off[d];
    const int deg   = g_cnt[d];

    const float4 ad = *(const float4*)(g_adst + d * 4);

    float4 sum = make_float4(0.f, 0.f, 0.f, 0.f);
    for (int k = lane; k < deg; k += 32) {
        const int s = g_csr[start + k];
        const float4 as = *(const float4*)(g_asrc + s * 4);
        float ex = as.x + ad.x, ey = as.y + ad.y, ez = as.z + ad.z, ew = as.w + ad.w;
        ex = ex > 0.f ? ex : 0.2f * ex;
        ey = ey > 0.f ? ey : 0.2f * ey;
        ez = ez > 0.f ? ez : 0.2f * ez;
        ew = ew > 0.f ? ew : 0.2f * ew;
        const float4 exv = make_float4(__expf(ex), __expf(ey), __expf(ez), __expf(ew));
        *(float4*)(g_alpha + (size_t)(start + k) * 4) = exv;
        sum.x += exv.x; sum.y += exv.y; sum.z += exv.z; sum.w += exv.w;
    }
#pragma unroll
    for (int o = 16; o > 0; o >>= 1) {
        sum.x += __shfl_down_sync(0xffffffffu, sum.x, o);
        sum.y += __shfl_down_sync(0xffffffffu, sum.y, o);
        sum.z += __shfl_down_sync(0xffffffffu, sum.z, o);
        sum.w += __shfl_down_sync(0xffffffffu, sum.w, o);
    }
    const float dx = __shfl_sync(0xffffffffu, sum.x, 0) + 1e-16f;
    const float dy = __shfl_sync(0xffffffffu, sum.y, 0) + 1e-16f;
    const float dz = __shfl_sync(0xffffffffu, sum.z, 0) + 1e-16f;
    const float dw = __shfl_sync(0xffffffffu, sum.w, 0) + 1e-16f;

    const int h = lane >> 3;
    const float denom = (h == 0) ? dx : (h == 1) ? dy : (h == 2) ? dz : dw;
    const float rden  = 1.f / denom;

    float acc[8];
#pragma unroll
    for (int i = 0; i < 8; i++) acc[i] = 0.f;

    const float* al = g_alpha + (size_t)start * 4;
    int k = 0;
    for (; k + 4 <= deg; k += 4) {
        const int s0 = g_csr[start + k];
        const int s1 = g_csr[start + k + 1];
        const int s2 = g_csr[start + k + 2];
        const int s3 = g_csr[start + k + 3];
        const float a0 = al[(k    ) * 4 + h] * rden;
        const float a1 = al[(k + 1) * 4 + h] * rden;
        const float a2 = al[(k + 2) * 4 + h] * rden;
        const float a3 = al[(k + 3) * 4 + h] * rden;
        const float4* x0 = (const float4*)(g_xg + (size_t)s0 * HC + lane * 8);
        const float4* x1 = (const float4*)(g_xg + (size_t)s1 * HC + lane * 8);
        const float4* x2 = (const float4*)(g_xg + (size_t)s2 * HC + lane * 8);
        const float4* x3 = (const float4*)(g_xg + (size_t)s3 * HC + lane * 8);
        const float4 p0 = x0[0], q0 = x0[1];
        const float4 p1 = x1[0], q1 = x1[1];
        const float4 p2 = x2[0], q2 = x2[1];
        const float4 p3 = x3[0], q3 = x3[1];
        acc[0] = fmaf(a0, p0.x, fmaf(a1, p1.x, fmaf(a2, p2.x, fmaf(a3, p3.x, acc[0]))));
        acc[1] = fmaf(a0, p0.y, fmaf(a1, p1.y, fmaf(a2, p2.y, fmaf(a3, p3.y, acc[1]))));
        acc[2] = fmaf(a0, p0.z, fmaf(a1, p1.z, fmaf(a2, p2.z, fmaf(a3, p3.z, acc[2]))));
        acc[3] = fmaf(a0, p0.w, fmaf(a1, p1.w, fmaf(a2, p2.w, fmaf(a3, p3.w, acc[3]))));
        acc[4] = fmaf(a0, q0.x, fmaf(a1, q1.x, fmaf(a2, q2.x, fmaf(a3, q3.x, acc[4]))));
        acc[5] = fmaf(a0, q0.y, fmaf(a1, q1.y, fmaf(a2, q2.y, fmaf(a3, q3.y, acc[5]))));
        acc[6] = fmaf(a0, q0.z, fmaf(a1, q1.z, fmaf(a2, q2.z, fmaf(a3, q3.z, acc[6]))));
        acc[7] = fmaf(a0, q0.w, fmaf(a1, q1.w, fmaf(a2, q2.w, fmaf(a3, q3.w, acc[7]))));
    }
    for (; k < deg; k++) {
        const int s = g_csr[start + k];
        const float a = al[k * 4 + h] * rden;
        const float4* xr = (const float4*)(g_xg + (size_t)s * HC + lane * 8);
        const float4 v0 = xr[0];
        const float4 v1 = xr[1];
        acc[0] = fmaf(a, v0.x, acc[0]);
        acc[1] = fmaf(a, v0.y, acc[1]);
        acc[2] = fmaf(a, v0.z, acc[2]);
        acc[3] = fmaf(a, v0.w, acc[3]);
        acc[4] = fmaf(a, v1.x, acc[4]);
        acc[5] = fmaf(a, v1.y, acc[5]);
        acc[6] = fmaf(a, v1.z, acc[6]);
        acc[7] = fmaf(a, v1.w, acc[7]);
    }

    const float4 bg0 = *(const float4*)(bias_g + lane * 8);
    const float4 bg1 = *(const float4*)(bias_g + lane * 8 + 4);
    float* op = out + (size_t)d * HC + lane * 8;
    *(float4*)op       = make_float4(acc[0] + bg0.x, acc[1] + bg0.y,
                                     acc[2] + bg0.z, acc[3] + bg0.w);
    *(float4*)(op + 4) = make_float4(acc[4] + bg1.x, acc[5] + bg1.y,
                                     acc[6] + bg1.z, acc[7] + bg1.w);
}

// ---------------- launch --------------------------------------------------------
extern "C" void kernel_launch(void* const* d_in, const int* in_sizes, int n_in,
                              void* d_out, int out_size) {
    const float* x   = (const float*)d_in[0];
    const int*   ei  = (const int*)d_in[1];
    const float* W1  = (const float*)d_in[2];
    const float* b1  = (const float*)d_in[3];
    const float* W2  = (const float*)d_in[4];
    const float* b2  = (const float*)d_in[5];
    const float* Wg  = (const float*)d_in[6];
    const float* att_src = (const float*)d_in[7];
    const float* att_dst = (const float*)d_in[8];
    const float* bias_g  = (const float*)d_in[9];
    float* out = (float*)d_out;

    __nv_bfloat16 *xhi, *xlo, *h1hi, *h1lo, *h2hi, *h2lo;
    __nv_bfloat16 *w1thi, *w1tlo, *w2thi, *w2tlo, *wgthi, *wgtlo;
    float* xg;
    int* cntp;
    cudaGetSymbolAddress((void**)&xhi,  g_xhi);
    cudaGetSymbolAddress((void**)&xlo,  g_xlo);
    cudaGetSymbolAddress((void**)&h1hi, g_h1hi);
    cudaGetSymbolAddress((void**)&h1lo, g_h1lo);
    cudaGetSymbolAddress((void**)&h2hi, g_h2hi);
    cudaGetSymbolAddress((void**)&h2lo, g_h2lo);
    cudaGetSymbolAddress((void**)&w1thi, g_w1thi);
    cudaGetSymbolAddress((void**)&w1tlo, g_w1tlo);
    cudaGetSymbolAddress((void**)&w2thi, g_w2thi);
    cudaGetSymbolAddress((void**)&w2tlo, g_w2tlo);
    cudaGetSymbolAddress((void**)&wgthi, g_wgthi);
    cudaGetSymbolAddress((void**)&wgtlo, g_wgtlo);
    cudaGetSymbolAddress((void**)&xg, g_xg);
    cudaGetSymbolAddress((void**)&cntp, g_cnt);

    const int SMEM = 2 * 4 * 128 * 40 * (int)sizeof(__nv_bfloat16);   // 81920
    cudaFuncSetAttribute(bf16gemm<true,  true,  true >,
                         cudaFuncAttributeMaxDynamicSharedMemorySize, SMEM);
    cudaFuncSetAttribute(bf16gemm<false, true,  true >,
                         cudaFuncAttributeMaxDynamicSharedMemorySize, SMEM);
    cudaFuncSetAttribute(bf16gemm<false, false, false>,
                         cudaFuncAttributeMaxDynamicSharedMemorySize, SMEM);

    const int mblk = (Nn + 127) / 128;   // 157

    // counts <- 0, then edge-count + weight-splits in one kernel
    cudaMemsetAsync(cntp, 0, Nn * sizeof(int));
    mega_prep_kernel<<<(PREP_TOTAL + 255) / 256, 256>>>(ei, W1, W2, Wg);
    scan_kernel<<<1, 1024>>>();
    scatter_kernel<<<(TT + 255) / 256, 256>>>(ei);

    // split x to bf16 hi/lo
    split_kernel<<<(Nn * F_IN / 4 + 255) / 256, 256>>>(x, xhi, xlo, Nn * F_IN / 4);

    // GEMM chain (bf16x3 on mma.sync.m16n8k16, cp.async pipelined)
    bf16gemm<true,  true,  true ><<<dim3(1, mblk), 256, SMEM>>>(
        xhi, xlo, w1thi, w1tlo, b1, nullptr, h1hi, h1lo, Nn, HID, F_IN);
    bf16gemm<false, true,  true ><<<dim3(1, mblk), 256, SMEM>>>(
        h1hi, h1lo, w2thi, w2tlo, b2, nullptr, h2hi, h2lo, Nn, OUT, HID);
    bf16gemm<false, false, false><<<dim3(2, mblk), 256, SMEM>>>(
        h2hi, h2lo, wgthi, wgtlo, nullptr, xg, nullptr, nullptr, Nn, HC, OUT);

    // attention coefficients
    att_kernel<<<(Nn * Hh + 7) / 8, 256>>>(att_src, att_dst);

    // fused softmax + aggregation
    gat_agg_kernel<<<(Nn + 7) / 8, 256>>>(out, bias_g);
}

// round 12
// speedup vs baseline: 1.2857x; 1.0612x over previous
#include <cuda_runtime.h>
#include <cuda_bf16.h>
#include <math.h>
#include <stdint.h>

#define Nn   20000
#define Ee   320000
#define F_IN 512
#define HID  128
#define OUT  128
#define Hh   4
#define Cc   64
#define HC   256
#define TT   (Ee + Nn)   // edges incl. self loops

// ---------------- scratch (static device globals; no allocation) -------------
__device__ __align__(16) __nv_bfloat16 g_xhi[Nn * F_IN];
__device__ __align__(16) __nv_bfloat16 g_xlo[Nn * F_IN];
__device__ __align__(16) __nv_bfloat16 g_h1hi[Nn * HID];
__device__ __align__(16) __nv_bfloat16 g_h1lo[Nn * HID];
__device__ __align__(16) __nv_bfloat16 g_h2hi[Nn * OUT];
__device__ __align__(16) __nv_bfloat16 g_h2lo[Nn * OUT];
__device__ __align__(16) __nv_bfloat16 g_w1thi[HID * F_IN];
__device__ __align__(16) __nv_bfloat16 g_w1tlo[HID * F_IN];
__device__ __align__(16) __nv_bfloat16 g_w2thi[OUT * HID];
__device__ __align__(16) __nv_bfloat16 g_w2tlo[OUT * HID];
__device__ __align__(16) __nv_bfloat16 g_wgthi[HC * OUT];
__device__ __align__(16) __nv_bfloat16 g_wgtlo[HC * OUT];
__device__ __align__(16) float g_xg[Nn * HC];
__device__ __align__(16) float g_asrc[Nn * Hh];
__device__ __align__(16) float g_adst[Nn * Hh];
__device__ __align__(16) float g_alpha[TT * Hh];
__device__ int g_cnt[Nn];
__device__ int g_off[Nn];
__device__ int g_cur[Nn];
__device__ int g_csr[TT];

// ---------------- helpers -------------------------------------------------------
__device__ __forceinline__ uint32_t s2u(const void* p) {
    return (uint32_t)__cvta_generic_to_shared(p);
}

__device__ __forceinline__ void cp16(uint32_t dst, const void* src, int bytes) {
    asm volatile("cp.async.cg.shared.global [%0], [%1], 16, %2;"
                 :: "r"(dst), "l"(src), "r"(bytes) : "memory");
}

__device__ __forceinline__ void ldm_x4(uint32_t* r, uint32_t addr) {
    asm volatile("ldmatrix.sync.aligned.m8n8.x4.shared.b16 {%0,%1,%2,%3}, [%4];"
                 : "=r"(r[0]), "=r"(r[1]), "=r"(r[2]), "=r"(r[3]) : "r"(addr));
}
__device__ __forceinline__ void ldm_x2(uint32_t* r, uint32_t addr) {
    asm volatile("ldmatrix.sync.aligned.m8n8.x2.shared.b16 {%0,%1}, [%2];"
                 : "=r"(r[0]), "=r"(r[1]) : "r"(addr));
}

__device__ __forceinline__ void mma_bf16(float* c, const uint32_t* a, const uint32_t* b) {
    asm volatile("mma.sync.aligned.m16n8k16.row.col.f32.bf16.bf16.f32 "
                 "{%0,%1,%2,%3}, {%4,%5,%6,%7}, {%8,%9}, {%0,%1,%2,%3};"
                 : "+f"(c[0]), "+f"(c[1]), "+f"(c[2]), "+f"(c[3])
                 : "r"(a[0]), "r"(a[1]), "r"(a[2]), "r"(a[3]), "r"(b[0]), "r"(b[1]));
}

// ============ bf16x3 GEMM, cp.async double-buffered, 2 CTAs/SM =================
// A pre-split bf16 hi/lo [M,K]; B pre-split+transposed [Nc,K].
// Block 128x128, BK=32; 8 warps 2(M)x4(N); warp tile 64x32.
// Dynamic smem: 2 stages x 4 matrices x 128 rows x 40 (padded) bf16 = 80 KB.
template<bool RELU, bool HAS_BIAS, bool OSPLIT>
__global__ __launch_bounds__(256, 2)
void bf16gemm(const __nv_bfloat16* __restrict__ Ahi,
              const __nv_bfloat16* __restrict__ Alo,
              const __nv_bfloat16* __restrict__ Bhi,
              const __nv_bfloat16* __restrict__ Blo,
              const float* __restrict__ bias,
              float* __restrict__ Cf,
              __nv_bfloat16* __restrict__ Chi,
              __nv_bfloat16* __restrict__ Clo,
              int M, int Nc, int K) {
    extern __shared__ __nv_bfloat16 sm[];
    constexpr int PAD   = 40;
    constexpr int MATS  = 128 * PAD;     // elems per matrix tile
    constexpr int STAGE = 4 * MATS;      // elems per stage

    const int tid  = threadIdx.x;
    const int lane = tid & 31;
    const int warp = tid >> 5;
    const int wm = warp & 1;
    const int wn = warp >> 1;
    const int g  = lane >> 2;
    const int t  = lane & 3;

    const int rowBase = blockIdx.y * 128;
    const int colBase = blockIdx.x * 128;

    float acc[4][4][4];
#pragma unroll
    for (int i = 0; i < 4; i++)
#pragma unroll
        for (int j = 0; j < 4; j++)
#pragma unroll
            for (int q = 0; q < 4; q++) acc[i][j][q] = 0.f;

    const int a_row = (lane & 7) + ((lane >> 3) & 1) * 8;
    const int a_kof = (lane >> 4) * 8;
    const int b_row = lane & 7;
    const int b_kof = ((lane >> 3) & 1) * 8;

    // per-thread fill coordinates (2 ids per thread)
    const int id0_row = tid >> 2;
    const int id0_prt = (tid & 3) * 8;
    const int id1_row = (tid + 256) >> 2;
    const int id1_prt = ((tid + 256) & 3) * 8;

    auto fill = [&](int c, int b) {
        const int kt = c << 5;
        __nv_bfloat16* s0 = sm + b * STAGE;
#pragma unroll
        for (int q = 0; q < 2; q++) {
            const int row  = q ? id1_row : id0_row;
            const int part = q ? id1_prt : id0_prt;
            const int off  = row * PAD + part;
            const int gr   = rowBase + row;
            const int pr   = gr < M ? gr : M - 1;
            const int nb   = gr < M ? 16 : 0;
            cp16(s2u(s0 + off),            Ahi + (size_t)pr * K + kt + part, nb);
            cp16(s2u(s0 + MATS + off),     Alo + (size_t)pr * K + kt + part, nb);
            const int gn = colBase + row;
            cp16(s2u(s0 + 2 * MATS + off), Bhi + (size_t)gn * K + kt + part, 16);
            cp16(s2u(s0 + 3 * MATS + off), Blo + (size_t)gn * K + kt + part, 16);
        }
        asm volatile("cp.async.commit_group;" ::: "memory");
    };

    const int nch = K >> 5;
    fill(0, 0);

    for (int c = 0; c < nch; c++) {
        const int b = c & 1;
        if (c + 1 < nch) {
            fill(c + 1, b ^ 1);
            asm volatile("cp.async.wait_group 1;" ::: "memory");
        } else {
            asm volatile("cp.async.wait_group 0;" ::: "memory");
        }
        __syncthreads();

        const __nv_bfloat16* Ash = sm + b * STAGE;
        const __nv_bfloat16* Asl = Ash + MATS;
        const __nv_bfloat16* Bsh = Ash + 2 * MATS;
        const __nv_bfloat16* Bsl = Ash + 3 * MATS;

#pragma unroll
        for (int ka = 0; ka < 2; ka++) {
            const int k0 = ka * 16;
            uint32_t bhi[4][2], blo[4][2];
#pragma unroll
            for (int na = 0; na < 4; na++) {
                const int n0 = wn * 32 + na * 8;
                ldm_x2(bhi[na], s2u(Bsh + (n0 + b_row) * PAD + k0 + b_kof));
                ldm_x2(blo[na], s2u(Bsl + (n0 + b_row) * PAD + k0 + b_kof));
            }
#pragma unroll
            for (int ma = 0; ma < 4; ma++) {
                const int m0 = wm * 64 + ma * 16;
                uint32_t ahi[4], alo[4];
                ldm_x4(ahi, s2u(Ash + (m0 + a_row) * PAD + k0 + a_kof));
                ldm_x4(alo, s2u(Asl + (m0 + a_row) * PAD + k0 + a_kof));
#pragma unroll
                for (int na = 0; na < 4; na++) {
                    mma_bf16(acc[ma][na], ahi, bhi[na]);
                    mma_bf16(acc[ma][na], alo, bhi[na]);
                    mma_bf16(acc[ma][na], ahi, blo[na]);
                }
            }
        }
        __syncthreads();
    }

    // ---- epilogue ----
#pragma unroll
    for (int na = 0; na < 4; na++) {
        const int c = colBase + wn * 32 + na * 8 + 2 * t;
        float2 bb = make_float2(0.f, 0.f);
        if (HAS_BIAS) bb = *(const float2*)(bias + c);
#pragma unroll
        for (int ma = 0; ma < 4; ma++) {
            const int r0 = rowBase + wm * 64 + ma * 16 + g;
            float v0 = acc[ma][na][0] + bb.x;
            float v1 = acc[ma][na][1] + bb.y;
            float v2 = acc[ma][na][2] + bb.x;
            float v3 = acc[ma][na][3] + bb.y;
            if (RELU) {
                v0 = fmaxf(v0, 0.f); v1 = fmaxf(v1, 0.f);
                v2 = fmaxf(v2, 0.f); v3 = fmaxf(v3, 0.f);
            }
            if (OSPLIT) {
                if (r0 < M) {
                    const __nv_bfloat16 h0 = __float2bfloat16(v0);
                    const __nv_bfloat16 h1 = __float2bfloat16(v1);
                    *(__nv_bfloat162*)(Chi + (size_t)r0 * Nc + c) = __halves2bfloat162(h0, h1);
                    *(__nv_bfloat162*)(Clo + (size_t)r0 * Nc + c) =
                        __halves2bfloat162(__float2bfloat16(v0 - __bfloat162float(h0)),
                                           __float2bfloat16(v1 - __bfloat162float(h1)));
                }
                if (r0 + 8 < M) {
                    const __nv_bfloat16 h2 = __float2bfloat16(v2);
                    const __nv_bfloat16 h3 = __float2bfloat16(v3);
                    *(__nv_bfloat162*)(Chi + (size_t)(r0 + 8) * Nc + c) = __halves2bfloat162(h2, h3);
                    *(__nv_bfloat162*)(Clo + (size_t)(r0 + 8) * Nc + c) =
                        __halves2bfloat162(__float2bfloat16(v2 - __bfloat162float(h2)),
                                           __float2bfloat16(v3 - __bfloat162float(h3)));
                }
            } else {
                if (r0 < M)     *(float2*)(Cf + (size_t)r0 * Nc + c)       = make_float2(v0, v1);
                if (r0 + 8 < M) *(float2*)(Cf + (size_t)(r0 + 8) * Nc + c) = make_float2(v2, v3);
            }
        }
    }
}

// ---------------- prep: fp32 -> bf16 hi/lo split (x) ---------------------------
__global__ void split_kernel(const float* __restrict__ src,
                             __nv_bfloat16* __restrict__ hi,
                             __nv_bfloat16* __restrict__ lo, int n4) {
    const int i = blockIdx.x * blockDim.x + threadIdx.x;
    if (i >= n4) return;
    const float4 v = *(const float4*)(src + (size_t)i * 4);
    const __nv_bfloat16 h0 = __float2bfloat16(v.x), h1 = __float2bfloat16(v.y);
    const __nv_bfloat16 h2 = __float2bfloat16(v.z), h3 = __float2bfloat16(v.w);
    __nv_bfloat162* hp = (__nv_bfloat162*)(hi + (size_t)i * 4);
    hp[0] = __halves2bfloat162(h0, h1);
    hp[1] = __halves2bfloat162(h2, h3);
    __nv_bfloat162* lp = (__nv_bfloat162*)(lo + (size_t)i * 4);
    lp[0] = __halves2bfloat162(__float2bfloat16(v.x - __bfloat162float(h0)),
                               __float2bfloat16(v.y - __bfloat162float(h1)));
    lp[1] = __halves2bfloat162(__float2bfloat16(v.z - __bfloat162float(h2)),
                               __float2bfloat16(v.w - __bfloat162float(h3)));
}

// ---------------- mega prep: edge count + weight transposes/splits -------------
__device__ __forceinline__ void wt_split_one(const float* __restrict__ W,
                                             __nv_bfloat16* __restrict__ thi,
                                             __nv_bfloat16* __restrict__ tlo,
                                             int K, int N, int i) {
    const int n = i / K, k = i % K;
    const float v = W[(size_t)k * N + n];
    const __nv_bfloat16 h = __float2bfloat16(v);
    thi[i] = h;
    tlo[i] = __float2bfloat16(v - __bfloat162float(h));
}

#define PREP_W1  (F_IN * HID)
#define PREP_W2  (HID * OUT)
#define PREP_WG  (OUT * HC)
#define PREP_TOTAL (Ee + PREP_W1 + PREP_W2 + PREP_WG)

__global__ void mega_prep_kernel(const int* __restrict__ ei,
                                 const float* __restrict__ W1,
                                 const float* __restrict__ W2,
                                 const float* __restrict__ Wg) {
    int i = blockIdx.x * blockDim.x + threadIdx.x;
    if (i < Ee) { atomicAdd(&g_cnt[ei[Ee + i]], 1); return; }
    i -= Ee;
    if (i < PREP_W1) { wt_split_one(W1, g_w1thi, g_w1tlo, F_IN, HID, i); return; }
    i -= PREP_W1;
    if (i < PREP_W2) { wt_split_one(W2, g_w2thi, g_w2tlo, HID, OUT, i); return; }
    i -= PREP_W2;
    if (i < PREP_WG) { wt_split_one(Wg, g_wgthi, g_wgtlo, OUT, HC, i); }
}

// ---------------- scan: off = exclusive_sum(cnt+1); cnt <- cnt+1 ---------------
__global__ __launch_bounds__(1024)
void scan_kernel() {
    __shared__ int part[1024];
    const int t = threadIdx.x;
    const int CH = (Nn + 1023) / 1024;
    const int base = t * CH;
    int s = 0;
    for (int i = 0; i < CH; i++) {
        const int idx = base + i;
        if (idx < Nn) s += g_cnt[idx] + 1;
    }
    part[t] = s;
    __syncthreads();
    for (int off = 1; off < 1024; off <<= 1) {
        int v = 0;
        if (t >= off) v = part[t - off];
        __syncthreads();
        if (t >= off) part[t] += v;
        __syncthreads();
    }
    int run = (t == 0) ? 0 : part[t - 1];
    for (int i = 0; i < CH; i++) {
        const int idx = base + i;
        if (idx < Nn) {
            const int c = g_cnt[idx] + 1;
            g_off[idx] = run;
            g_cur[idx] = run;
            g_cnt[idx] = c;
            run += c;
        }
    }
}

__global__ void scatter_kernel(const int* __restrict__ ei) {
    const int e = blockIdx.x * blockDim.x + threadIdx.x;
    if (e >= TT) return;
    int src, dst;
    if (e < Ee) { src = ei[e]; dst = ei[Ee + e]; }
    else        { src = dst = e - Ee; }
    const int pos = atomicAdd(&g_cur[dst], 1);
    g_csr[pos] = src;
}

// ---------------- attention coefficients --------------------------------------
__global__ void att_kernel(const float* __restrict__ att_src,
                           const float* __restrict__ att_dst) {
    const int warp = (blockIdx.x * blockDim.x + threadIdx.x) >> 5;
    const int lane = threadIdx.x & 31;
    if (warp >= Nn * Hh) return;
    const int n = warp >> 2;
    const int h = warp & 3;
    const float* xr = g_xg + (size_t)n * HC + h * Cc;
    const float v0 = xr[lane];
    const float v1 = xr[lane + 32];
    float ss = v0 * __ldg(att_src + h * Cc + lane) + v1 * __ldg(att_src + h * Cc + lane + 32);
    float sd = v0 * __ldg(att_dst + h * Cc + lane) + v1 * __ldg(att_dst + h * Cc + lane + 32);
#pragma unroll
    for (int o = 16; o > 0; o >>= 1) {
        ss += __shfl_down_sync(0xffffffffu, ss, o);
        sd += __shfl_down_sync(0xffffffffu, sd, o);
    }
    if (lane == 0) {
        g_asrc[n * Hh + h] = ss;
        g_adst[n * Hh + h] = sd;
    }
}

// ---------------- fused GAT softmax + aggregation: one warp per dst -----------
__global__ void gat_agg_kernel(float* __restrict__ out,
                               const float* __restrict__ bias_g) {
    const int d    = (blockIdx.x * blockDim.x + threadIdx.x) >> 5;
    const int lane = threadIdx.x & 31;
    if (d >= Nn) return;

    const int start = g_off[d];
    const int deg   = g_cnt[d];

    const float4 ad = *(const float4*)(g_adst + d * 4);

    float4 sum = make_float4(0.f, 0.f, 0.f, 0.f);
    for (int k = lane; k < deg; k += 32) {
        const int s = g_csr[start + k];
        const float4 as = *(const float4*)(g_asrc + s * 4);
        float ex = as.x + ad.x, ey = as.y + ad.y, ez = as.z + ad.z, ew = as.w + ad.w;
        ex = ex > 0.f ? ex : 0.2f * ex;
        ey = ey > 0.f ? ey : 0.2f * ey;
        ez = ez > 0.f ? ez : 0.2f * ez;
        ew = ew > 0.f ? ew : 0.2f * ew;
        const float4 exv = make_float4(__expf(ex), __expf(ey), __expf(ez), __expf(ew));
        *(float4*)(g_alpha + (size_t)(start + k) * 4) = exv;
        sum.x += exv.x; sum.y += exv.y; sum.z += exv.z; sum.w += exv.w;
    }
#pragma unroll
    for (int o = 16; o > 0; o >>= 1) {
        sum.x += __shfl_down_sync(0xffffffffu, sum.x, o);
        sum.y += __shfl_down_sync(0xffffffffu, sum.y, o);
        sum.z += __shfl_down_sync(0xffffffffu, sum.z, o);
        sum.w += __shfl_down_sync(0xffffffffu, sum.w, o);
    }
    const float dx = __shfl_sync(0xffffffffu, sum.x, 0) + 1e-16f;
    const float dy = __shfl_sync(0xffffffffu, sum.y, 0) + 1e-16f;
    const float dz = __shfl_sync(0xffffffffu, sum.z, 0) + 1e-16f;
    const float dw = __shfl_sync(0xffffffffu, sum.w, 0) + 1e-16f;

    const int h = lane >> 3;
    const float denom = (h == 0) ? dx : (h == 1) ? dy : (h == 2) ? dz : dw;
    const float rden  = 1.f / denom;

    float acc[8];
#pragma unroll
    for (int i = 0; i < 8; i++) acc[i] = 0.f;

    const float* al = g_alpha + (size_t)start * 4;
    int k = 0;
    for (; k + 4 <= deg; k += 4) {
        const int s0 = g_csr[start + k];
        const int s1 = g_csr[start + k + 1];
        const int s2 = g_csr[start + k + 2];
        const int s3 = g_csr[start + k + 3];
        const float a0 = al[(k    ) * 4 + h] * rden;
        const float a1 = al[(k + 1) * 4 + h] * rden;
        const float a2 = al[(k + 2) * 4 + h] * rden;
        const float a3 = al[(k + 3) * 4 + h] * rden;
        const float4* x0 = (const float4*)(g_xg + (size_t)s0 * HC + lane * 8);
        const float4* x1 = (const float4*)(g_xg + (size_t)s1 * HC + lane * 8);
        const float4* x2 = (const float4*)(g_xg + (size_t)s2 * HC + lane * 8);
        const float4* x3 = (const float4*)(g_xg + (size_t)s3 * HC + lane * 8);
        const float4 p0 = x0[0], q0 = x0[1];
        const float4 p1 = x1[0], q1 = x1[1];
        const float4 p2 = x2[0], q2 = x2[1];
        const float4 p3 = x3[0], q3 = x3[1];
        acc[0] = fmaf(a0, p0.x, fmaf(a1, p1.x, fmaf(a2, p2.x, fmaf(a3, p3.x, acc[0]))));
        acc[1] = fmaf(a0, p0.y, fmaf(a1, p1.y, fmaf(a2, p2.y, fmaf(a3, p3.y, acc[1]))));
        acc[2] = fmaf(a0, p0.z, fmaf(a1, p1.z, fmaf(a2, p2.z, fmaf(a3, p3.z, acc[2]))));
        acc[3] = fmaf(a0, p0.w, fmaf(a1, p1.w, fmaf(a2, p2.w, fmaf(a3, p3.w, acc[3]))));
        acc[4] = fmaf(a0, q0.x, fmaf(a1, q1.x, fmaf(a2, q2.x, fmaf(a3, q3.x, acc[4]))));
        acc[5] = fmaf(a0, q0.y, fmaf(a1, q1.y, fmaf(a2, q2.y, fmaf(a3, q3.y, acc[5]))));
        acc[6] = fmaf(a0, q0.z, fmaf(a1, q1.z, fmaf(a2, q2.z, fmaf(a3, q3.z, acc[6]))));
        acc[7] = fmaf(a0, q0.w, fmaf(a1, q1.w, fmaf(a2, q2.w, fmaf(a3, q3.w, acc[7]))));
    }
    for (; k < deg; k++) {
        const int s = g_csr[start + k];
        const float a = al[k * 4 + h] * rden;
        const float4* xr = (const float4*)(g_xg + (size_t)s * HC + lane * 8);
        const float4 v0 = xr[0];
        const float4 v1 = xr[1];
        acc[0] = fmaf(a, v0.x, acc[0]);
        acc[1] = fmaf(a, v0.y, acc[1]);
        acc[2] = fmaf(a, v0.z, acc[2]);
        acc[3] = fmaf(a, v0.w, acc[3]);
        acc[4] = fmaf(a, v1.x, acc[4]);
        acc[5] = fmaf(a, v1.y, acc[5]);
        acc[6] = fmaf(a, v1.z, acc[6]);
        acc[7] = fmaf(a, v1.w, acc[7]);
    }

    const float4 bg0 = *(const float4*)(bias_g + lane * 8);
    const float4 bg1 = *(const float4*)(bias_g + lane * 8 + 4);
    float* op = out + (size_t)d * HC + lane * 8;
    *(float4*)op       = make_float4(acc[0] + bg0.x, acc[1] + bg0.y,
                                     acc[2] + bg0.z, acc[3] + bg0.w);
    *(float4*)(op + 4) = make_float4(acc[4] + bg1.x, acc[5] + bg1.y,
                                     acc[6] + bg1.z, acc[7] + bg1.w);
}

// ---------------- launch --------------------------------------------------------
extern "C" void kernel_launch(void* const* d_in, const int* in_sizes, int n_in,
                              void* d_out, int out_size) {
    const float* x   = (const float*)d_in[0];
    const int*   ei  = (const int*)d_in[1];
    const float* W1  = (const float*)d_in[2];
    const float* b1  = (const float*)d_in[3];
    const float* W2  = (const float*)d_in[4];
    const float* b2  = (const float*)d_in[5];
    const float* Wg  = (const float*)d_in[6];
    const float* att_src = (const float*)d_in[7];
    const float* att_dst = (const float*)d_in[8];
    const float* bias_g  = (const float*)d_in[9];
    float* out = (float*)d_out;

    __nv_bfloat16 *xhi, *xlo, *h1hi, *h1lo, *h2hi, *h2lo;
    __nv_bfloat16 *w1thi, *w1tlo, *w2thi, *w2tlo, *wgthi, *wgtlo;
    float* xg;
    int* cntp;
    cudaGetSymbolAddress((void**)&xhi,  g_xhi);
    cudaGetSymbolAddress((void**)&xlo,  g_xlo);
    cudaGetSymbolAddress((void**)&h1hi, g_h1hi);
    cudaGetSymbolAddress((void**)&h1lo, g_h1lo);
    cudaGetSymbolAddress((void**)&h2hi, g_h2hi);
    cudaGetSymbolAddress((void**)&h2lo, g_h2lo);
    cudaGetSymbolAddress((void**)&w1thi, g_w1thi);
    cudaGetSymbolAddress((void**)&w1tlo, g_w1tlo);
    cudaGetSymbolAddress((void**)&w2thi, g_w2thi);
    cudaGetSymbolAddress((void**)&w2tlo, g_w2tlo);
    cudaGetSymbolAddress((void**)&wgthi, g_wgthi);
    cudaGetSymbolAddress((void**)&wgtlo, g_wgtlo);
    cudaGetSymbolAddress((void**)&xg, g_xg);
    cudaGetSymbolAddress((void**)&cntp, g_cnt);

    const int SMEM = 2 * 4 * 128 * 40 * (int)sizeof(__nv_bfloat16);   // 81920
    cudaFuncSetAttribute(bf16gemm<true,  true,  true >,
                         cudaFuncAttributeMaxDynamicSharedMemorySize, SMEM);
    cudaFuncSetAttribute(bf16gemm<false, true,  true >,
                         cudaFuncAttributeMaxDynamicSharedMemorySize, SMEM);
    cudaFuncSetAttribute(bf16gemm<false, false, false>,
                         cudaFuncAttributeMaxDynamicSharedMemorySize, SMEM);

    const int mblk = (Nn + 127) / 128;   // 157

    // counts <- 0, then edge-count + weight-splits in one kernel
    cudaMemsetAsync(cntp, 0, Nn * sizeof(int));
    mega_prep_kernel<<<(PREP_TOTAL + 255) / 256, 256>>>(ei, W1, W2, Wg);
    scan_kernel<<<1, 1024>>>();
    scatter_kernel<<<(TT + 255) / 256, 256>>>(ei);

    // split x to bf16 hi/lo
    split_kernel<<<(Nn * F_IN / 4 + 255) / 256, 256>>>(x, xhi, xlo, Nn * F_IN / 4);

    // GEMM chain (bf16x3 on mma.sync.m16n8k16, cp.async pipelined, 2 CTA/SM)
    bf16gemm<true,  true,  true ><<<dim3(1, mblk), 256, SMEM>>>(
        xhi, xlo, w1thi, w1tlo, b1, nullptr, h1hi, h1lo, Nn, HID, F_IN);
    bf16gemm<false, true,  true ><<<dim3(1, mblk), 256, SMEM>>>(
        h1hi, h1lo, w2thi, w2tlo, b2, nullptr, h2hi, h2lo, Nn, OUT, HID);
    bf16gemm<false, false, false><<<dim3(2, mblk), 256, SMEM>>>(
        h2hi, h2lo, wgthi, wgtlo, nullptr, xg, nullptr, nullptr, Nn, HC, OUT);

    // attention coefficients
    att_kernel<<<(Nn * Hh + 7) / 8, 256>>>(att_src, att_dst);

    // fused softmax + aggregation
    gat_agg_kernel<<<(Nn + 7) / 8, 256>>>(out, bias_g);
}

// round 13
// speedup vs baseline: 1.3265x; 1.0317x over previous
#include <cuda_runtime.h>
#include <cuda_bf16.h>
#include <math.h>
#include <stdint.h>

#define Nn   20000
#define Ee   320000
#define F_IN 512
#define HID  128
#define OUT  128
#define Hh   4
#define Cc   64
#define HC   256
#define TT   (Ee + Nn)   // edges incl. self loops

// ---------------- scratch (static device globals; no allocation) -------------
__device__ __align__(16) __nv_bfloat16 g_xhi[Nn * F_IN];
__device__ __align__(16) __nv_bfloat16 g_xlo[Nn * F_IN];
__device__ __align__(16) __nv_bfloat16 g_h1hi[Nn * HID];
__device__ __align__(16) __nv_bfloat16 g_h1lo[Nn * HID];
__device__ __align__(16) __nv_bfloat16 g_h2hi[Nn * OUT];
__device__ __align__(16) __nv_bfloat16 g_h2lo[Nn * OUT];
__device__ __align__(16) __nv_bfloat16 g_w1thi[HID * F_IN];
__device__ __align__(16) __nv_bfloat16 g_w1tlo[HID * F_IN];
__device__ __align__(16) __nv_bfloat16 g_w2thi[OUT * HID];
__device__ __align__(16) __nv_bfloat16 g_w2tlo[OUT * HID];
__device__ __align__(16) __nv_bfloat16 g_wgthi[HC * OUT];
__device__ __align__(16) __nv_bfloat16 g_wgtlo[HC * OUT];
__device__ __align__(16) float g_xg[Nn * HC];
__device__ __align__(16) float g_asrc[Nn * Hh];
__device__ __align__(16) float g_adst[Nn * Hh];
__device__ __align__(16) float g_alpha[TT * Hh];
__device__ int g_cnt[Nn];
__device__ int g_off[Nn];
__device__ int g_cur[Nn];
__device__ int g_csr[TT];

// ---------------- helpers -------------------------------------------------------
__device__ __forceinline__ uint32_t s2u(const void* p) {
    return (uint32_t)__cvta_generic_to_shared(p);
}

__device__ __forceinline__ void cp16(uint32_t dst, const void* src, int bytes) {
    asm volatile("cp.async.cg.shared.global [%0], [%1], 16, %2;"
                 :: "r"(dst), "l"(src), "r"(bytes) : "memory");
}

__device__ __forceinline__ void ldm_x4(uint32_t* r, uint32_t addr) {
    asm volatile("ldmatrix.sync.aligned.m8n8.x4.shared.b16 {%0,%1,%2,%3}, [%4];"
                 : "=r"(r[0]), "=r"(r[1]), "=r"(r[2]), "=r"(r[3]) : "r"(addr));
}
__device__ __forceinline__ void ldm_x2(uint32_t* r, uint32_t addr) {
    asm volatile("ldmatrix.sync.aligned.m8n8.x2.shared.b16 {%0,%1}, [%2];"
                 : "=r"(r[0]), "=r"(r[1]) : "r"(addr));
}

__device__ __forceinline__ void mma_bf16(float* c, const uint32_t* a, const uint32_t* b) {
    asm volatile("mma.sync.aligned.m16n8k16.row.col.f32.bf16.bf16.f32 "
                 "{%0,%1,%2,%3}, {%4,%5,%6,%7}, {%8,%9}, {%0,%1,%2,%3};"
                 : "+f"(c[0]), "+f"(c[1]), "+f"(c[2]), "+f"(c[3])
                 : "r"(a[0]), "r"(a[1]), "r"(a[2]), "r"(a[3]), "r"(b[0]), "r"(b[1]));
}

// ============ bf16x3 GEMM, cp.async double-buffered, 2 CTAs/SM =================
// ATT: epilogue additionally accumulates a_src/a_dst = einsum(C, att) via
// quad-shuffle + atomicAdd (G3 only; needs g_asrc/g_adst pre-zeroed).
template<bool RELU, bool HAS_BIAS, bool OSPLIT, bool ATT>
__global__ __launch_bounds__(256, 2)
void bf16gemm(const __nv_bfloat16* __restrict__ Ahi,
              const __nv_bfloat16* __restrict__ Alo,
              const __nv_bfloat16* __restrict__ Bhi,
              const __nv_bfloat16* __restrict__ Blo,
              const float* __restrict__ bias,
              float* __restrict__ Cf,
              __nv_bfloat16* __restrict__ Chi,
              __nv_bfloat16* __restrict__ Clo,
              const float* __restrict__ att_s,
              const float* __restrict__ att_d,
              int M, int Nc, int K) {
    extern __shared__ __nv_bfloat16 sm[];
    constexpr int PAD   = 40;
    constexpr int MATS  = 128 * PAD;
    constexpr int STAGE = 4 * MATS;

    const int tid  = threadIdx.x;
    const int lane = tid & 31;
    const int warp = tid >> 5;
    const int wm = warp & 1;
    const int wn = warp >> 1;
    const int g  = lane >> 2;
    const int t  = lane & 3;

    const int rowBase = blockIdx.y * 128;
    const int colBase = blockIdx.x * 128;

    float acc[4][4][4];
#pragma unroll
    for (int i = 0; i < 4; i++)
#pragma unroll
        for (int j = 0; j < 4; j++)
#pragma unroll
            for (int q = 0; q < 4; q++) acc[i][j][q] = 0.f;

    const int a_row = (lane & 7) + ((lane >> 3) & 1) * 8;
    const int a_kof = (lane >> 4) * 8;
    const int b_row = lane & 7;
    const int b_kof = ((lane >> 3) & 1) * 8;

    const int id0_row = tid >> 2;
    const int id0_prt = (tid & 3) * 8;
    const int id1_row = (tid + 256) >> 2;
    const int id1_prt = ((tid + 256) & 3) * 8;

    auto fill = [&](int c, int b) {
        const int kt = c << 5;
        __nv_bfloat16* s0 = sm + b * STAGE;
#pragma unroll
        for (int q = 0; q < 2; q++) {
            const int row  = q ? id1_row : id0_row;
            const int part = q ? id1_prt : id0_prt;
            const int off  = row * PAD + part;
            const int gr   = rowBase + row;
            const int pr   = gr < M ? gr : M - 1;
            const int nb   = gr < M ? 16 : 0;
            cp16(s2u(s0 + off),            Ahi + (size_t)pr * K + kt + part, nb);
            cp16(s2u(s0 + MATS + off),     Alo + (size_t)pr * K + kt + part, nb);
            const int gn = colBase + row;
            cp16(s2u(s0 + 2 * MATS + off), Bhi + (size_t)gn * K + kt + part, 16);
            cp16(s2u(s0 + 3 * MATS + off), Blo + (size_t)gn * K + kt + part, 16);
        }
        asm volatile("cp.async.commit_group;" ::: "memory");
    };

    const int nch = K >> 5;
    fill(0, 0);

    for (int c = 0; c < nch; c++) {
        const int b = c & 1;
        if (c + 1 < nch) {
            fill(c + 1, b ^ 1);
            asm volatile("cp.async.wait_group 1;" ::: "memory");
        } else {
            asm volatile("cp.async.wait_group 0;" ::: "memory");
        }
        __syncthreads();

        const __nv_bfloat16* Ash = sm + b * STAGE;
        const __nv_bfloat16* Asl = Ash + MATS;
        const __nv_bfloat16* Bsh = Ash + 2 * MATS;
        const __nv_bfloat16* Bsl = Ash + 3 * MATS;

#pragma unroll
        for (int ka = 0; ka < 2; ka++) {
            const int k0 = ka * 16;
            uint32_t bhi[4][2], blo[4][2];
#pragma unroll
            for (int na = 0; na < 4; na++) {
                const int n0 = wn * 32 + na * 8;
                ldm_x2(bhi[na], s2u(Bsh + (n0 + b_row) * PAD + k0 + b_kof));
                ldm_x2(blo[na], s2u(Bsl + (n0 + b_row) * PAD + k0 + b_kof));
            }
#pragma unroll
            for (int ma = 0; ma < 4; ma++) {
                const int m0 = wm * 64 + ma * 16;
                uint32_t ahi[4], alo[4];
                ldm_x4(ahi, s2u(Ash + (m0 + a_row) * PAD + k0 + a_kof));
                ldm_x4(alo, s2u(Asl + (m0 + a_row) * PAD + k0 + a_kof));
#pragma unroll
                for (int na = 0; na < 4; na++) {
                    mma_bf16(acc[ma][na], ahi, bhi[na]);
                    mma_bf16(acc[ma][na], alo, bhi[na]);
                    mma_bf16(acc[ma][na], ahi, blo[na]);
                }
            }
        }
        __syncthreads();
    }

    // ---- epilogue stores ----
#pragma unroll
    for (int na = 0; na < 4; na++) {
        const int c = colBase + wn * 32 + na * 8 + 2 * t;
        float2 bb = make_float2(0.f, 0.f);
        if (HAS_BIAS) bb = *(const float2*)(bias + c);
#pragma unroll
        for (int ma = 0; ma < 4; ma++) {
            const int r0 = rowBase + wm * 64 + ma * 16 + g;
            float v0 = acc[ma][na][0] + bb.x;
            float v1 = acc[ma][na][1] + bb.y;
            float v2 = acc[ma][na][2] + bb.x;
            float v3 = acc[ma][na][3] + bb.y;
            if (RELU) {
                v0 = fmaxf(v0, 0.f); v1 = fmaxf(v1, 0.f);
                v2 = fmaxf(v2, 0.f); v3 = fmaxf(v3, 0.f);
            }
            if (OSPLIT) {
                if (r0 < M) {
                    const __nv_bfloat16 h0 = __float2bfloat16(v0);
                    const __nv_bfloat16 h1 = __float2bfloat16(v1);
                    *(__nv_bfloat162*)(Chi + (size_t)r0 * Nc + c) = __halves2bfloat162(h0, h1);
                    *(__nv_bfloat162*)(Clo + (size_t)r0 * Nc + c) =
                        __halves2bfloat162(__float2bfloat16(v0 - __bfloat162float(h0)),
                                           __float2bfloat16(v1 - __bfloat162float(h1)));
                }
                if (r0 + 8 < M) {
                    const __nv_bfloat16 h2 = __float2bfloat16(v2);
                    const __nv_bfloat16 h3 = __float2bfloat16(v3);
                    *(__nv_bfloat162*)(Chi + (size_t)(r0 + 8) * Nc + c) = __halves2bfloat162(h2, h3);
                    *(__nv_bfloat162*)(Clo + (size_t)(r0 + 8) * Nc + c) =
                        __halves2bfloat162(__float2bfloat16(v2 - __bfloat162float(h2)),
                                           __float2bfloat16(v3 - __bfloat162float(h3)));
                }
            } else {
                if (r0 < M)     *(float2*)(Cf + (size_t)r0 * Nc + c)       = make_float2(v0, v1);
                if (r0 + 8 < M) *(float2*)(Cf + (size_t)(r0 + 8) * Nc + c) = make_float2(v2, v3);
            }
        }
    }

    // ---- fused attention coefficients (G3 only) ----
    if (ATT) {
        const int h = (colBase + wn * 32) >> 6;     // this warp's head
        float asv[4][2], adv[4][2];
#pragma unroll
        for (int na = 0; na < 4; na++) {
            const int cc = (wn * 32 + na * 8 + 2 * t) & 63;
            asv[na][0] = __ldg(att_s + h * Cc + cc);
            asv[na][1] = __ldg(att_s + h * Cc + cc + 1);
            adv[na][0] = __ldg(att_d + h * Cc + cc);
            adv[na][1] = __ldg(att_d + h * Cc + cc + 1);
        }
#pragma unroll
        for (int ma = 0; ma < 4; ma++) {
            const int r0 = rowBase + wm * 64 + ma * 16 + g;
            float ps0 = 0.f, pd0 = 0.f, ps1 = 0.f, pd1 = 0.f;
#pragma unroll
            for (int na = 0; na < 4; na++) {
                ps0 += acc[ma][na][0] * asv[na][0] + acc[ma][na][1] * asv[na][1];
                pd0 += acc[ma][na][0] * adv[na][0] + acc[ma][na][1] * adv[na][1];
                ps1 += acc[ma][na][2] * asv[na][0] + acc[ma][na][3] * asv[na][1];
                pd1 += acc[ma][na][2] * adv[na][0] + acc[ma][na][3] * adv[na][1];
            }
#pragma unroll
            for (int o = 2; o >= 1; o >>= 1) {
                ps0 += __shfl_down_sync(0xffffffffu, ps0, o);
                pd0 += __shfl_down_sync(0xffffffffu, pd0, o);
                ps1 += __shfl_down_sync(0xffffffffu, ps1, o);
                pd1 += __shfl_down_sync(0xffffffffu, pd1, o);
            }
            if (t == 0) {
                if (r0 < M) {
                    atomicAdd(&g_asrc[r0 * Hh + h], ps0);
                    atomicAdd(&g_adst[r0 * Hh + h], pd0);
                }
                if (r0 + 8 < M) {
                    atomicAdd(&g_asrc[(r0 + 8) * Hh + h], ps1);
                    atomicAdd(&g_adst[(r0 + 8) * Hh + h], pd1);
                }
            }
        }
    }
}

// ---------------- mega prep: edge count + weight splits + x split --------------
__device__ __forceinline__ void wt_split_one(const float* __restrict__ W,
                                             __nv_bfloat16* __restrict__ thi,
                                             __nv_bfloat16* __restrict__ tlo,
                                             int K, int N, int i) {
    const int n = i / K, k = i % K;
    const float v = W[(size_t)k * N + n];
    const __nv_bfloat16 h = __float2bfloat16(v);
    thi[i] = h;
    tlo[i] = __float2bfloat16(v - __bfloat162float(h));
}

#define PREP_W1  (F_IN * HID)
#define PREP_W2  (HID * OUT)
#define PREP_WG  (OUT * HC)
#define PREP_X4  (Nn * F_IN / 4)
#define PREP_TOTAL (Ee + PREP_W1 + PREP_W2 + PREP_WG + PREP_X4)

__global__ void mega_prep_kernel(const int* __restrict__ ei,
                                 const float* __restrict__ W1,
                                 const float* __restrict__ W2,
                                 const float* __restrict__ Wg,
                                 const float* __restrict__ x) {
    int i = blockIdx.x * blockDim.x + threadIdx.x;
    if (i < Ee) { atomicAdd(&g_cnt[ei[Ee + i]], 1); return; }
    i -= Ee;
    if (i < PREP_W1) { wt_split_one(W1, g_w1thi, g_w1tlo, F_IN, HID, i); return; }
    i -= PREP_W1;
    if (i < PREP_W2) { wt_split_one(W2, g_w2thi, g_w2tlo, HID, OUT, i); return; }
    i -= PREP_W2;
    if (i < PREP_WG) { wt_split_one(Wg, g_wgthi, g_wgtlo, OUT, HC, i); return; }
    i -= PREP_WG;
    if (i < PREP_X4) {
        const float4 v = *(const float4*)(x + (size_t)i * 4);
        const __nv_bfloat16 h0 = __float2bfloat16(v.x), h1 = __float2bfloat16(v.y);
        const __nv_bfloat16 h2 = __float2bfloat16(v.z), h3 = __float2bfloat16(v.w);
        __nv_bfloat162* hp = (__nv_bfloat162*)(g_xhi + (size_t)i * 4);
        hp[0] = __halves2bfloat162(h0, h1);
        hp[1] = __halves2bfloat162(h2, h3);
        __nv_bfloat162* lp = (__nv_bfloat162*)(g_xlo + (size_t)i * 4);
        lp[0] = __halves2bfloat162(__float2bfloat16(v.x - __bfloat162float(h0)),
                                   __float2bfloat16(v.y - __bfloat162float(h1)));
        lp[1] = __halves2bfloat162(__float2bfloat16(v.z - __bfloat162float(h2)),
                                   __float2bfloat16(v.w - __bfloat162float(h3)));
    }
}

// ---------------- scan: off = exclusive_sum(cnt+1); cnt <- cnt+1 ---------------
__global__ __launch_bounds__(1024)
void scan_kernel() {
    __shared__ int part[1024];
    const int t = threadIdx.x;
    const int CH = (Nn + 1023) / 1024;
    const int base = t * CH;
    int s = 0;
    for (int i = 0; i < CH; i++) {
        const int idx = base + i;
        if (idx < Nn) s += g_cnt[idx] + 1;
    }
    part[t] = s;
    __syncthreads();
    for (int off = 1; off < 1024; off <<= 1) {
        int v = 0;
        if (t >= off) v = part[t - off];
        __syncthreads();
        if (t >= off) part[t] += v;
        __syncthreads();
    }
    int run = (t == 0) ? 0 : part[t - 1];
    for (int i = 0; i < CH; i++) {
        const int idx = base + i;
        if (idx < Nn) {
            const int c = g_cnt[idx] + 1;
            g_off[idx] = run;
            g_cur[idx] = run;
            g_cnt[idx] = c;
            run += c;
        }
    }
}

__global__ void scatter_kernel(const int* __restrict__ ei) {
    const int e = blockIdx.x * blockDim.x + threadIdx.x;
    if (e >= TT) return;
    int src, dst;
    if (e < Ee) { src = ei[e]; dst = ei[Ee + e]; }
    else        { src = dst = e - Ee; }
    const int pos = atomicAdd(&g_cur[dst], 1);
    g_csr[pos] = src;
}

// ---------------- fused GAT softmax + aggregation: one warp per dst -----------
__global__ void gat_agg_kernel(float* __restrict__ out,
                               const float* __restrict__ bias_g) {
    const int d    = (blockIdx.x * blockDim.x + threadIdx.x) >> 5;
    const int lane = threadIdx.x & 31;
    if (d >= Nn) return;

    const int start = g_off[d];
    const int deg   = g_cnt[d];

    const float4 ad = *(const float4*)(g_adst + d * 4);

    float4 sum = make_float4(0.f, 0.f, 0.f, 0.f);
    for (int k = lane; k < deg; k += 32) {
        const int s = g_csr[start + k];
        const float4 as = *(const float4*)(g_asrc + s * 4);
        float ex = as.x + ad.x, ey = as.y + ad.y, ez = as.z + ad.z, ew = as.w + ad.w;
        ex = ex > 0.f ? ex : 0.2f * ex;
        ey = ey > 0.f ? ey : 0.2f * ey;
        ez = ez > 0.f ? ez : 0.2f * ez;
        ew = ew > 0.f ? ew : 0.2f * ew;
        const float4 exv = make_float4(__expf(ex), __expf(ey), __expf(ez), __expf(ew));
        *(float4*)(g_alpha + (size_t)(start + k) * 4) = exv;
        sum.x += exv.x; sum.y += exv.y; sum.z += exv.z; sum.w += exv.w;
    }
#pragma unroll
    for (int o = 16; o > 0; o >>= 1) {
        sum.x += __shfl_down_sync(0xffffffffu, sum.x, o);
        sum.y += __shfl_down_sync(0xffffffffu, sum.y, o);
        sum.z += __shfl_down_sync(0xffffffffu, sum.z, o);
        sum.w += __shfl_down_sync(0xffffffffu, sum.w, o);
    }
    const float dx = __shfl_sync(0xffffffffu, sum.x, 0) + 1e-16f;
    const float dy = __shfl_sync(0xffffffffu, sum.y, 0) + 1e-16f;
    const float dz = __shfl_sync(0xffffffffu, sum.z, 0) + 1e-16f;
    const float dw = __shfl_sync(0xffffffffu, sum.w, 0) + 1e-16f;

    const int h = lane >> 3;
    const float denom = (h == 0) ? dx : (h == 1) ? dy : (h == 2) ? dz : dw;
    const float rden  = 1.f / denom;

    float acc[8];
#pragma unroll
    for (int i = 0; i < 8; i++) acc[i] = 0.f;

    const float* al = g_alpha + (size_t)start * 4;
    int k = 0;
    for (; k + 4 <= deg; k += 4) {
        const int s0 = g_csr[start + k];
        const int s1 = g_csr[start + k + 1];
        const int s2 = g_csr[start + k + 2];
        const int s3 = g_csr[start + k + 3];
        const float a0 = al[(k    ) * 4 + h] * rden;
        const float a1 = al[(k + 1) * 4 + h] * rden;
        const float a2 = al[(k + 2) * 4 + h] * rden;
        const float a3 = al[(k + 3) * 4 + h] * rden;
        const float4* x0 = (const float4*)(g_xg + (size_t)s0 * HC + lane * 8);
        const float4* x1 = (const float4*)(g_xg + (size_t)s1 * HC + lane * 8);
        const float4* x2 = (const float4*)(g_xg + (size_t)s2 * HC + lane * 8);
        const float4* x3 = (const float4*)(g_xg + (size_t)s3 * HC + lane * 8);
        const float4 p0 = x0[0], q0 = x0[1];
        const float4 p1 = x1[0], q1 = x1[1];
        const float4 p2 = x2[0], q2 = x2[1];
        const float4 p3 = x3[0], q3 = x3[1];
        acc[0] = fmaf(a0, p0.x, fmaf(a1, p1.x, fmaf(a2, p2.x, fmaf(a3, p3.x, acc[0]))));
        acc[1] = fmaf(a0, p0.y, fmaf(a1, p1.y, fmaf(a2, p2.y, fmaf(a3, p3.y, acc[1]))));
        acc[2] = fmaf(a0, p0.z, fmaf(a1, p1.z, fmaf(a2, p2.z, fmaf(a3, p3.z, acc[2]))));
        acc[3] = fmaf(a0, p0.w, fmaf(a1, p1.w, fmaf(a2, p2.w, fmaf(a3, p3.w, acc[3]))));
        acc[4] = fmaf(a0, q0.x, fmaf(a1, q1.x, fmaf(a2, q2.x, fmaf(a3, q3.x, acc[4]))));
        acc[5] = fmaf(a0, q0.y, fmaf(a1, q1.y, fmaf(a2, q2.y, fmaf(a3, q3.y, acc[5]))));
        acc[6] = fmaf(a0, q0.z, fmaf(a1, q1.z, fmaf(a2, q2.z, fmaf(a3, q3.z, acc[6]))));
        acc[7] = fmaf(a0, q0.w, fmaf(a1, q1.w, fmaf(a2, q2.w, fmaf(a3, q3.w, acc[7]))));
    }
    for (; k < deg; k++) {
        const int s = g_csr[start + k];
        const float a = al[k * 4 + h] * rden;
        const float4* xr = (const float4*)(g_xg + (size_t)s * HC + lane * 8);
        const float4 v0 = xr[0];
        const float4 v1 = xr[1];
        acc[0] = fmaf(a, v0.x, acc[0]);
        acc[1] = fmaf(a, v0.y, acc[1]);
        acc[2] = fmaf(a, v0.z, acc[2]);
        acc[3] = fmaf(a, v0.w, acc[3]);
        acc[4] = fmaf(a, v1.x, acc[4]);
        acc[5] = fmaf(a, v1.y, acc[5]);
        acc[6] = fmaf(a, v1.z, acc[6]);
        acc[7] = fmaf(a, v1.w, acc[7]);
    }

    const float4 bg0 = *(const float4*)(bias_g + lane * 8);
    const float4 bg1 = *(const float4*)(bias_g + lane * 8 + 4);
    float* op = out + (size_t)d * HC + lane * 8;
    *(float4*)op       = make_float4(acc[0] + bg0.x, acc[1] + bg0.y,
                                     acc[2] + bg0.z, acc[3] + bg0.w);
    *(float4*)(op + 4) = make_float4(acc[4] + bg1.x, acc[5] + bg1.y,
                                     acc[6] + bg1.z, acc[7] + bg1.w);
}

// ---------------- launch --------------------------------------------------------
extern "C" void kernel_launch(void* const* d_in, const int* in_sizes, int n_in,
                              void* d_out, int out_size) {
    const float* x   = (const float*)d_in[0];
    const int*   ei  = (const int*)d_in[1];
    const float* W1  = (const float*)d_in[2];
    const float* b1  = (const float*)d_in[3];
    const float* W2  = (const float*)d_in[4];
    const float* b2  = (const float*)d_in[5];
    const float* Wg  = (const float*)d_in[6];
    const float* att_src = (const float*)d_in[7];
    const float* att_dst = (const float*)d_in[8];
    const float* bias_g  = (const float*)d_in[9];
    float* out = (float*)d_out;

    __nv_bfloat16 *xhi, *xlo, *h1hi, *h1lo, *h2hi, *h2lo;
    __nv_bfloat16 *w1thi, *w1tlo, *w2thi, *w2tlo, *wgthi, *wgtlo;
    float *xg, *asrcp, *adstp;
    int* cntp;
    cudaGetSymbolAddress((void**)&xhi,  g_xhi);
    cudaGetSymbolAddress((void**)&xlo,  g_xlo);
    cudaGetSymbolAddress((void**)&h1hi, g_h1hi);
    cudaGetSymbolAddress((void**)&h1lo, g_h1lo);
    cudaGetSymbolAddress((void**)&h2hi, g_h2hi);
    cudaGetSymbolAddress((void**)&h2lo, g_h2lo);
    cudaGetSymbolAddress((void**)&w1thi, g_w1thi);
    cudaGetSymbolAddress((void**)&w1tlo, g_w1tlo);
    cudaGetSymbolAddress((void**)&w2thi, g_w2thi);
    cudaGetSymbolAddress((void**)&w2tlo, g_w2tlo);
    cudaGetSymbolAddress((void**)&wgthi, g_wgthi);
    cudaGetSymbolAddress((void**)&wgtlo, g_wgtlo);
    cudaGetSymbolAddress((void**)&xg, g_xg);
    cudaGetSymbolAddress((void**)&asrcp, g_asrc);
    cudaGetSymbolAddress((void**)&adstp, g_adst);
    cudaGetSymbolAddress((void**)&cntp, g_cnt);

    const int SMEM = 2 * 4 * 128 * 40 * (int)sizeof(__nv_bfloat16);   // 81920
    cudaFuncSetAttribute(bf16gemm<true,  true,  true,  false>,
                         cudaFuncAttributeMaxDynamicSharedMemorySize, SMEM);
    cudaFuncSetAttribute(bf16gemm<false, true,  true,  false>,
                         cudaFuncAttributeMaxDynamicSharedMemorySize, SMEM);
    cudaFuncSetAttribute(bf16gemm<false, false, false, true >,
                         cudaFuncAttributeMaxDynamicSharedMemorySize, SMEM);

    const int mblk = (Nn + 127) / 128;   // 157

    // zero counts + att accumulators (memset nodes)
    cudaMemsetAsync(cntp,  0, Nn * sizeof(int));
    cudaMemsetAsync(asrcp, 0, Nn * Hh * sizeof(float));
    cudaMemsetAsync(adstp, 0, Nn * Hh * sizeof(float));

    // prep: edge count + weight splits + x split, all in one launch
    mega_prep_kernel<<<(PREP_TOTAL + 255) / 256, 256>>>(ei, W1, W2, Wg, x);
    scan_kernel<<<1, 1024>>>();
    scatter_kernel<<<(TT + 255) / 256, 256>>>(ei);

    // GEMM chain (bf16x3, cp.async pipelined, 2 CTA/SM); G3 fuses attention
    bf16gemm<true,  true,  true,  false><<<dim3(1, mblk), 256, SMEM>>>(
        xhi, xlo, w1thi, w1tlo, b1,
        nullptr, h1hi, h1lo, nullptr, nullptr, Nn, HID, F_IN);
    bf16gemm<false, true,  true,  false><<<dim3(1, mblk), 256, SMEM>>>(
        h1hi, h1lo, w2thi, w2tlo, b2,
        nullptr, h2hi, h2lo, nullptr, nullptr, Nn, OUT, HID);
    bf16gemm<false, false, false, true ><<<dim3(2, mblk), 256, SMEM>>>(
        h2hi, h2lo, wgthi, wgtlo, nullptr,
        xg, nullptr, nullptr, att_src, att_dst, Nn, HC, OUT);

    // fused softmax + aggregation
    gat_agg_kernel<<<(Nn + 7) / 8, 256>>>(out, bias_g);
}

// round 14
// speedup vs baseline: 1.4157x; 1.0672x over previous
#include <cuda_runtime.h>
#include <cuda_bf16.h>
#include <math.h>
#include <stdint.h>

#define Nn   20000
#define Ee   320000
#define F_IN 512
#define HID  128
#define OUT  128
#define Hh   4
#define Cc   64
#define HC   256
#define TT   (Ee + Nn)   // edges incl. self loops

// ---------------- scratch (static device globals; no allocation) -------------
__device__ __align__(16) __nv_bfloat16 g_xhi[Nn * F_IN];
__device__ __align__(16) __nv_bfloat16 g_xlo[Nn * F_IN];
__device__ __align__(16) __nv_bfloat16 g_h1hi[Nn * HID];
__device__ __align__(16) __nv_bfloat16 g_h1lo[Nn * HID];
__device__ __align__(16) __nv_bfloat16 g_h2hi[Nn * OUT];
__device__ __align__(16) __nv_bfloat16 g_h2lo[Nn * OUT];
__device__ __align__(16) __nv_bfloat16 g_w1thi[HID * F_IN];
__device__ __align__(16) __nv_bfloat16 g_w1tlo[HID * F_IN];
__device__ __align__(16) __nv_bfloat16 g_w2thi[OUT * HID];
__device__ __align__(16) __nv_bfloat16 g_w2tlo[OUT * HID];
__device__ __align__(16) __nv_bfloat16 g_wgthi[HC * OUT];
__device__ __align__(16) __nv_bfloat16 g_wgtlo[HC * OUT];
__device__ __align__(16) float g_xg[Nn * HC];
__device__ __align__(16) float g_asrc[Nn * Hh];
__device__ __align__(16) float g_adst[Nn * Hh];
__device__ __align__(16) float g_alpha[TT * Hh];
__device__ int g_cnt[Nn];
__device__ int g_off[Nn];
__device__ int g_cur[Nn];
__device__ int g_csr[TT];

// ---------------- helpers -------------------------------------------------------
__device__ __forceinline__ uint32_t s2u(const void* p) {
    return (uint32_t)__cvta_generic_to_shared(p);
}

__device__ __forceinline__ void cp16(uint32_t dst, const void* src, int bytes) {
    asm volatile("cp.async.cg.shared.global [%0], [%1], 16, %2;"
                 :: "r"(dst), "l"(src), "r"(bytes) : "memory");
}

__device__ __forceinline__ void ldm_x4(uint32_t* r, uint32_t addr) {
    asm volatile("ldmatrix.sync.aligned.m8n8.x4.shared.b16 {%0,%1,%2,%3}, [%4];"
                 : "=r"(r[0]), "=r"(r[1]), "=r"(r[2]), "=r"(r[3]) : "r"(addr));
}
__device__ __forceinline__ void ldm_x2(uint32_t* r, uint32_t addr) {
    asm volatile("ldmatrix.sync.aligned.m8n8.x2.shared.b16 {%0,%1}, [%2];"
                 : "=r"(r[0]), "=r"(r[1]) : "r"(addr));
}

__device__ __forceinline__ void mma_bf16(float* c, const uint32_t* a, const uint32_t* b) {
    asm volatile("mma.sync.aligned.m16n8k16.row.col.f32.bf16.bf16.f32 "
                 "{%0,%1,%2,%3}, {%4,%5,%6,%7}, {%8,%9}, {%0,%1,%2,%3};"
                 : "+f"(c[0]), "+f"(c[1]), "+f"(c[2]), "+f"(c[3])
                 : "r"(a[0]), "r"(a[1]), "r"(a[2]), "r"(a[3]), "r"(b[0]), "r"(b[1]));
}

// ============ bf16x3 GEMM, 64x128 tile, cp.async 2-stage, 3 CTAs/SM ============
// A pre-split bf16 hi/lo [M,K]; B pre-split+transposed [Nc,K].
// BM=64, BN=128, BK=32; 8 warps 2(M)x4(N); warp tile 32x32 = 2x4 atoms.
// Dynamic smem: 2 stages x (64+64+128+128) rows x 40 (padded) bf16 = 60 KB.
template<bool RELU, bool HAS_BIAS, bool OSPLIT, bool ATT>
__global__ __launch_bounds__(256, 3)
void bf16gemm(const __nv_bfloat16* __restrict__ Ahi,
              const __nv_bfloat16* __restrict__ Alo,
              const __nv_bfloat16* __restrict__ Bhi,
              const __nv_bfloat16* __restrict__ Blo,
              const float* __restrict__ bias,
              float* __restrict__ Cf,
              __nv_bfloat16* __restrict__ Chi,
              __nv_bfloat16* __restrict__ Clo,
              const float* __restrict__ att_s,
              const float* __restrict__ att_d,
              int M, int Nc, int K) {
    extern __shared__ __nv_bfloat16 sm[];
    constexpr int PAD   = 40;
    constexpr int ALO_O = 64 * PAD;            // 2560
    constexpr int BHI_O = 2 * 64 * PAD;        // 5120
    constexpr int BLO_O = BHI_O + 128 * PAD;   // 10240
    constexpr int STAGE = BLO_O + 128 * PAD;   // 15360 elems = 30720 B

    const int tid  = threadIdx.x;
    const int lane = tid & 31;
    const int warp = tid >> 5;
    const int wm = warp & 1;          // 0..1 -> 32 rows each
    const int wn = warp >> 1;         // 0..3 -> 32 cols each
    const int g  = lane >> 2;         // 0..7
    const int t  = lane & 3;          // 0..3

    const int rowBase = blockIdx.y * 64;
    const int colBase = blockIdx.x * 128;

    float acc[2][4][4];
#pragma unroll
    for (int i = 0; i < 2; i++)
#pragma unroll
        for (int j = 0; j < 4; j++)
#pragma unroll
            for (int q = 0; q < 4; q++) acc[i][j][q] = 0.f;

    const int a_row = (lane & 7) + ((lane >> 3) & 1) * 8;   // 0..15
    const int a_kof = (lane >> 4) * 8;                      // 0 or 8
    const int b_row = lane & 7;
    const int b_kof = ((lane >> 3) & 1) * 8;

    // fill coordinates: A one cp/thread (hi & lo), B two cps/thread (hi & lo)
    const int fa_row = tid >> 2;             // 0..63
    const int fa_prt = (tid & 3) * 8;
    const int fb0_row = tid >> 1;            // 0..127 (256 thr -> 2 parts each)
    const int fb0_prt = (tid & 1) * 8;       // 0 or 8 -- wait: need 4 parts/row
    // B has 128 rows x 4 parts = 512 cps; id = tid + q*256
    auto fill = [&](int c, int b) {
        const int kt = c << 5;
        __nv_bfloat16* s0 = sm + b * STAGE;
        {
            const int off = fa_row * PAD + fa_prt;
            const int gr  = rowBase + fa_row;
            const int pr  = gr < M ? gr : M - 1;
            const int nb  = gr < M ? 16 : 0;
            cp16(s2u(s0 + off),         Ahi + (size_t)pr * K + kt + fa_prt, nb);
            cp16(s2u(s0 + ALO_O + off), Alo + (size_t)pr * K + kt + fa_prt, nb);
        }
#pragma unroll
        for (int q = 0; q < 2; q++) {
            const int id   = tid + q * 256;
            const int row  = id >> 2;            // 0..127
            const int part = (id & 3) * 8;
            const int off  = row * PAD + part;
            const int gn   = colBase + row;
            cp16(s2u(s0 + BHI_O + off), Bhi + (size_t)gn * K + kt + part, 16);
            cp16(s2u(s0 + BLO_O + off), Blo + (size_t)gn * K + kt + part, 16);
        }
        asm volatile("cp.async.commit_group;" ::: "memory");
    };

    const int nch = K >> 5;
    fill(0, 0);

    for (int c = 0; c < nch; c++) {
        const int b = c & 1;
        if (c + 1 < nch) {
            fill(c + 1, b ^ 1);
            asm volatile("cp.async.wait_group 1;" ::: "memory");
        } else {
            asm volatile("cp.async.wait_group 0;" ::: "memory");
        }
        __syncthreads();

        const __nv_bfloat16* Ash = sm + b * STAGE;
        const __nv_bfloat16* Asl = Ash + ALO_O;
        const __nv_bfloat16* Bsh = sm + b * STAGE + BHI_O;
        const __nv_bfloat16* Bsl = sm + b * STAGE + BLO_O;

#pragma unroll
        for (int ka = 0; ka < 2; ka++) {
            const int k0 = ka * 16;
            uint32_t bhi[4][2], blo[4][2];
#pragma unroll
            for (int na = 0; na < 4; na++) {
                const int n0 = wn * 32 + na * 8;
                ldm_x2(bhi[na], s2u(Bsh + (n0 + b_row) * PAD + k0 + b_kof));
                ldm_x2(blo[na], s2u(Bsl + (n0 + b_row) * PAD + k0 + b_kof));
            }
#pragma unroll
            for (int ma = 0; ma < 2; ma++) {
                const int m0 = wm * 32 + ma * 16;
                uint32_t ahi[4], alo[4];
                ldm_x4(ahi, s2u(Ash + (m0 + a_row) * PAD + k0 + a_kof));
                ldm_x4(alo, s2u(Asl + (m0 + a_row) * PAD + k0 + a_kof));
#pragma unroll
                for (int na = 0; na < 4; na++) {
                    mma_bf16(acc[ma][na], ahi, bhi[na]);
                    mma_bf16(acc[ma][na], alo, bhi[na]);
                    mma_bf16(acc[ma][na], ahi, blo[na]);
                }
            }
        }
        __syncthreads();
    }

    // ---- epilogue stores ----
#pragma unroll
    for (int na = 0; na < 4; na++) {
        const int c = colBase + wn * 32 + na * 8 + 2 * t;
        float2 bb = make_float2(0.f, 0.f);
        if (HAS_BIAS) bb = *(const float2*)(bias + c);
#pragma unroll
        for (int ma = 0; ma < 2; ma++) {
            const int r0 = rowBase + wm * 32 + ma * 16 + g;
            float v0 = acc[ma][na][0] + bb.x;
            float v1 = acc[ma][na][1] + bb.y;
            float v2 = acc[ma][na][2] + bb.x;
            float v3 = acc[ma][na][3] + bb.y;
            if (RELU) {
                v0 = fmaxf(v0, 0.f); v1 = fmaxf(v1, 0.f);
                v2 = fmaxf(v2, 0.f); v3 = fmaxf(v3, 0.f);
            }
            if (OSPLIT) {
                if (r0 < M) {
                    const __nv_bfloat16 h0 = __float2bfloat16(v0);
                    const __nv_bfloat16 h1 = __float2bfloat16(v1);
                    *(__nv_bfloat162*)(Chi + (size_t)r0 * Nc + c) = __halves2bfloat162(h0, h1);
                    *(__nv_bfloat162*)(Clo + (size_t)r0 * Nc + c) =
                        __halves2bfloat162(__float2bfloat16(v0 - __bfloat162float(h0)),
                                           __float2bfloat16(v1 - __bfloat162float(h1)));
                }
                if (r0 + 8 < M) {
                    const __nv_bfloat16 h2 = __float2bfloat16(v2);
                    const __nv_bfloat16 h3 = __float2bfloat16(v3);
                    *(__nv_bfloat162*)(Chi + (size_t)(r0 + 8) * Nc + c) = __halves2bfloat162(h2, h3);
                    *(__nv_bfloat162*)(Clo + (size_t)(r0 + 8) * Nc + c) =
                        __halves2bfloat162(__float2bfloat16(v2 - __bfloat162float(h2)),
                                           __float2bfloat16(v3 - __bfloat162float(h3)));
                }
            } else {
                if (r0 < M)     *(float2*)(Cf + (size_t)r0 * Nc + c)       = make_float2(v0, v1);
                if (r0 + 8 < M) *(float2*)(Cf + (size_t)(r0 + 8) * Nc + c) = make_float2(v2, v3);
            }
        }
    }

    // ---- fused attention coefficients (G3 only) ----
    if (ATT) {
        const int h = (colBase + wn * 32) >> 6;
        float asv[4][2], adv[4][2];
#pragma unroll
        for (int na = 0; na < 4; na++) {
            const int cc = (wn * 32 + na * 8 + 2 * t) & 63;
            asv[na][0] = __ldg(att_s + h * Cc + cc);
            asv[na][1] = __ldg(att_s + h * Cc + cc + 1);
            adv[na][0] = __ldg(att_d + h * Cc + cc);
            adv[na][1] = __ldg(att_d + h * Cc + cc + 1);
        }
#pragma unroll
        for (int ma = 0; ma < 2; ma++) {
            const int r0 = rowBase + wm * 32 + ma * 16 + g;
            float ps0 = 0.f, pd0 = 0.f, ps1 = 0.f, pd1 = 0.f;
#pragma unroll
            for (int na = 0; na < 4; na++) {
                ps0 += acc[ma][na][0] * asv[na][0] + acc[ma][na][1] * asv[na][1];
                pd0 += acc[ma][na][0] * adv[na][0] + acc[ma][na][1] * adv[na][1];
                ps1 += acc[ma][na][2] * asv[na][0] + acc[ma][na][3] * asv[na][1];
                pd1 += acc[ma][na][2] * adv[na][0] + acc[ma][na][3] * adv[na][1];
            }
#pragma unroll
            for (int o = 2; o >= 1; o >>= 1) {
                ps0 += __shfl_down_sync(0xffffffffu, ps0, o);
                pd0 += __shfl_down_sync(0xffffffffu, pd0, o);
                ps1 += __shfl_down_sync(0xffffffffu, ps1, o);
                pd1 += __shfl_down_sync(0xffffffffu, pd1, o);
            }
            if (t == 0) {
                if (r0 < M) {
                    atomicAdd(&g_asrc[r0 * Hh + h], ps0);
                    atomicAdd(&g_adst[r0 * Hh + h], pd0);
                }
                if (r0 + 8 < M) {
                    atomicAdd(&g_asrc[(r0 + 8) * Hh + h], ps1);
                    atomicAdd(&g_adst[(r0 + 8) * Hh + h], pd1);
                }
            }
        }
    }
}

// ---------------- mega prep: edge count + weight splits + x split --------------
__device__ __forceinline__ void wt_split_one(const float* __restrict__ W,
                                             __nv_bfloat16* __restrict__ thi,
                                             __nv_bfloat16* __restrict__ tlo,
                                             int K, int N, int i) {
    const int n = i / K, k = i % K;
    const float v = W[(size_t)k * N + n];
    const __nv_bfloat16 h = __float2bfloat16(v);
    thi[i] = h;
    tlo[i] = __float2bfloat16(v - __bfloat162float(h));
}

#define PREP_W1  (F_IN * HID)
#define PREP_W2  (HID * OUT)
#define PREP_WG  (OUT * HC)
#define PREP_X4  (Nn * F_IN / 4)
#define PREP_TOTAL (Ee + PREP_W1 + PREP_W2 + PREP_WG + PREP_X4)

__global__ void mega_prep_kernel(const int* __restrict__ ei,
                                 const float* __restrict__ W1,
                                 const float* __restrict__ W2,
                                 const float* __restrict__ Wg,
                                 const float* __restrict__ x) {
    int i = blockIdx.x * blockDim.x + threadIdx.x;
    if (i < Ee) { atomicAdd(&g_cnt[ei[Ee + i]], 1); return; }
    i -= Ee;
    if (i < PREP_W1) { wt_split_one(W1, g_w1thi, g_w1tlo, F_IN, HID, i); return; }
    i -= PREP_W1;
    if (i < PREP_W2) { wt_split_one(W2, g_w2thi, g_w2tlo, HID, OUT, i); return; }
    i -= PREP_W2;
    if (i < PREP_WG) { wt_split_one(Wg, g_wgthi, g_wgtlo, OUT, HC, i); return; }
    i -= PREP_WG;
    if (i < PREP_X4) {
        const float4 v = *(const float4*)(x + (size_t)i * 4);
        const __nv_bfloat16 h0 = __float2bfloat16(v.x), h1 = __float2bfloat16(v.y);
        const __nv_bfloat16 h2 = __float2bfloat16(v.z), h3 = __float2bfloat16(v.w);
        __nv_bfloat162* hp = (__nv_bfloat162*)(g_xhi + (size_t)i * 4);
        hp[0] = __halves2bfloat162(h0, h1);
        hp[1] = __halves2bfloat162(h2, h3);
        __nv_bfloat162* lp = (__nv_bfloat162*)(g_xlo + (size_t)i * 4);
        lp[0] = __halves2bfloat162(__float2bfloat16(v.x - __bfloat162float(h0)),
                                   __float2bfloat16(v.y - __bfloat162float(h1)));
        lp[1] = __halves2bfloat162(__float2bfloat16(v.z - __bfloat162float(h2)),
                                   __float2bfloat16(v.w - __bfloat162float(h3)));
    }
}

// ---------------- scan: off = exclusive_sum(cnt+1); cnt <- cnt+1 ---------------
__global__ __launch_bounds__(1024)
void scan_kernel() {
    __shared__ int part[1024];
    const int t = threadIdx.x;
    const int CH = (Nn + 1023) / 1024;
    const int base = t * CH;
    int s = 0;
    for (int i = 0; i < CH; i++) {
        const int idx = base + i;
        if (idx < Nn) s += g_cnt[idx] + 1;
    }
    part[t] = s;
    __syncthreads();
    for (int off = 1; off < 1024; off <<= 1) {
        int v = 0;
        if (t >= off) v = part[t - off];
        __syncthreads();
        if (t >= off) part[t] += v;
        __syncthreads();
    }
    int run = (t == 0) ? 0 : part[t - 1];
    for (int i = 0; i < CH; i++) {
        const int idx = base + i;
        if (idx < Nn) {
            const int c = g_cnt[idx] + 1;
            g_off[idx] = run;
            g_cur[idx] = run;
            g_cnt[idx] = c;
            run += c;
        }
    }
}

__global__ void scatter_kernel(const int* __restrict__ ei) {
    const int e = blockIdx.x * blockDim.x + threadIdx.x;
    if (e >= TT) return;
    int src, dst;
    if (e < Ee) { src = ei[e]; dst = ei[Ee + e]; }
    else        { src = dst = e - Ee; }
    const int pos = atomicAdd(&g_cur[dst], 1);
    g_csr[pos] = src;
}

// ---------------- fused GAT softmax + aggregation: one warp per dst -----------
__global__ void gat_agg_kernel(float* __restrict__ out,
                               const float* __restrict__ bias_g) {
    const int d    = (blockIdx.x * blockDim.x + threadIdx.x) >> 5;
    const int lane = threadIdx.x & 31;
    if (d >= Nn) return;

    const int start = g_off[d];
    const int deg   = g_cnt[d];

    const float4 ad = *(const float4*)(g_adst + d * 4);

    float4 sum = make_float4(0.f, 0.f, 0.f, 0.f);
    for (int k = lane; k < deg; k += 32) {
        const int s = g_csr[start + k];
        const float4 as = *(const float4*)(g_asrc + s * 4);
        float ex = as.x + ad.x, ey = as.y + ad.y, ez = as.z + ad.z, ew = as.w + ad.w;
        ex = ex > 0.f ? ex : 0.2f * ex;
        ey = ey > 0.f ? ey : 0.2f * ey;
        ez = ez > 0.f ? ez : 0.2f * ez;
        ew = ew > 0.f ? ew : 0.2f * ew;
        const float4 exv = make_float4(__expf(ex), __expf(ey), __expf(ez), __expf(ew));
        *(float4*)(g_alpha + (size_t)(start + k) * 4) = exv;
        sum.x += exv.x; sum.y += exv.y; sum.z += exv.z; sum.w += exv.w;
    }
#pragma unroll
    for (int o = 16; o > 0; o >>= 1) {
        sum.x += __shfl_down_sync(0xffffffffu, sum.x, o);
        sum.y += __shfl_down_sync(0xffffffffu, sum.y, o);
        sum.z += __shfl_down_sync(0xffffffffu, sum.z, o);
        sum.w += __shfl_down_sync(0xffffffffu, sum.w, o);
    }
    const float dx = __shfl_sync(0xffffffffu, sum.x, 0) + 1e-16f;
    const float dy = __shfl_sync(0xffffffffu, sum.y, 0) + 1e-16f;
    const float dz = __shfl_sync(0xffffffffu, sum.z, 0) + 1e-16f;
    const float dw = __shfl_sync(0xffffffffu, sum.w, 0) + 1e-16f;

    const int h = lane >> 3;
    const float denom = (h == 0) ? dx : (h == 1) ? dy : (h == 2) ? dz : dw;
    const float rden  = 1.f / denom;

    float acc[8];
#pragma unroll
    for (int i = 0; i < 8; i++) acc[i] = 0.f;

    const float* al = g_alpha + (size_t)start * 4;
    int k = 0;
    for (; k + 4 <= deg; k += 4) {
        const int s0 = g_csr[start + k];
        const int s1 = g_csr[start + k + 1];
        const int s2 = g_csr[start + k + 2];
        const int s3 = g_csr[start + k + 3];
        const float a0 = al[(k    ) * 4 + h] * rden;
        const float a1 = al[(k + 1) * 4 + h] * rden;
        const float a2 = al[(k + 2) * 4 + h] * rden;
        const float a3 = al[(k + 3) * 4 + h] * rden;
        const float4* x0 = (const float4*)(g_xg + (size_t)s0 * HC + lane * 8);
        const float4* x1 = (const float4*)(g_xg + (size_t)s1 * HC + lane * 8);
        const float4* x2 = (const float4*)(g_xg + (size_t)s2 * HC + lane * 8);
        const float4* x3 = (const float4*)(g_xg + (size_t)s3 * HC + lane * 8);
        const float4 p0 = x0[0], q0 = x0[1];
        const float4 p1 = x1[0], q1 = x1[1];
        const float4 p2 = x2[0], q2 = x2[1];
        const float4 p3 = x3[0], q3 = x3[1];
        acc[0] = fmaf(a0, p0.x, fmaf(a1, p1.x, fmaf(a2, p2.x, fmaf(a3, p3.x, acc[0]))));
        acc[1] = fmaf(a0, p0.y, fmaf(a1, p1.y, fmaf(a2, p2.y, fmaf(a3, p3.y, acc[1]))));
        acc[2] = fmaf(a0, p0.z, fmaf(a1, p1.z, fmaf(a2, p2.z, fmaf(a3, p3.z, acc[2]))));
        acc[3] = fmaf(a0, p0.w, fmaf(a1, p1.w, fmaf(a2, p2.w, fmaf(a3, p3.w, acc[3]))));
        acc[4] = fmaf(a0, q0.x, fmaf(a1, q1.x, fmaf(a2, q2.x, fmaf(a3, q3.x, acc[4]))));
        acc[5] = fmaf(a0, q0.y, fmaf(a1, q1.y, fmaf(a2, q2.y, fmaf(a3, q3.y, acc[5]))));
        acc[6] = fmaf(a0, q0.z, fmaf(a1, q1.z, fmaf(a2, q2.z, fmaf(a3, q3.z, acc[6]))));
        acc[7] = fmaf(a0, q0.w, fmaf(a1, q1.w, fmaf(a2, q2.w, fmaf(a3, q3.w, acc[7]))));
    }
    for (; k < deg; k++) {
        const int s = g_csr[start + k];
        const float a = al[k * 4 + h] * rden;
        const float4* xr = (const float4*)(g_xg + (size_t)s * HC + lane * 8);
        const float4 v0 = xr[0];
        const float4 v1 = xr[1];
        acc[0] = fmaf(a, v0.x, acc[0]);
        acc[1] = fmaf(a, v0.y, acc[1]);
        acc[2] = fmaf(a, v0.z, acc[2]);
        acc[3] = fmaf(a, v0.w, acc[3]);
        acc[4] = fmaf(a, v1.x, acc[4]);
        acc[5] = fmaf(a, v1.y, acc[5]);
        acc[6] = fmaf(a, v1.z, acc[6]);
        acc[7] = fmaf(a, v1.w, acc[7]);
    }

    const float4 bg0 = *(const float4*)(bias_g + lane * 8);
    const float4 bg1 = *(const float4*)(bias_g + lane * 8 + 4);
    float* op = out + (size_t)d * HC + lane * 8;
    *(float4*)op       = make_float4(acc[0] + bg0.x, acc[1] + bg0.y,
                                     acc[2] + bg0.z, acc[3] + bg0.w);
    *(float4*)(op + 4) = make_float4(acc[4] + bg1.x, acc[5] + bg1.y,
                                     acc[6] + bg1.z, acc[7] + bg1.w);
}

// ---------------- launch --------------------------------------------------------
extern "C" void kernel_launch(void* const* d_in, const int* in_sizes, int n_in,
                              void* d_out, int out_size) {
    const float* x   = (const float*)d_in[0];
    const int*   ei  = (const int*)d_in[1];
    const float* W1  = (const float*)d_in[2];
    const float* b1  = (const float*)d_in[3];
    const float* W2  = (const float*)d_in[4];
    const float* b2  = (const float*)d_in[5];
    const float* Wg  = (const float*)d_in[6];
    const float* att_src = (const float*)d_in[7];
    const float* att_dst = (const float*)d_in[8];
    const float* bias_g  = (const float*)d_in[9];
    float* out = (float*)d_out;

    __nv_bfloat16 *xhi, *xlo, *h1hi, *h1lo, *h2hi, *h2lo;
    __nv_bfloat16 *w1thi, *w1tlo, *w2thi, *w2tlo, *wgthi, *wgtlo;
    float *xg, *asrcp, *adstp;
    int* cntp;
    cudaGetSymbolAddress((void**)&xhi,  g_xhi);
    cudaGetSymbolAddress((void**)&xlo,  g_xlo);
    cudaGetSymbolAddress((void**)&h1hi, g_h1hi);
    cudaGetSymbolAddress((void**)&h1lo, g_h1lo);
    cudaGetSymbolAddress((void**)&h2hi, g_h2hi);
    cudaGetSymbolAddress((void**)&h2lo, g_h2lo);
    cudaGetSymbolAddress((void**)&w1thi, g_w1thi);
    cudaGetSymbolAddress((void**)&w1tlo, g_w1tlo);
    cudaGetSymbolAddress((void**)&w2thi, g_w2thi);
    cudaGetSymbolAddress((void**)&w2tlo, g_w2tlo);
    cudaGetSymbolAddress((void**)&wgthi, g_wgthi);
    cudaGetSymbolAddress((void**)&wgtlo, g_wgtlo);
    cudaGetSymbolAddress((void**)&xg, g_xg);
    cudaGetSymbolAddress((void**)&asrcp, g_asrc);
    cudaGetSymbolAddress((void**)&adstp, g_adst);
    cudaGetSymbolAddress((void**)&cntp, g_cnt);

    const int SMEM = 2 * (64 + 64 + 128 + 128) * 40 * (int)sizeof(__nv_bfloat16);  // 61440
    cudaFuncSetAttribute(bf16gemm<true,  true,  true,  false>,
                         cudaFuncAttributeMaxDynamicSharedMemorySize, SMEM);
    cudaFuncSetAttribute(bf16gemm<false, true,  true,  false>,
                         cudaFuncAttributeMaxDynamicSharedMemorySize, SMEM);
    cudaFuncSetAttribute(bf16gemm<false, false, false, true >,
                         cudaFuncAttributeMaxDynamicSharedMemorySize, SMEM);

    const int mblk = (Nn + 63) / 64;   // 313

    // zero counts + att accumulators (memset nodes)
    cudaMemsetAsync(cntp,  0, Nn * sizeof(int));
    cudaMemsetAsync(asrcp, 0, Nn * Hh * sizeof(float));
    cudaMemsetAsync(adstp, 0, Nn * Hh * sizeof(float));

    // prep: edge count + weight splits + x split, all in one launch
    mega_prep_kernel<<<(PREP_TOTAL + 255) / 256, 256>>>(ei, W1, W2, Wg, x);
    scan_kernel<<<1, 1024>>>();
    scatter_kernel<<<(TT + 255) / 256, 256>>>(ei);

    // GEMM chain (bf16x3, 64x128 tiles, 3 CTA/SM); G3 fuses attention
    bf16gemm<true,  true,  true,  false><<<dim3(1, mblk), 256, SMEM>>>(
        xhi, xlo, w1thi, w1tlo, b1,
        nullptr, h1hi, h1lo, nullptr, nullptr, Nn, HID, F_IN);
    bf16gemm<false, true,  true,  false><<<dim3(1, mblk), 256, SMEM>>>(
        h1hi, h1lo, w2thi, w2tlo, b2,
        nullptr, h2hi, h2lo, nullptr, nullptr, Nn, OUT, HID);
    bf16gemm<false, false, false, true ><<<dim3(2, mblk), 256, SMEM>>>(
        h2hi, h2lo, wgthi, wgtlo, nullptr,
        xg, nullptr, nullptr, att_src, att_dst, Nn, HC, OUT);

    // fused softmax + aggregation
    gat_agg_kernel<<<(Nn + 7) / 8, 256>>>(out, bias_g);
}

// round 15
// speedup vs baseline: 1.5882x; 1.1219x over previous
#include <cuda_runtime.h>
#include <cuda_bf16.h>
#include <math.h>
#include <stdint.h>

#define Nn   20000
#define Ee   320000
#define F_IN 512
#define HID  128
#define OUT  128
#define Hh   4
#define Cc   64
#define HC   256
#define TT   (Ee + Nn)   // edges incl. self loops

// ---------------- scratch (static device globals; no allocation) -------------
__device__ __align__(16) __nv_bfloat16 g_xhi[Nn * F_IN];
__device__ __align__(16) __nv_bfloat16 g_xlo[Nn * F_IN];
__device__ __align__(16) __nv_bfloat16 g_h1hi[Nn * HID];
__device__ __align__(16) __nv_bfloat16 g_h1lo[Nn * HID];
__device__ __align__(16) __nv_bfloat16 g_h2hi[Nn * OUT];
__device__ __align__(16) __nv_bfloat16 g_h2lo[Nn * OUT];
__device__ __align__(16) __nv_bfloat16 g_w1thi[HID * F_IN];
__device__ __align__(16) __nv_bfloat16 g_w1tlo[HID * F_IN];
__device__ __align__(16) __nv_bfloat16 g_w2thi[OUT * HID];
__device__ __align__(16) __nv_bfloat16 g_w2tlo[OUT * HID];
__device__ __align__(16) __nv_bfloat16 g_wgthi[HC * OUT];
__device__ __align__(16) __nv_bfloat16 g_wgtlo[HC * OUT];
__device__ __align__(16) float g_xg[Nn * HC];
__device__ __align__(16) float g_asrc[Nn * Hh];
__device__ __align__(16) float g_adst[Nn * Hh];
__device__ __align__(16) float g_alpha[TT * Hh];
__device__ int g_cnt[Nn];
__device__ int g_off[Nn];
__device__ int g_cur[Nn];
__device__ int g_csr[TT];

// ---------------- side stream / events (created pre-main, outside capture) ----
static cudaStream_t g_s2;
static cudaEvent_t  g_e1, g_e2;
static const bool g_stream_init = [] {
    cudaStreamCreateWithFlags(&g_s2, cudaStreamNonBlocking);
    cudaEventCreateWithFlags(&g_e1, cudaEventDisableTiming);
    cudaEventCreateWithFlags(&g_e2, cudaEventDisableTiming);
    return true;
}();

// ---------------- helpers -------------------------------------------------------
__device__ __forceinline__ uint32_t s2u(const void* p) {
    return (uint32_t)__cvta_generic_to_shared(p);
}

__device__ __forceinline__ void cp16(uint32_t dst, const void* src, int bytes) {
    asm volatile("cp.async.cg.shared.global [%0], [%1], 16, %2;"
                 :: "r"(dst), "l"(src), "r"(bytes) : "memory");
}

__device__ __forceinline__ void ldm_x4(uint32_t* r, uint32_t addr) {
    asm volatile("ldmatrix.sync.aligned.m8n8.x4.shared.b16 {%0,%1,%2,%3}, [%4];"
                 : "=r"(r[0]), "=r"(r[1]), "=r"(r[2]), "=r"(r[3]) : "r"(addr));
}
__device__ __forceinline__ void ldm_x2(uint32_t* r, uint32_t addr) {
    asm volatile("ldmatrix.sync.aligned.m8n8.x2.shared.b16 {%0,%1}, [%2];"
                 : "=r"(r[0]), "=r"(r[1]) : "r"(addr));
}

__device__ __forceinline__ void mma_bf16(float* c, const uint32_t* a, const uint32_t* b) {
    asm volatile("mma.sync.aligned.m16n8k16.row.col.f32.bf16.bf16.f32 "
                 "{%0,%1,%2,%3}, {%4,%5,%6,%7}, {%8,%9}, {%0,%1,%2,%3};"
                 : "+f"(c[0]), "+f"(c[1]), "+f"(c[2]), "+f"(c[3])
                 : "r"(a[0]), "r"(a[1]), "r"(a[2]), "r"(a[3]), "r"(b[0]), "r"(b[1]));
}

// ============ bf16x3 GEMM, 64x128 tile, cp.async 2-stage, 3 CTAs/SM ============
template<bool RELU, bool HAS_BIAS, bool OSPLIT, bool ATT>
__global__ __launch_bounds__(256, 3)
void bf16gemm(const __nv_bfloat16* __restrict__ Ahi,
              const __nv_bfloat16* __restrict__ Alo,
              const __nv_bfloat16* __restrict__ Bhi,
              const __nv_bfloat16* __restrict__ Blo,
              const float* __restrict__ bias,
              float* __restrict__ Cf,
              __nv_bfloat16* __restrict__ Chi,
              __nv_bfloat16* __restrict__ Clo,
              const float* __restrict__ att_s,
              const float* __restrict__ att_d,
              int M, int Nc, int K) {
    extern __shared__ __nv_bfloat16 sm[];
    constexpr int PAD   = 40;
    constexpr int ALO_O = 64 * PAD;
    constexpr int BHI_O = 2 * 64 * PAD;
    constexpr int BLO_O = BHI_O + 128 * PAD;
    constexpr int STAGE = BLO_O + 128 * PAD;

    const int tid  = threadIdx.x;
    const int lane = tid & 31;
    const int warp = tid >> 5;
    const int wm = warp & 1;
    const int wn = warp >> 1;
    const int g  = lane >> 2;
    const int t  = lane & 3;

    const int rowBase = blockIdx.y * 64;
    const int colBase = blockIdx.x * 128;

    float acc[2][4][4];
#pragma unroll
    for (int i = 0; i < 2; i++)
#pragma unroll
        for (int j = 0; j < 4; j++)
#pragma unroll
            for (int q = 0; q < 4; q++) acc[i][j][q] = 0.f;

    const int a_row = (lane & 7) + ((lane >> 3) & 1) * 8;
    const int a_kof = (lane >> 4) * 8;
    const int b_row = lane & 7;
    const int b_kof = ((lane >> 3) & 1) * 8;

    const int fa_row = tid >> 2;
    const int fa_prt = (tid & 3) * 8;

    auto fill = [&](int c, int b) {
        const int kt = c << 5;
        __nv_bfloat16* s0 = sm + b * STAGE;
        {
            const int off = fa_row * PAD + fa_prt;
            const int gr  = rowBase + fa_row;
            const int pr  = gr < M ? gr : M - 1;
            const int nb  = gr < M ? 16 : 0;
            cp16(s2u(s0 + off),         Ahi + (size_t)pr * K + kt + fa_prt, nb);
            cp16(s2u(s0 + ALO_O + off), Alo + (size_t)pr * K + kt + fa_prt, nb);
        }
#pragma unroll
        for (int q = 0; q < 2; q++) {
            const int id   = tid + q * 256;
            const int row  = id >> 2;
            const int part = (id & 3) * 8;
            const int off  = row * PAD + part;
            const int gn   = colBase + row;
            cp16(s2u(s0 + BHI_O + off), Bhi + (size_t)gn * K + kt + part, 16);
            cp16(s2u(s0 + BLO_O + off), Blo + (size_t)gn * K + kt + part, 16);
        }
        asm volatile("cp.async.commit_group;" ::: "memory");
    };

    const int nch = K >> 5;
    fill(0, 0);

    for (int c = 0; c < nch; c++) {
        const int b = c & 1;
        if (c + 1 < nch) {
            fill(c + 1, b ^ 1);
            asm volatile("cp.async.wait_group 1;" ::: "memory");
        } else {
            asm volatile("cp.async.wait_group 0;" ::: "memory");
        }
        __syncthreads();

        const __nv_bfloat16* Ash = sm + b * STAGE;
        const __nv_bfloat16* Asl = Ash + ALO_O;
        const __nv_bfloat16* Bsh = sm + b * STAGE + BHI_O;
        const __nv_bfloat16* Bsl = sm + b * STAGE + BLO_O;

#pragma unroll
        for (int ka = 0; ka < 2; ka++) {
            const int k0 = ka * 16;
            uint32_t bhi[4][2], blo[4][2];
#pragma unroll
            for (int na = 0; na < 4; na++) {
                const int n0 = wn * 32 + na * 8;
                ldm_x2(bhi[na], s2u(Bsh + (n0 + b_row) * PAD + k0 + b_kof));
                ldm_x2(blo[na], s2u(Bsl + (n0 + b_row) * PAD + k0 + b_kof));
            }
#pragma unroll
            for (int ma = 0; ma < 2; ma++) {
                const int m0 = wm * 32 + ma * 16;
                uint32_t ahi[4], alo[4];
                ldm_x4(ahi, s2u(Ash + (m0 + a_row) * PAD + k0 + a_kof));
                ldm_x4(alo, s2u(Asl + (m0 + a_row) * PAD + k0 + a_kof));
#pragma unroll
                for (int na = 0; na < 4; na++) {
                    mma_bf16(acc[ma][na], ahi, bhi[na]);
                    mma_bf16(acc[ma][na], alo, bhi[na]);
                    mma_bf16(acc[ma][na], ahi, blo[na]);
                }
            }
        }
        __syncthreads();
    }

    // ---- epilogue stores ----
#pragma unroll
    for (int na = 0; na < 4; na++) {
        const int c = colBase + wn * 32 + na * 8 + 2 * t;
        float2 bb = make_float2(0.f, 0.f);
        if (HAS_BIAS) bb = *(const float2*)(bias + c);
#pragma unroll
        for (int ma = 0; ma < 2; ma++) {
            const int r0 = rowBase + wm * 32 + ma * 16 + g;
            float v0 = acc[ma][na][0] + bb.x;
            float v1 = acc[ma][na][1] + bb.y;
            float v2 = acc[ma][na][2] + bb.x;
            float v3 = acc[ma][na][3] + bb.y;
            if (RELU) {
                v0 = fmaxf(v0, 0.f); v1 = fmaxf(v1, 0.f);
                v2 = fmaxf(v2, 0.f); v3 = fmaxf(v3, 0.f);
            }
            if (OSPLIT) {
                if (r0 < M) {
                    const __nv_bfloat16 h0 = __float2bfloat16(v0);
                    const __nv_bfloat16 h1 = __float2bfloat16(v1);
                    *(__nv_bfloat162*)(Chi + (size_t)r0 * Nc + c) = __halves2bfloat162(h0, h1);
                    *(__nv_bfloat162*)(Clo + (size_t)r0 * Nc + c) =
                        __halves2bfloat162(__float2bfloat16(v0 - __bfloat162float(h0)),
                                           __float2bfloat16(v1 - __bfloat162float(h1)));
                }
                if (r0 + 8 < M) {
                    const __nv_bfloat16 h2 = __float2bfloat16(v2);
                    const __nv_bfloat16 h3 = __float2bfloat16(v3);
                    *(__nv_bfloat162*)(Chi + (size_t)(r0 + 8) * Nc + c) = __halves2bfloat162(h2, h3);
                    *(__nv_bfloat162*)(Clo + (size_t)(r0 + 8) * Nc + c) =
                        __halves2bfloat162(__float2bfloat16(v2 - __bfloat162float(h2)),
                                           __float2bfloat16(v3 - __bfloat162float(h3)));
                }
            } else {
                if (r0 < M)     *(float2*)(Cf + (size_t)r0 * Nc + c)       = make_float2(v0, v1);
                if (r0 + 8 < M) *(float2*)(Cf + (size_t)(r0 + 8) * Nc + c) = make_float2(v2, v3);
            }
        }
    }

    // ---- fused attention coefficients (G3 only) ----
    if (ATT) {
        const int h = (colBase + wn * 32) >> 6;
        float asv[4][2], adv[4][2];
#pragma unroll
        for (int na = 0; na < 4; na++) {
            const int cc = (wn * 32 + na * 8 + 2 * t) & 63;
            asv[na][0] = __ldg(att_s + h * Cc + cc);
            asv[na][1] = __ldg(att_s + h * Cc + cc + 1);
            adv[na][0] = __ldg(att_d + h * Cc + cc);
            adv[na][1] = __ldg(att_d + h * Cc + cc + 1);
        }
#pragma unroll
        for (int ma = 0; ma < 2; ma++) {
            const int r0 = rowBase + wm * 32 + ma * 16 + g;
            float ps0 = 0.f, pd0 = 0.f, ps1 = 0.f, pd1 = 0.f;
#pragma unroll
            for (int na = 0; na < 4; na++) {
                ps0 += acc[ma][na][0] * asv[na][0] + acc[ma][na][1] * asv[na][1];
                pd0 += acc[ma][na][0] * adv[na][0] + acc[ma][na][1] * adv[na][1];
                ps1 += acc[ma][na][2] * asv[na][0] + acc[ma][na][3] * asv[na][1];
                pd1 += acc[ma][na][2] * adv[na][0] + acc[ma][na][3] * adv[na][1];
            }
#pragma unroll
            for (int o = 2; o >= 1; o >>= 1) {
                ps0 += __shfl_down_sync(0xffffffffu, ps0, o);
                pd0 += __shfl_down_sync(0xffffffffu, pd0, o);
                ps1 += __shfl_down_sync(0xffffffffu, ps1, o);
                pd1 += __shfl_down_sync(0xffffffffu, pd1, o);
            }
            if (t == 0) {
                if (r0 < M) {
                    atomicAdd(&g_asrc[r0 * Hh + h], ps0);
                    atomicAdd(&g_adst[r0 * Hh + h], pd0);
                }
                if (r0 + 8 < M) {
                    atomicAdd(&g_asrc[(r0 + 8) * Hh + h], ps1);
                    atomicAdd(&g_adst[(r0 + 8) * Hh + h], pd1);
                }
            }
        }
    }
}

// ---------------- split prep (main stream): weight transposes + x split --------
__device__ __forceinline__ void wt_split_one(const float* __restrict__ W,
                                             __nv_bfloat16* __restrict__ thi,
                                             __nv_bfloat16* __restrict__ tlo,
                                             int K, int N, int i) {
    const int n = i / K, k = i % K;
    const float v = W[(size_t)k * N + n];
    const __nv_bfloat16 h = __float2bfloat16(v);
    thi[i] = h;
    tlo[i] = __float2bfloat16(v - __bfloat162float(h));
}

#define PREP_W1  (F_IN * HID)
#define PREP_W2  (HID * OUT)
#define PREP_WG  (OUT * HC)
#define PREP_X4  (Nn * F_IN / 4)
#define SPLIT_TOTAL (PREP_W1 + PREP_W2 + PREP_WG + PREP_X4)

__global__ void split_prep_kernel(const float* __restrict__ W1,
                                  const float* __restrict__ W2,
                                  const float* __restrict__ Wg,
                                  const float* __restrict__ x) {
    int i = blockIdx.x * blockDim.x + threadIdx.x;
    if (i < PREP_W1) { wt_split_one(W1, g_w1thi, g_w1tlo, F_IN, HID, i); return; }
    i -= PREP_W1;
    if (i < PREP_W2) { wt_split_one(W2, g_w2thi, g_w2tlo, HID, OUT, i); return; }
    i -= PREP_W2;
    if (i < PREP_WG) { wt_split_one(Wg, g_wgthi, g_wgtlo, OUT, HC, i); return; }
    i -= PREP_WG;
    if (i < PREP_X4) {
        const float4 v = *(const float4*)(x + (size_t)i * 4);
        const __nv_bfloat16 h0 = __float2bfloat16(v.x), h1 = __float2bfloat16(v.y);
        const __nv_bfloat16 h2 = __float2bfloat16(v.z), h3 = __float2bfloat16(v.w);
        __nv_bfloat162* hp = (__nv_bfloat162*)(g_xhi + (size_t)i * 4);
        hp[0] = __halves2bfloat162(h0, h1);
        hp[1] = __halves2bfloat162(h2, h3);
        __nv_bfloat162* lp = (__nv_bfloat162*)(g_xlo + (size_t)i * 4);
        lp[0] = __halves2bfloat162(__float2bfloat16(v.x - __bfloat162float(h0)),
                                   __float2bfloat16(v.y - __bfloat162float(h1)));
        lp[1] = __halves2bfloat162(__float2bfloat16(v.z - __bfloat162float(h2)),
                                   __float2bfloat16(v.w - __bfloat162float(h3)));
    }
}

// ---------------- CSR build (side stream) --------------------------------------
__global__ void count_kernel(const int* __restrict__ ei) {
    const int e = blockIdx.x * blockDim.x + threadIdx.x;
    if (e < Ee) atomicAdd(&g_cnt[ei[Ee + e]], 1);
}

__global__ __launch_bounds__(1024)
void scan_kernel() {
    __shared__ int part[1024];
    const int t = threadIdx.x;
    const int CH = (Nn + 1023) / 1024;
    const int base = t * CH;
    int s = 0;
    for (int i = 0; i < CH; i++) {
        const int idx = base + i;
        if (idx < Nn) s += g_cnt[idx] + 1;
    }
    part[t] = s;
    __syncthreads();
    for (int off = 1; off < 1024; off <<= 1) {
        int v = 0;
        if (t >= off) v = part[t - off];
        __syncthreads();
        if (t >= off) part[t] += v;
        __syncthreads();
    }
    int run = (t == 0) ? 0 : part[t - 1];
    for (int i = 0; i < CH; i++) {
        const int idx = base + i;
        if (idx < Nn) {
            const int c = g_cnt[idx] + 1;
            g_off[idx] = run;
            g_cur[idx] = run;
            g_cnt[idx] = c;
            run += c;
        }
    }
}

__global__ void scatter_kernel(const int* __restrict__ ei) {
    const int e = blockIdx.x * blockDim.x + threadIdx.x;
    if (e >= TT) return;
    int src, dst;
    if (e < Ee) { src = ei[e]; dst = ei[Ee + e]; }
    else        { src = dst = e - Ee; }
    const int pos = atomicAdd(&g_cur[dst], 1);
    g_csr[pos] = src;
}

// ---------------- fused GAT softmax + aggregation: one warp per dst -----------
__global__ void gat_agg_kernel(float* __restrict__ out,
                               const float* __restrict__ bias_g) {
    const int d    = (blockIdx.x * blockDim.x + threadIdx.x) >> 5;
    const int lane = threadIdx.x & 31;
    if (d >= Nn) return;

    const int start = g_off[d];
    const int deg   = g_cnt[d];

    const float4 ad = *(const float4*)(g_adst + d * 4);

    float4 sum = make_float4(0.f, 0.f, 0.f, 0.f);
    for (int k = lane; k < deg; k += 32) {
        const int s = g_csr[start + k];
        const float4 as = *(const float4*)(g_asrc + s * 4);
        float ex = as.x + ad.x, ey = as.y + ad.y, ez = as.z + ad.z, ew = as.w + ad.w;
        ex = ex > 0.f ? ex : 0.2f * ex;
        ey = ey > 0.f ? ey : 0.2f * ey;
        ez = ez > 0.f ? ez : 0.2f * ez;
        ew = ew > 0.f ? ew : 0.2f * ew;
        const float4 exv = make_float4(__expf(ex), __expf(ey), __expf(ez), __expf(ew));
        *(float4*)(g_alpha + (size_t)(start + k) * 4) = exv;
        sum.x += exv.x; sum.y += exv.y; sum.z += exv.z; sum.w += exv.w;
    }
#pragma unroll
    for (int o = 16; o > 0; o >>= 1) {
        sum.x += __shfl_down_sync(0xffffffffu, sum.x, o);
        sum.y += __shfl_down_sync(0xffffffffu, sum.y, o);
        sum.z += __shfl_down_sync(0xffffffffu, sum.z, o);
        sum.w += __shfl_down_sync(0xffffffffu, sum.w, o);
    }
    const float dx = __shfl_sync(0xffffffffu, sum.x, 0) + 1e-16f;
    const float dy = __shfl_sync(0xffffffffu, sum.y, 0) + 1e-16f;
    const float dz = __shfl_sync(0xffffffffu, sum.z, 0) + 1e-16f;
    const float dw = __shfl_sync(0xffffffffu, sum.w, 0) + 1e-16f;

    const int h = lane >> 3;
    const float denom = (h == 0) ? dx : (h == 1) ? dy : (h == 2) ? dz : dw;
    const float rden  = 1.f / denom;

    float acc[8];
#pragma unroll
    for (int i = 0; i < 8; i++) acc[i] = 0.f;

    const float* al = g_alpha + (size_t)start * 4;
    int k = 0;
    for (; k + 4 <= deg; k += 4) {
        const int s0 = g_csr[start + k];
        const int s1 = g_csr[start + k + 1];
        const int s2 = g_csr[start + k + 2];
        const int s3 = g_csr[start + k + 3];
        const float a0 = al[(k    ) * 4 + h] * rden;
        const float a1 = al[(k + 1) * 4 + h] * rden;
        const float a2 = al[(k + 2) * 4 + h] * rden;
        const float a3 = al[(k + 3) * 4 + h] * rden;
        const float4* x0 = (const float4*)(g_xg + (size_t)s0 * HC + lane * 8);
        const float4* x1 = (const float4*)(g_xg + (size_t)s1 * HC + lane * 8);
        const float4* x2 = (const float4*)(g_xg + (size_t)s2 * HC + lane * 8);
        const float4* x3 = (const float4*)(g_xg + (size_t)s3 * HC + lane * 8);
        const float4 p0 = x0[0], q0 = x0[1];
        const float4 p1 = x1[0], q1 = x1[1];
        const float4 p2 = x2[0], q2 = x2[1];
        const float4 p3 = x3[0], q3 = x3[1];
        acc[0] = fmaf(a0, p0.x, fmaf(a1, p1.x, fmaf(a2, p2.x, fmaf(a3, p3.x, acc[0]))));
        acc[1] = fmaf(a0, p0.y, fmaf(a1, p1.y, fmaf(a2, p2.y, fmaf(a3, p3.y, acc[1]))));
        acc[2] = fmaf(a0, p0.z, fmaf(a1, p1.z, fmaf(a2, p2.z, fmaf(a3, p3.z, acc[2]))));
        acc[3] = fmaf(a0, p0.w, fmaf(a1, p1.w, fmaf(a2, p2.w, fmaf(a3, p3.w, acc[3]))));
        acc[4] = fmaf(a0, q0.x, fmaf(a1, q1.x, fmaf(a2, q2.x, fmaf(a3, q3.x, acc[4]))));
        acc[5] = fmaf(a0, q0.y, fmaf(a1, q1.y, fmaf(a2, q2.y, fmaf(a3, q3.y, acc[5]))));
        acc[6] = fmaf(a0, q0.z, fmaf(a1, q1.z, fmaf(a2, q2.z, fmaf(a3, q3.z, acc[6]))));
        acc[7] = fmaf(a0, q0.w, fmaf(a1, q1.w, fmaf(a2, q2.w, fmaf(a3, q3.w, acc[7]))));
    }
    for (; k < deg; k++) {
        const int s = g_csr[start + k];
        const float a = al[k * 4 + h] * rden;
        const float4* xr = (const float4*)(g_xg + (size_t)s * HC + lane * 8);
        const float4 v0 = xr[0];
        const float4 v1 = xr[1];
        acc[0] = fmaf(a, v0.x, acc[0]);
        acc[1] = fmaf(a, v0.y, acc[1]);
        acc[2] = fmaf(a, v0.z, acc[2]);
        acc[3] = fmaf(a, v0.w, acc[3]);
        acc[4] = fmaf(a, v1.x, acc[4]);
        acc[5] = fmaf(a, v1.y, acc[5]);
        acc[6] = fmaf(a, v1.z, acc[6]);
        acc[7] = fmaf(a, v1.w, acc[7]);
    }

    const float4 bg0 = *(const float4*)(bias_g + lane * 8);
    const float4 bg1 = *(const float4*)(bias_g + lane * 8 + 4);
    float* op = out + (size_t)d * HC + lane * 8;
    *(float4*)op       = make_float4(acc[0] + bg0.x, acc[1] + bg0.y,
                                     acc[2] + bg0.z, acc[3] + bg0.w);
    *(float4*)(op + 4) = make_float4(acc[4] + bg1.x, acc[5] + bg1.y,
                                     acc[6] + bg1.z, acc[7] + bg1.w);
}

// ---------------- launch --------------------------------------------------------
extern "C" void kernel_launch(void* const* d_in, const int* in_sizes, int n_in,
                              void* d_out, int out_size) {
    const float* x   = (const float*)d_in[0];
    const int*   ei  = (const int*)d_in[1];
    const float* W1  = (const float*)d_in[2];
    const float* b1  = (const float*)d_in[3];
    const float* W2  = (const float*)d_in[4];
    const float* b2  = (const float*)d_in[5];
    const float* Wg  = (const float*)d_in[6];
    const float* att_src = (const float*)d_in[7];
    const float* att_dst = (const float*)d_in[8];
    const float* bias_g  = (const float*)d_in[9];
    float* out = (float*)d_out;

    __nv_bfloat16 *xhi, *xlo, *h1hi, *h1lo, *h2hi, *h2lo;
    __nv_bfloat16 *w1thi, *w1tlo, *w2thi, *w2tlo, *wgthi, *wgtlo;
    float *xg, *asrcp, *adstp;
    int* cntp;
    cudaGetSymbolAddress((void**)&xhi,  g_xhi);
    cudaGetSymbolAddress((void**)&xlo,  g_xlo);
    cudaGetSymbolAddress((void**)&h1hi, g_h1hi);
    cudaGetSymbolAddress((void**)&h1lo, g_h1lo);
    cudaGetSymbolAddress((void**)&h2hi, g_h2hi);
    cudaGetSymbolAddress((void**)&h2lo, g_h2lo);
    cudaGetSymbolAddress((void**)&w1thi, g_w1thi);
    cudaGetSymbolAddress((void**)&w1tlo, g_w1tlo);
    cudaGetSymbolAddress((void**)&w2thi, g_w2thi);
    cudaGetSymbolAddress((void**)&w2tlo, g_w2tlo);
    cudaGetSymbolAddress((void**)&wgthi, g_wgthi);
    cudaGetSymbolAddress((void**)&wgtlo, g_wgtlo);
    cudaGetSymbolAddress((void**)&xg, g_xg);
    cudaGetSymbolAddress((void**)&asrcp, g_asrc);
    cudaGetSymbolAddress((void**)&adstp, g_adst);
    cudaGetSymbolAddress((void**)&cntp, g_cnt);

    const int SMEM = 2 * (64 + 64 + 128 + 128) * 40 * (int)sizeof(__nv_bfloat16);  // 61440
    cudaFuncSetAttribute(bf16gemm<true,  true,  true,  false>,
                         cudaFuncAttributeMaxDynamicSharedMemorySize, SMEM);
    cudaFuncSetAttribute(bf16gemm<false, true,  true,  false>,
                         cudaFuncAttributeMaxDynamicSharedMemorySize, SMEM);
    cudaFuncSetAttribute(bf16gemm<false, false, false, true >,
                         cudaFuncAttributeMaxDynamicSharedMemorySize, SMEM);

    const int mblk = (Nn + 63) / 64;   // 313

    // ---- fork: CSR build on side stream ----
    cudaEventRecord(g_e1, 0);
    cudaStreamWaitEvent(g_s2, g_e1, 0);
    cudaMemsetAsync(cntp, 0, Nn * sizeof(int), g_s2);
    count_kernel<<<(Ee + 255) / 256, 256, 0, g_s2>>>(ei);
    scan_kernel<<<1, 1024, 0, g_s2>>>();
    scatter_kernel<<<(TT + 255) / 256, 256, 0, g_s2>>>(ei);
    cudaEventRecord(g_e2, g_s2);

    // ---- main stream: att accumulator zero + splits + GEMM chain ----
    cudaMemsetAsync(asrcp, 0, Nn * Hh * sizeof(float));
    cudaMemsetAsync(adstp, 0, Nn * Hh * sizeof(float));
    split_prep_kernel<<<(SPLIT_TOTAL + 255) / 256, 256>>>(W1, W2, Wg, x);

    bf16gemm<true,  true,  true,  false><<<dim3(1, mblk), 256, SMEM>>>(
        xhi, xlo, w1thi, w1tlo, b1,
        nullptr, h1hi, h1lo, nullptr, nullptr, Nn, HID, F_IN);
    bf16gemm<false, true,  true,  false><<<dim3(1, mblk), 256, SMEM>>>(
        h1hi, h1lo, w2thi, w2tlo, b2,
        nullptr, h2hi, h2lo, nullptr, nullptr, Nn, OUT, HID);
    bf16gemm<false, false, false, true ><<<dim3(2, mblk), 256, SMEM>>>(
        h2hi, h2lo, wgthi, wgtlo, nullptr,
        xg, nullptr, nullptr, att_src, att_dst, Nn, HC, OUT);

    // ---- join: CSR must be done before aggregation ----
    cudaStreamWaitEvent(0, g_e2, 0);
    gat_agg_kernel<<<(Nn + 7) / 8, 256>>>(out, bias_g);
}

// round 16
// speedup vs baseline: 1.6342x; 1.0290x over previous
#include <cuda_runtime.h>
#include <cuda_bf16.h>
#include <math.h>
#include <stdint.h>

#define Nn   20000
#define Ee   320000
#define F_IN 512
#define HID  128
#define OUT  128
#define Hh   4
#define Cc   64
#define HC   256
#define TT   (Ee + Nn)   // edges incl. self loops

// ---------------- scratch (static device globals; no allocation) -------------
__device__ __align__(16) __nv_bfloat16 g_xhi[Nn * F_IN];
__device__ __align__(16) __nv_bfloat16 g_xlo[Nn * F_IN];
__device__ __align__(16) __nv_bfloat16 g_h2hi[Nn * OUT];
__device__ __align__(16) __nv_bfloat16 g_h2lo[Nn * OUT];
__device__ __align__(16) __nv_bfloat16 g_w1thi[HID * F_IN];
__device__ __align__(16) __nv_bfloat16 g_w1tlo[HID * F_IN];
__device__ __align__(16) __nv_bfloat16 g_w2thi[OUT * HID];
__device__ __align__(16) __nv_bfloat16 g_w2tlo[OUT * HID];
__device__ __align__(16) __nv_bfloat16 g_wgthi[HC * OUT];
__device__ __align__(16) __nv_bfloat16 g_wgtlo[HC * OUT];
__device__ __align__(16) float g_xg[Nn * HC];
__device__ __align__(16) float g_asrc[Nn * Hh];
__device__ __align__(16) float g_adst[Nn * Hh];
__device__ __align__(16) float g_alpha[TT * Hh];
__device__ int g_cnt[Nn];
__device__ int g_off[Nn];
__device__ int g_cur[Nn];
__device__ int g_csr[TT];

// ---------------- side stream / events (created pre-main, outside capture) ----
static cudaStream_t g_s2;
static cudaEvent_t  g_e1, g_e2;
static const bool g_stream_init = [] {
    cudaStreamCreateWithFlags(&g_s2, cudaStreamNonBlocking);
    cudaEventCreateWithFlags(&g_e1, cudaEventDisableTiming);
    cudaEventCreateWithFlags(&g_e2, cudaEventDisableTiming);
    return true;
}();

// ---------------- helpers -------------------------------------------------------
__device__ __forceinline__ uint32_t s2u(const void* p) {
    return (uint32_t)__cvta_generic_to_shared(p);
}

__device__ __forceinline__ void cp16(uint32_t dst, const void* src, int bytes) {
    asm volatile("cp.async.cg.shared.global [%0], [%1], 16, %2;"
                 :: "r"(dst), "l"(src), "r"(bytes) : "memory");
}

__device__ __forceinline__ void ldm_x4(uint32_t* r, uint32_t addr) {
    asm volatile("ldmatrix.sync.aligned.m8n8.x4.shared.b16 {%0,%1,%2,%3}, [%4];"
                 : "=r"(r[0]), "=r"(r[1]), "=r"(r[2]), "=r"(r[3]) : "r"(addr));
}
__device__ __forceinline__ void ldm_x2(uint32_t* r, uint32_t addr) {
    asm volatile("ldmatrix.sync.aligned.m8n8.x2.shared.b16 {%0,%1}, [%2];"
                 : "=r"(r[0]), "=r"(r[1]) : "r"(addr));
}

__device__ __forceinline__ void mma_bf16(float* c, const uint32_t* a, const uint32_t* b) {
    asm volatile("mma.sync.aligned.m16n8k16.row.col.f32.bf16.bf16.f32 "
                 "{%0,%1,%2,%3}, {%4,%5,%6,%7}, {%8,%9}, {%0,%1,%2,%3};"
                 : "+f"(c[0]), "+f"(c[1]), "+f"(c[2]), "+f"(c[3])
                 : "r"(a[0]), "r"(a[1]), "r"(a[2]), "r"(a[3]), "r"(b[0]), "r"(b[1]));
}

// ============ fused MLP: h2 = (relu(x@W1+b1))@W2+b2, bf16x3, 64-row tiles ======
// Phase 1: 16 k-chunks (K=512), cp.async double-buffered stages.
// h1 kept in smem (bf16 hi/lo, [64][136]); phase 2: 4 k-chunks (K=128),
// W2t streamed via cp.async double buffer. 3 CTAs/SM (75.8 KB smem).
__global__ __launch_bounds__(256, 3)
void mlp12_kernel(const __nv_bfloat16* __restrict__ Ahi,
                  const __nv_bfloat16* __restrict__ Alo,
                  const __nv_bfloat16* __restrict__ B1hi,
                  const __nv_bfloat16* __restrict__ B1lo,
                  const float* __restrict__ b1,
                  const __nv_bfloat16* __restrict__ B2hi,
                  const __nv_bfloat16* __restrict__ B2lo,
                  const float* __restrict__ b2,
                  __nv_bfloat16* __restrict__ Chi,
                  __nv_bfloat16* __restrict__ Clo,
                  int M) {
    extern __shared__ __nv_bfloat16 sm[];
    constexpr int PAD    = 40;
    constexpr int ALO_O  = 64 * PAD;            // phase-1 stage internals
    constexpr int BHI_O  = 2 * 64 * PAD;
    constexpr int BLO_O  = BHI_O + 128 * PAD;
    constexpr int STAGE1 = BLO_O + 128 * PAD;   // 15360 elems
    constexpr int H1PAD  = 136;                 // phase-2 h1 row stride (odd 16B units)
    constexpr int H1LO_O = 64 * H1PAD;          // 8704
    constexpr int B2_O   = 2 * 64 * H1PAD;      // 17408
    constexpr int S2     = 128 * PAD * 2;       // 10240 elems per phase-2 stage (hi+lo)

    const int tid  = threadIdx.x;
    const int lane = tid & 31;
    const int warp = tid >> 5;
    const int wm = warp & 1;
    const int wn = warp >> 1;
    const int g  = lane >> 2;
    const int t  = lane & 3;

    const int rowBase = blockIdx.x * 64;

    const int a_row = (lane & 7) + ((lane >> 3) & 1) * 8;
    const int a_kof = (lane >> 4) * 8;
    const int b_row = lane & 7;
    const int b_kof = ((lane >> 3) & 1) * 8;

    const int fa_row = tid >> 2;
    const int fa_prt = (tid & 3) * 8;

    float acc[2][4][4];
#pragma unroll
    for (int i = 0; i < 2; i++)
#pragma unroll
        for (int j = 0; j < 4; j++)
#pragma unroll
            for (int q = 0; q < 4; q++) acc[i][j][q] = 0.f;

    // ---------------- phase 1: x @ W1t ----------------
    auto fill1 = [&](int c, int b) {
        const int kt = c << 5;
        __nv_bfloat16* s0 = sm + b * STAGE1;
        {
            const int off = fa_row * PAD + fa_prt;
            const int gr  = rowBase + fa_row;
            const int pr  = gr < M ? gr : M - 1;
            const int nb  = gr < M ? 16 : 0;
            cp16(s2u(s0 + off),         Ahi + (size_t)pr * F_IN + kt + fa_prt, nb);
            cp16(s2u(s0 + ALO_O + off), Alo + (size_t)pr * F_IN + kt + fa_prt, nb);
        }
#pragma unroll
        for (int q = 0; q < 2; q++) {
            const int id   = tid + q * 256;
            const int row  = id >> 2;
            const int part = (id & 3) * 8;
            const int off  = row * PAD + part;
            cp16(s2u(s0 + BHI_O + off), B1hi + (size_t)row * F_IN + kt + part, 16);
            cp16(s2u(s0 + BLO_O + off), B1lo + (size_t)row * F_IN + kt + part, 16);
        }
        asm volatile("cp.async.commit_group;" ::: "memory");
    };

    fill1(0, 0);
    for (int c = 0; c < 16; c++) {
        const int b = c & 1;
        if (c + 1 < 16) {
            fill1(c + 1, b ^ 1);
            asm volatile("cp.async.wait_group 1;" ::: "memory");
        } else {
            asm volatile("cp.async.wait_group 0;" ::: "memory");
        }
        __syncthreads();

        const __nv_bfloat16* Ash = sm + b * STAGE1;
        const __nv_bfloat16* Asl = Ash + ALO_O;
        const __nv_bfloat16* Bsh = Ash + BHI_O;
        const __nv_bfloat16* Bsl = Ash + BLO_O;

#pragma unroll
        for (int ka = 0; ka < 2; ka++) {
            const int k0 = ka * 16;
            uint32_t bhi[4][2], blo[4][2];
#pragma unroll
            for (int na = 0; na < 4; na++) {
                const int n0 = wn * 32 + na * 8;
                ldm_x2(bhi[na], s2u(Bsh + (n0 + b_row) * PAD + k0 + b_kof));
                ldm_x2(blo[na], s2u(Bsl + (n0 + b_row) * PAD + k0 + b_kof));
            }
#pragma unroll
            for (int ma = 0; ma < 2; ma++) {
                const int m0 = wm * 32 + ma * 16;
                uint32_t ahi[4], alo[4];
                ldm_x4(ahi, s2u(Ash + (m0 + a_row) * PAD + k0 + a_kof));
                ldm_x4(alo, s2u(Asl + (m0 + a_row) * PAD + k0 + a_kof));
#pragma unroll
                for (int na = 0; na < 4; na++) {
                    mma_bf16(acc[ma][na], ahi, bhi[na]);
                    mma_bf16(acc[ma][na], alo, bhi[na]);
                    mma_bf16(acc[ma][na], ahi, blo[na]);
                }
            }
        }
        __syncthreads();
    }

    // ---------------- phase-2 B prefetch (chunk 0) ----------------
    auto fill2 = [&](int c, int b) {
        const int kt = c << 5;
        __nv_bfloat16* s0 = sm + B2_O + b * S2;
#pragma unroll
        for (int q = 0; q < 2; q++) {
            const int id   = tid + q * 256;
            const int row  = id >> 2;
            const int part = (id & 3) * 8;
            const int off  = row * PAD + part;
            cp16(s2u(s0 + off),             B2hi + (size_t)row * HID + kt + part, 16);
            cp16(s2u(s0 + 128 * PAD + off), B2lo + (size_t)row * HID + kt + part, 16);
        }
        asm volatile("cp.async.commit_group;" ::: "memory");
    };
    fill2(0, 0);   // into region overlapping dead phase-1 buf1 tail — safe post-sync

    // ---------------- epilogue 1: bias + relu -> h1 smem (bf16 hi/lo) ---------
    {
        __nv_bfloat16* h1h = sm;
        __nv_bfloat16* h1l = sm + H1LO_O;
#pragma unroll
        for (int na = 0; na < 4; na++) {
            const int c = wn * 32 + na * 8 + 2 * t;
            const float2 bb = *(const float2*)(b1 + c);
#pragma unroll
            for (int ma = 0; ma < 2; ma++) {
                const int r0 = wm * 32 + ma * 16 + g;   // local row
                float v0 = fmaxf(acc[ma][na][0] + bb.x, 0.f);
                float v1 = fmaxf(acc[ma][na][1] + bb.y, 0.f);
                float v2 = fmaxf(acc[ma][na][2] + bb.x, 0.f);
                float v3 = fmaxf(acc[ma][na][3] + bb.y, 0.f);
                const __nv_bfloat16 h0 = __float2bfloat16(v0);
                const __nv_bfloat16 h1 = __float2bfloat16(v1);
                const __nv_bfloat16 h2 = __float2bfloat16(v2);
                const __nv_bfloat16 h3 = __float2bfloat16(v3);
                *(__nv_bfloat162*)(h1h + r0 * H1PAD + c) = __halves2bfloat162(h0, h1);
                *(__nv_bfloat162*)(h1l + r0 * H1PAD + c) =
                    __halves2bfloat162(__float2bfloat16(v0 - __bfloat162float(h0)),
                                       __float2bfloat16(v1 - __bfloat162float(h1)));
                *(__nv_bfloat162*)(h1h + (r0 + 8) * H1PAD + c) = __halves2bfloat162(h2, h3);
                *(__nv_bfloat162*)(h1l + (r0 + 8) * H1PAD + c) =
                    __halves2bfloat162(__float2bfloat16(v2 - __bfloat162float(h2)),
                                       __float2bfloat16(v3 - __bfloat162float(h3)));
            }
        }
    }
    __syncthreads();

    // ---------------- phase 2: h1 @ W2t ----------------
#pragma unroll
    for (int i = 0; i < 2; i++)
#pragma unroll
        for (int j = 0; j < 4; j++)
#pragma unroll
            for (int q = 0; q < 4; q++) acc[i][j][q] = 0.f;

    const __nv_bfloat16* h1h = sm;
    const __nv_bfloat16* h1l = sm + H1LO_O;

    for (int c = 0; c < 4; c++) {
        const int b = c & 1;
        if (c + 1 < 4) {
            fill2(c + 1, b ^ 1);
            asm volatile("cp.async.wait_group 1;" ::: "memory");
        } else {
            asm volatile("cp.async.wait_group 0;" ::: "memory");
        }
        __syncthreads();

        const __nv_bfloat16* Bsh = sm + B2_O + b * S2;
        const __nv_bfloat16* Bsl = Bsh + 128 * PAD;

#pragma unroll
        for (int ka = 0; ka < 2; ka++) {
            const int k0 = ka * 16;
            const int kg = c * 32 + k0;
            uint32_t bhi[4][2], blo[4][2];
#pragma unroll
            for (int na = 0; na < 4; na++) {
                const int n0 = wn * 32 + na * 8;
                ldm_x2(bhi[na], s2u(Bsh + (n0 + b_row) * PAD + k0 + b_kof));
                ldm_x2(blo[na], s2u(Bsl + (n0 + b_row) * PAD + k0 + b_kof));
            }
#pragma unroll
            for (int ma = 0; ma < 2; ma++) {
                const int m0 = wm * 32 + ma * 16;
                uint32_t ahi[4], alo[4];
                ldm_x4(ahi, s2u(h1h + (m0 + a_row) * H1PAD + kg + a_kof));
                ldm_x4(alo, s2u(h1l + (m0 + a_row) * H1PAD + kg + a_kof));
#pragma unroll
                for (int na = 0; na < 4; na++) {
                    mma_bf16(acc[ma][na], ahi, bhi[na]);
                    mma_bf16(acc[ma][na], alo, bhi[na]);
                    mma_bf16(acc[ma][na], ahi, blo[na]);
                }
            }
        }
        __syncthreads();
    }

    // ---------------- epilogue 2: bias -> h2 hi/lo global ----------------------
#pragma unroll
    for (int na = 0; na < 4; na++) {
        const int c = wn * 32 + na * 8 + 2 * t;
        const float2 bb = *(const float2*)(b2 + c);
#pragma unroll
        for (int ma = 0; ma < 2; ma++) {
            const int r0 = rowBase + wm * 32 + ma * 16 + g;
            float v0 = acc[ma][na][0] + bb.x;
            float v1 = acc[ma][na][1] + bb.y;
            float v2 = acc[ma][na][2] + bb.x;
            float v3 = acc[ma][na][3] + bb.y;
            if (r0 < M) {
                const __nv_bfloat16 h0 = __float2bfloat16(v0);
                const __nv_bfloat16 h1 = __float2bfloat16(v1);
                *(__nv_bfloat162*)(Chi + (size_t)r0 * OUT + c) = __halves2bfloat162(h0, h1);
                *(__nv_bfloat162*)(Clo + (size_t)r0 * OUT + c) =
                    __halves2bfloat162(__float2bfloat16(v0 - __bfloat162float(h0)),
                                       __float2bfloat16(v1 - __bfloat162float(h1)));
            }
            if (r0 + 8 < M) {
                const __nv_bfloat16 h2 = __float2bfloat16(v2);
                const __nv_bfloat16 h3 = __float2bfloat16(v3);
                *(__nv_bfloat162*)(Chi + (size_t)(r0 + 8) * OUT + c) = __halves2bfloat162(h2, h3);
                *(__nv_bfloat162*)(Clo + (size_t)(r0 + 8) * OUT + c) =
                    __halves2bfloat162(__float2bfloat16(v2 - __bfloat162float(h2)),
                                       __float2bfloat16(v3 - __bfloat162float(h3)));
            }
        }
    }
}

// ============ bf16x3 GEMM (G3 only), 64x128 tile, cp.async, 3 CTAs/SM ==========
template<bool ATT>
__global__ __launch_bounds__(256, 3)
void bf16gemm(const __nv_bfloat16* __restrict__ Ahi,
              const __nv_bfloat16* __restrict__ Alo,
              const __nv_bfloat16* __restrict__ Bhi,
              const __nv_bfloat16* __restrict__ Blo,
              float* __restrict__ Cf,
              const float* __restrict__ att_s,
              const float* __restrict__ att_d,
              int M, int Nc, int K) {
    extern __shared__ __nv_bfloat16 sm[];
    constexpr int PAD   = 40;
    constexpr int ALO_O = 64 * PAD;
    constexpr int BHI_O = 2 * 64 * PAD;
    constexpr int BLO_O = BHI_O + 128 * PAD;
    constexpr int STAGE = BLO_O + 128 * PAD;

    const int tid  = threadIdx.x;
    const int lane = tid & 31;
    const int warp = tid >> 5;
    const int wm = warp & 1;
    const int wn = warp >> 1;
    const int g  = lane >> 2;
    const int t  = lane & 3;

    const int rowBase = blockIdx.y * 64;
    const int colBase = blockIdx.x * 128;

    float acc[2][4][4];
#pragma unroll
    for (int i = 0; i < 2; i++)
#pragma unroll
        for (int j = 0; j < 4; j++)
#pragma unroll
            for (int q = 0; q < 4; q++) acc[i][j][q] = 0.f;

    const int a_row = (lane & 7) + ((lane >> 3) & 1) * 8;
    const int a_kof = (lane >> 4) * 8;
    const int b_row = lane & 7;
    const int b_kof = ((lane >> 3) & 1) * 8;

    const int fa_row = tid >> 2;
    const int fa_prt = (tid & 3) * 8;

    auto fill = [&](int c, int b) {
        const int kt = c << 5;
        __nv_bfloat16* s0 = sm + b * STAGE;
        {
            const int off = fa_row * PAD + fa_prt;
            const int gr  = rowBase + fa_row;
            const int pr  = gr < M ? gr : M - 1;
            const int nb  = gr < M ? 16 : 0;
            cp16(s2u(s0 + off),         Ahi + (size_t)pr * K + kt + fa_prt, nb);
            cp16(s2u(s0 + ALO_O + off), Alo + (size_t)pr * K + kt + fa_prt, nb);
        }
#pragma unroll
        for (int q = 0; q < 2; q++) {
            const int id   = tid + q * 256;
            const int row  = id >> 2;
            const int part = (id & 3) * 8;
            const int off  = row * PAD + part;
            const int gn   = colBase + row;
            cp16(s2u(s0 + BHI_O + off), Bhi + (size_t)gn * K + kt + part, 16);
            cp16(s2u(s0 + BLO_O + off), Blo + (size_t)gn * K + kt + part, 16);
        }
        asm volatile("cp.async.commit_group;" ::: "memory");
    };

    const int nch = K >> 5;
    fill(0, 0);

    for (int c = 0; c < nch; c++) {
        const int b = c & 1;
        if (c + 1 < nch) {
            fill(c + 1, b ^ 1);
            asm volatile("cp.async.wait_group 1;" ::: "memory");
        } else {
            asm volatile("cp.async.wait_group 0;" ::: "memory");
        }
        __syncthreads();

        const __nv_bfloat16* Ash = sm + b * STAGE;
        const __nv_bfloat16* Asl = Ash + ALO_O;
        const __nv_bfloat16* Bsh = Ash + BHI_O;
        const __nv_bfloat16* Bsl = Ash + BLO_O;

#pragma unroll
        for (int ka = 0; ka < 2; ka++) {
            const int k0 = ka * 16;
            uint32_t bhi[4][2], blo[4][2];
#pragma unroll
            for (int na = 0; na < 4; na++) {
                const int n0 = wn * 32 + na * 8;
                ldm_x2(bhi[na], s2u(Bsh + (n0 + b_row) * PAD + k0 + b_kof));
                ldm_x2(blo[na], s2u(Bsl + (n0 + b_row) * PAD + k0 + b_kof));
            }
#pragma unroll
            for (int ma = 0; ma < 2; ma++) {
                const int m0 = wm * 32 + ma * 16;
                uint32_t ahi[4], alo[4];
                ldm_x4(ahi, s2u(Ash + (m0 + a_row) * PAD + k0 + a_kof));
                ldm_x4(alo, s2u(Asl + (m0 + a_row) * PAD + k0 + a_kof));
#pragma unroll
                for (int na = 0; na < 4; na++) {
                    mma_bf16(acc[ma][na], ahi, bhi[na]);
                    mma_bf16(acc[ma][na], alo, bhi[na]);
                    mma_bf16(acc[ma][na], ahi, blo[na]);
                }
            }
        }
        __syncthreads();
    }

    // ---- epilogue stores (fp32) ----
#pragma unroll
    for (int na = 0; na < 4; na++) {
        const int c = colBase + wn * 32 + na * 8 + 2 * t;
#pragma unroll
        for (int ma = 0; ma < 2; ma++) {
            const int r0 = rowBase + wm * 32 + ma * 16 + g;
            if (r0 < M)
                *(float2*)(Cf + (size_t)r0 * Nc + c) =
                    make_float2(acc[ma][na][0], acc[ma][na][1]);
            if (r0 + 8 < M)
                *(float2*)(Cf + (size_t)(r0 + 8) * Nc + c) =
                    make_float2(acc[ma][na][2], acc[ma][na][3]);
        }
    }

    // ---- fused attention coefficients ----
    if (ATT) {
        const int h = (colBase + wn * 32) >> 6;
        float asv[4][2], adv[4][2];
#pragma unroll
        for (int na = 0; na < 4; na++) {
            const int cc = (wn * 32 + na * 8 + 2 * t) & 63;
            asv[na][0] = __ldg(att_s + h * Cc + cc);
            asv[na][1] = __ldg(att_s + h * Cc + cc + 1);
            adv[na][0] = __ldg(att_d + h * Cc + cc);
            adv[na][1] = __ldg(att_d + h * Cc + cc + 1);
        }
#pragma unroll
        for (int ma = 0; ma < 2; ma++) {
            const int r0 = rowBase + wm * 32 + ma * 16 + g;
            float ps0 = 0.f, pd0 = 0.f, ps1 = 0.f, pd1 = 0.f;
#pragma unroll
            for (int na = 0; na < 4; na++) {
                ps0 += acc[ma][na][0] * asv[na][0] + acc[ma][na][1] * asv[na][1];
                pd0 += acc[ma][na][0] * adv[na][0] + acc[ma][na][1] * adv[na][1];
                ps1 += acc[ma][na][2] * asv[na][0] + acc[ma][na][3] * asv[na][1];
                pd1 += acc[ma][na][2] * adv[na][0] + acc[ma][na][3] * adv[na][1];
            }
#pragma unroll
            for (int o = 2; o >= 1; o >>= 1) {
                ps0 += __shfl_down_sync(0xffffffffu, ps0, o);
                pd0 += __shfl_down_sync(0xffffffffu, pd0, o);
                ps1 += __shfl_down_sync(0xffffffffu, ps1, o);
                pd1 += __shfl_down_sync(0xffffffffu, pd1, o);
            }
            if (t == 0) {
                if (r0 < M) {
                    atomicAdd(&g_asrc[r0 * Hh + h], ps0);
                    atomicAdd(&g_adst[r0 * Hh + h], pd0);
                }
                if (r0 + 8 < M) {
                    atomicAdd(&g_asrc[(r0 + 8) * Hh + h], ps1);
                    atomicAdd(&g_adst[(r0 + 8) * Hh + h], pd1);
                }
            }
        }
    }
}

// ---------------- split prep (main stream): weight transposes + x split --------
__device__ __forceinline__ void wt_split_one(const float* __restrict__ W,
                                             __nv_bfloat16* __restrict__ thi,
                                             __nv_bfloat16* __restrict__ tlo,
                                             int K, int N, int i) {
    const int n = i / K, k = i % K;
    const float v = W[(size_t)k * N + n];
    const __nv_bfloat16 h = __float2bfloat16(v);
    thi[i] = h;
    tlo[i] = __float2bfloat16(v - __bfloat162float(h));
}

#define PREP_W1  (F_IN * HID)
#define PREP_W2  (HID * OUT)
#define PREP_WG  (OUT * HC)
#define PREP_X4  (Nn * F_IN / 4)
#define SPLIT_TOTAL (PREP_W1 + PREP_W2 + PREP_WG + PREP_X4)

__global__ void split_prep_kernel(const float* __restrict__ W1,
                                  const float* __restrict__ W2,
                                  const float* __restrict__ Wg,
                                  const float* __restrict__ x) {
    int i = blockIdx.x * blockDim.x + threadIdx.x;
    if (i < PREP_W1) { wt_split_one(W1, g_w1thi, g_w1tlo, F_IN, HID, i); return; }
    i -= PREP_W1;
    if (i < PREP_W2) { wt_split_one(W2, g_w2thi, g_w2tlo, HID, OUT, i); return; }
    i -= PREP_W2;
    if (i < PREP_WG) { wt_split_one(Wg, g_wgthi, g_wgtlo, OUT, HC, i); return; }
    i -= PREP_WG;
    if (i < PREP_X4) {
        const float4 v = *(const float4*)(x + (size_t)i * 4);
        const __nv_bfloat16 h0 = __float2bfloat16(v.x), h1 = __float2bfloat16(v.y);
        const __nv_bfloat16 h2 = __float2bfloat16(v.z), h3 = __float2bfloat16(v.w);
        __nv_bfloat162* hp = (__nv_bfloat162*)(g_xhi + (size_t)i * 4);
        hp[0] = __halves2bfloat162(h0, h1);
        hp[1] = __halves2bfloat162(h2, h3);
        __nv_bfloat162* lp = (__nv_bfloat162*)(g_xlo + (size_t)i * 4);
        lp[0] = __halves2bfloat162(__float2bfloat16(v.x - __bfloat162float(h0)),
                                   __float2bfloat16(v.y - __bfloat162float(h1)));
        lp[1] = __halves2bfloat162(__float2bfloat16(v.z - __bfloat162float(h2)),
                                   __float2bfloat16(v.w - __bfloat162float(h3)));
    }
}

// ---------------- CSR build (side stream) --------------------------------------
__global__ void count_kernel(const int* __restrict__ ei) {
    const int e = blockIdx.x * blockDim.x + threadIdx.x;
    if (e < Ee) atomicAdd(&g_cnt[ei[Ee + e]], 1);
}

__global__ __launch_bounds__(1024)
void scan_kernel() {
    __shared__ int part[1024];
    const int t = threadIdx.x;
    const int CH = (Nn + 1023) / 1024;
    const int base = t * CH;
    int s = 0;
    for (int i = 0; i < CH; i++) {
        const int idx = base + i;
        if (idx < Nn) s += g_cnt[idx] + 1;
    }
    part[t] = s;
    __syncthreads();
    for (int off = 1; off < 1024; off <<= 1) {
        int v = 0;
        if (t >= off) v = part[t - off];
        __syncthreads();
        if (t >= off) part[t] += v;
        __syncthreads();
    }
    int run = (t == 0) ? 0 : part[t - 1];
    for (int i = 0; i < CH; i++) {
        const int idx = base + i;
        if (idx < Nn) {
            const int c = g_cnt[idx] + 1;
            g_off[idx] = run;
            g_cur[idx] = run;
            g_cnt[idx] = c;
            run += c;
        }
    }
}

__global__ void scatter_kernel(const int* __restrict__ ei) {
    const int e = blockIdx.x * blockDim.x + threadIdx.x;
    if (e >= TT) return;
    int src, dst;
    if (e < Ee) { src = ei[e]; dst = ei[Ee + e]; }
    else        { src = dst = e - Ee; }
    const int pos = atomicAdd(&g_cur[dst], 1);
    g_csr[pos] = src;
}

// ---------------- fused GAT softmax + aggregation: one warp per dst -----------
__global__ void gat_agg_kernel(float* __restrict__ out,
                               const float* __restrict__ bias_g) {
    const int d    = (blockIdx.x * blockDim.x + threadIdx.x) >> 5;
    const int lane = threadIdx.x & 31;
    if (d >= Nn) return;

    const int start = g_off[d];
    const int deg   = g_cnt[d];

    const float4 ad = *(const float4*)(g_adst + d * 4);

    float4 sum = make_float4(0.f, 0.f, 0.f, 0.f);
    for (int k = lane; k < deg; k += 32) {
        const int s = g_csr[start + k];
        const float4 as = *(const float4*)(g_asrc + s * 4);
        float ex = as.x + ad.x, ey = as.y + ad.y, ez = as.z + ad.z, ew = as.w + ad.w;
        ex = ex > 0.f ? ex : 0.2f * ex;
        ey = ey > 0.f ? ey : 0.2f * ey;
        ez = ez > 0.f ? ez : 0.2f * ez;
        ew = ew > 0.f ? ew : 0.2f * ew;
        const float4 exv = make_float4(__expf(ex), __expf(ey), __expf(ez), __expf(ew));
        *(float4*)(g_alpha + (size_t)(start + k) * 4) = exv;
        sum.x += exv.x; sum.y += exv.y; sum.z += exv.z; sum.w += exv.w;
    }
#pragma unroll
    for (int o = 16; o > 0; o >>= 1) {
        sum.x += __shfl_down_sync(0xffffffffu, sum.x, o);
        sum.y += __shfl_down_sync(0xffffffffu, sum.y, o);
        sum.z += __shfl_down_sync(0xffffffffu, sum.z, o);
        sum.w += __shfl_down_sync(0xffffffffu, sum.w, o);
    }
    const float dx = __shfl_sync(0xffffffffu, sum.x, 0) + 1e-16f;
    const float dy = __shfl_sync(0xffffffffu, sum.y, 0) + 1e-16f;
    const float dz = __shfl_sync(0xffffffffu, sum.z, 0) + 1e-16f;
    const float dw = __shfl_sync(0xffffffffu, sum.w, 0) + 1e-16f;

    const int h = lane >> 3;
    const float denom = (h == 0) ? dx : (h == 1) ? dy : (h == 2) ? dz : dw;
    const float rden  = 1.f / denom;

    float acc[8];
#pragma unroll
    for (int i = 0; i < 8; i++) acc[i] = 0.f;

    const float* al = g_alpha + (size_t)start * 4;
    int k = 0;
    for (; k + 4 <= deg; k += 4) {
        const int s0 = g_csr[start + k];
        const int s1 = g_csr[start + k + 1];
        const int s2 = g_csr[start + k + 2];
        const int s3 = g_csr[start + k + 3];
        const float a0 = al[(k    ) * 4 + h] * rden;
        const float a1 = al[(k + 1) * 4 + h] * rden;
        const float a2 = al[(k + 2) * 4 + h] * rden;
        const float a3 = al[(k + 3) * 4 + h] * rden;
        const float4* x0 = (const float4*)(g_xg + (size_t)s0 * HC + lane * 8);
        const float4* x1 = (const float4*)(g_xg + (size_t)s1 * HC + lane * 8);
        const float4* x2 = (const float4*)(g_xg + (size_t)s2 * HC + lane * 8);
        const float4* x3 = (const float4*)(g_xg + (size_t)s3 * HC + lane * 8);
        const float4 p0 = x0[0], q0 = x0[1];
        const float4 p1 = x1[0], q1 = x1[1];
        const float4 p2 = x2[0], q2 = x2[1];
        const float4 p3 = x3[0], q3 = x3[1];
        acc[0] = fmaf(a0, p0.x, fmaf(a1, p1.x, fmaf(a2, p2.x, fmaf(a3, p3.x, acc[0]))));
        acc[1] = fmaf(a0, p0.y, fmaf(a1, p1.y, fmaf(a2, p2.y, fmaf(a3, p3.y, acc[1]))));
        acc[2] = fmaf(a0, p0.z, fmaf(a1, p1.z, fmaf(a2, p2.z, fmaf(a3, p3.z, acc[2]))));
        acc[3] = fmaf(a0, p0.w, fmaf(a1, p1.w, fmaf(a2, p2.w, fmaf(a3, p3.w, acc[3]))));
        acc[4] = fmaf(a0, q0.x, fmaf(a1, q1.x, fmaf(a2, q2.x, fmaf(a3, q3.x, acc[4]))));
        acc[5] = fmaf(a0, q0.y, fmaf(a1, q1.y, fmaf(a2, q2.y, fmaf(a3, q3.y, acc[5]))));
        acc[6] = fmaf(a0, q0.z, fmaf(a1, q1.z, fmaf(a2, q2.z, fmaf(a3, q3.z, acc[6]))));
        acc[7] = fmaf(a0, q0.w, fmaf(a1, q1.w, fmaf(a2, q2.w, fmaf(a3, q3.w, acc[7]))));
    }
    for (; k < deg; k++) {
        const int s = g_csr[start + k];
        const float a = al[k * 4 + h] * rden;
        const float4* xr = (const float4*)(g_xg + (size_t)s * HC + lane * 8);
        const float4 v0 = xr[0];
        const float4 v1 = xr[1];
        acc[0] = fmaf(a, v0.x, acc[0]);
        acc[1] = fmaf(a, v0.y, acc[1]);
        acc[2] = fmaf(a, v0.z, acc[2]);
        acc[3] = fmaf(a, v0.w, acc[3]);
        acc[4] = fmaf(a, v1.x, acc[4]);
        acc[5] = fmaf(a, v1.y, acc[5]);
        acc[6] = fmaf(a, v1.z, acc[6]);
        acc[7] = fmaf(a, v1.w, acc[7]);
    }

    const float4 bg0 = *(const float4*)(bias_g + lane * 8);
    const float4 bg1 = *(const float4*)(bias_g + lane * 8 + 4);
    float* op = out + (size_t)d * HC + lane * 8;
    *(float4*)op       = make_float4(acc[0] + bg0.x, acc[1] + bg0.y,
                                     acc[2] + bg0.z, acc[3] + bg0.w);
    *(float4*)(op + 4) = make_float4(acc[4] + bg1.x, acc[5] + bg1.y,
                                     acc[6] + bg1.z, acc[7] + bg1.w);
}

// ---------------- launch --------------------------------------------------------
extern "C" void kernel_launch(void* const* d_in, const int* in_sizes, int n_in,
                              void* d_out, int out_size) {
    const float* x   = (const float*)d_in[0];
    const int*   ei  = (const int*)d_in[1];
    const float* W1  = (const float*)d_in[2];
    const float* b1  = (const float*)d_in[3];
    const float* W2  = (const float*)d_in[4];
    const float* b2  = (const float*)d_in[5];
    const float* Wg  = (const float*)d_in[6];
    const float* att_src = (const float*)d_in[7];
    const float* att_dst = (const float*)d_in[8];
    const float* bias_g  = (const float*)d_in[9];
    float* out = (float*)d_out;

    __nv_bfloat16 *xhi, *xlo, *h2hi, *h2lo;
    __nv_bfloat16 *w1thi, *w1tlo, *w2thi, *w2tlo, *wgthi, *wgtlo;
    float *xg, *asrcp, *adstp;
    int* cntp;
    cudaGetSymbolAddress((void**)&xhi,  g_xhi);
    cudaGetSymbolAddress((void**)&xlo,  g_xlo);
    cudaGetSymbolAddress((void**)&h2hi, g_h2hi);
    cudaGetSymbolAddress((void**)&h2lo, g_h2lo);
    cudaGetSymbolAddress((void**)&w1thi, g_w1thi);
    cudaGetSymbolAddress((void**)&w1tlo, g_w1tlo);
    cudaGetSymbolAddress((void**)&w2thi, g_w2thi);
    cudaGetSymbolAddress((void**)&w2tlo, g_w2tlo);
    cudaGetSymbolAddress((void**)&wgthi, g_wgthi);
    cudaGetSymbolAddress((void**)&wgtlo, g_wgtlo);
    cudaGetSymbolAddress((void**)&xg, g_xg);
    cudaGetSymbolAddress((void**)&asrcp, g_asrc);
    cudaGetSymbolAddress((void**)&adstp, g_adst);
    cudaGetSymbolAddress((void**)&cntp, g_cnt);

    const int SMEM_G  = 2 * (64 + 64 + 128 + 128) * 40 * (int)sizeof(__nv_bfloat16);  // 61440
    const int SMEM_F  = (2 * 64 * 136 + 2 * 128 * 40 * 2) * (int)sizeof(__nv_bfloat16); // 75776
    cudaFuncSetAttribute(mlp12_kernel,
                         cudaFuncAttributeMaxDynamicSharedMemorySize, SMEM_F);
    cudaFuncSetAttribute(bf16gemm<true>,
                         cudaFuncAttributeMaxDynamicSharedMemorySize, SMEM_G);

    const int mblk = (Nn + 63) / 64;   // 313

    // ---- fork: CSR build on side stream ----
    cudaEventRecord(g_e1, 0);
    cudaStreamWaitEvent(g_s2, g_e1, 0);
    cudaMemsetAsync(cntp, 0, Nn * sizeof(int), g_s2);
    count_kernel<<<(Ee + 255) / 256, 256, 0, g_s2>>>(ei);
    scan_kernel<<<1, 1024, 0, g_s2>>>();
    scatter_kernel<<<(TT + 255) / 256, 256, 0, g_s2>>>(ei);
    cudaEventRecord(g_e2, g_s2);

    // ---- main stream: att accumulator zero + splits + fused MLP + G3 ----
    cudaMemsetAsync(asrcp, 0, Nn * Hh * sizeof(float));
    cudaMemsetAsync(adstp, 0, Nn * Hh * sizeof(float));
    split_prep_kernel<<<(SPLIT_TOTAL + 255) / 256, 256>>>(W1, W2, Wg, x);

    mlp12_kernel<<<mblk, 256, SMEM_F>>>(
        xhi, xlo, w1thi, w1tlo, b1, w2thi, w2tlo, b2, h2hi, h2lo, Nn);

    bf16gemm<true><<<dim3(2, mblk), 256, SMEM_G>>>(
        h2hi, h2lo, wgthi, wgtlo, xg, att_src, att_dst, Nn, HC, OUT);

    // ---- join: CSR must be done before aggregation ----
    cudaStreamWaitEvent(0, g_e2, 0);
    gat_agg_kernel<<<(Nn + 7) / 8, 256>>>(out, bias_g);
}

// round 17
// speedup vs baseline: 1.6567x; 1.0138x over previous
#include <cuda_runtime.h>
#include <cuda_bf16.h>
#include <math.h>
#include <stdint.h>

#define Nn   20000
#define Ee   320000
#define F_IN 512
#define HID  128
#define OUT  128
#define Hh   4
#define Cc   64
#define HC   256
#define TT   (Ee + Nn)   // edges incl. self loops

// ---------------- scratch (static device globals; no allocation) -------------
__device__ __align__(16) __nv_bfloat16 g_xhi[Nn * F_IN];
__device__ __align__(16) __nv_bfloat16 g_xlo[Nn * F_IN];
__device__ __align__(16) __nv_bfloat16 g_w1thi[HID * F_IN];
__device__ __align__(16) __nv_bfloat16 g_w1tlo[HID * F_IN];
__device__ __align__(16) __nv_bfloat16 g_w2thi[OUT * HID];
__device__ __align__(16) __nv_bfloat16 g_w2tlo[OUT * HID];
__device__ __align__(16) __nv_bfloat16 g_wgthi[HC * OUT];
__device__ __align__(16) __nv_bfloat16 g_wgtlo[HC * OUT];
__device__ __align__(16) float g_xg[Nn * HC];
__device__ __align__(16) float g_asrc[Nn * Hh];
__device__ __align__(16) float g_adst[Nn * Hh];
__device__ __align__(16) float g_alpha[TT * Hh];
__device__ int g_cnt[Nn];
__device__ int g_off[Nn];
__device__ int g_cur[Nn];
__device__ int g_csr[TT];

// ---------------- side stream / events (created pre-main, outside capture) ----
static cudaStream_t g_s2;
static cudaEvent_t  g_e1, g_e2;
static const bool g_stream_init = [] {
    cudaStreamCreateWithFlags(&g_s2, cudaStreamNonBlocking);
    cudaEventCreateWithFlags(&g_e1, cudaEventDisableTiming);
    cudaEventCreateWithFlags(&g_e2, cudaEventDisableTiming);
    return true;
}();

// ---------------- helpers -------------------------------------------------------
__device__ __forceinline__ uint32_t s2u(const void* p) {
    return (uint32_t)__cvta_generic_to_shared(p);
}

__device__ __forceinline__ void cp16(uint32_t dst, const void* src, int bytes) {
    asm volatile("cp.async.cg.shared.global [%0], [%1], 16, %2;"
                 :: "r"(dst), "l"(src), "r"(bytes) : "memory");
}

__device__ __forceinline__ void ldm_x4(uint32_t* r, uint32_t addr) {
    asm volatile("ldmatrix.sync.aligned.m8n8.x4.shared.b16 {%0,%1,%2,%3}, [%4];"
                 : "=r"(r[0]), "=r"(r[1]), "=r"(r[2]), "=r"(r[3]) : "r"(addr));
}
__device__ __forceinline__ void ldm_x2(uint32_t* r, uint32_t addr) {
    asm volatile("ldmatrix.sync.aligned.m8n8.x2.shared.b16 {%0,%1}, [%2];"
                 : "=r"(r[0]), "=r"(r[1]) : "r"(addr));
}

__device__ __forceinline__ void mma_bf16(float* c, const uint32_t* a, const uint32_t* b) {
    asm volatile("mma.sync.aligned.m16n8k16.row.col.f32.bf16.bf16.f32 "
                 "{%0,%1,%2,%3}, {%4,%5,%6,%7}, {%8,%9}, {%0,%1,%2,%3};"
                 : "+f"(c[0]), "+f"(c[1]), "+f"(c[2]), "+f"(c[3])
                 : "r"(a[0]), "r"(a[1]), "r"(a[2]), "r"(a[3]), "r"(b[0]), "r"(b[1]));
}

// ============ fully fused GNN front-end ========================================
// Per 64-row CTA: phase1 h1=relu(x@W1t+b1) -> smem; phase2 h2=h1@W2t+b2 -> smem;
// phase3 xg=h2@Wgt (two N=128 halves) -> global + fused attention coefficients.
// bf16x3 everywhere, cp.async double-buffered B tiles, 3 CTAs/SM.
__global__ __launch_bounds__(256, 3)
void gnn_mlp_kernel(const __nv_bfloat16* __restrict__ Ahi,
                    const __nv_bfloat16* __restrict__ Alo,
                    const __nv_bfloat16* __restrict__ B1hi,
                    const __nv_bfloat16* __restrict__ B1lo,
                    const float* __restrict__ b1,
                    const __nv_bfloat16* __restrict__ B2hi,
                    const __nv_bfloat16* __restrict__ B2lo,
                    const float* __restrict__ b2,
                    const __nv_bfloat16* __restrict__ BGhi,
                    const __nv_bfloat16* __restrict__ BGlo,
                    float* __restrict__ xg,
                    const float* __restrict__ att_s,
                    const float* __restrict__ att_d,
                    int M) {
    extern __shared__ __nv_bfloat16 sm[];
    constexpr int PAD    = 40;
    constexpr int ALO_O  = 64 * PAD;
    constexpr int BHI_O  = 2 * 64 * PAD;
    constexpr int BLO_O  = BHI_O + 128 * PAD;
    constexpr int STAGE1 = BLO_O + 128 * PAD;   // phase-1 stage: 15360 elems
    constexpr int HPAD   = 136;                 // h buffer row stride
    constexpr int HLO_O  = 64 * HPAD;           // 8704
    constexpr int B2_O   = 2 * 64 * HPAD;       // 17408 (B staging, phases 2&3)
    constexpr int S2     = 128 * PAD * 2;       // 10240 per stage (hi+lo)

    const int tid  = threadIdx.x;
    const int lane = tid & 31;
    const int warp = tid >> 5;
    const int wm = warp & 1;
    const int wn = warp >> 1;
    const int g  = lane >> 2;
    const int t  = lane & 3;

    const int rowBase = blockIdx.x * 64;

    const int a_row = (lane & 7) + ((lane >> 3) & 1) * 8;
    const int a_kof = (lane >> 4) * 8;
    const int b_row = lane & 7;
    const int b_kof = ((lane >> 3) & 1) * 8;

    const int fa_row = tid >> 2;
    const int fa_prt = (tid & 3) * 8;

    float acc[2][4][4];
#pragma unroll
    for (int i = 0; i < 2; i++)
#pragma unroll
        for (int j = 0; j < 4; j++)
#pragma unroll
            for (int q = 0; q < 4; q++) acc[i][j][q] = 0.f;

    // ---------------- phase 1: x @ W1t ----------------
    auto fill1 = [&](int c, int b) {
        const int kt = c << 5;
        __nv_bfloat16* s0 = sm + b * STAGE1;
        {
            const int off = fa_row * PAD + fa_prt;
            const int gr  = rowBase + fa_row;
            const int pr  = gr < M ? gr : M - 1;
            const int nb  = gr < M ? 16 : 0;
            cp16(s2u(s0 + off),         Ahi + (size_t)pr * F_IN + kt + fa_prt, nb);
            cp16(s2u(s0 + ALO_O + off), Alo + (size_t)pr * F_IN + kt + fa_prt, nb);
        }
#pragma unroll
        for (int q = 0; q < 2; q++) {
            const int id   = tid + q * 256;
            const int row  = id >> 2;
            const int part = (id & 3) * 8;
            const int off  = row * PAD + part;
            cp16(s2u(s0 + BHI_O + off), B1hi + (size_t)row * F_IN + kt + part, 16);
            cp16(s2u(s0 + BLO_O + off), B1lo + (size_t)row * F_IN + kt + part, 16);
        }
        asm volatile("cp.async.commit_group;" ::: "memory");
    };

    fill1(0, 0);
    for (int c = 0; c < 16; c++) {
        const int b = c & 1;
        if (c + 1 < 16) {
            fill1(c + 1, b ^ 1);
            asm volatile("cp.async.wait_group 1;" ::: "memory");
        } else {
            asm volatile("cp.async.wait_group 0;" ::: "memory");
        }
        __syncthreads();

        const __nv_bfloat16* Ash = sm + b * STAGE1;
        const __nv_bfloat16* Asl = Ash + ALO_O;
        const __nv_bfloat16* Bsh = Ash + BHI_O;
        const __nv_bfloat16* Bsl = Ash + BLO_O;

#pragma unroll
        for (int ka = 0; ka < 2; ka++) {
            const int k0 = ka * 16;
            uint32_t bhi[4][2], blo[4][2];
#pragma unroll
            for (int na = 0; na < 4; na++) {
                const int n0 = wn * 32 + na * 8;
                ldm_x2(bhi[na], s2u(Bsh + (n0 + b_row) * PAD + k0 + b_kof));
                ldm_x2(blo[na], s2u(Bsl + (n0 + b_row) * PAD + k0 + b_kof));
            }
#pragma unroll
            for (int ma = 0; ma < 2; ma++) {
                const int m0 = wm * 32 + ma * 16;
                uint32_t ahi[4], alo[4];
                ldm_x4(ahi, s2u(Ash + (m0 + a_row) * PAD + k0 + a_kof));
                ldm_x4(alo, s2u(Asl + (m0 + a_row) * PAD + k0 + a_kof));
#pragma unroll
                for (int na = 0; na < 4; na++) {
                    mma_bf16(acc[ma][na], ahi, bhi[na]);
                    mma_bf16(acc[ma][na], alo, bhi[na]);
                    mma_bf16(acc[ma][na], ahi, blo[na]);
                }
            }
        }
        __syncthreads();
    }

    // generic phase-2/3 B filler: rows [rbase, rbase+128) of a [*,HID] matrix
    auto fillB = [&](const __nv_bfloat16* Bh, const __nv_bfloat16* Bl,
                     int rbase, int c, int b) {
        const int kt = c << 5;
        __nv_bfloat16* s0 = sm + B2_O + b * S2;
#pragma unroll
        for (int q = 0; q < 2; q++) {
            const int id   = tid + q * 256;
            const int row  = id >> 2;
            const int part = (id & 3) * 8;
            const int off  = row * PAD + part;
            cp16(s2u(s0 + off),             Bh + (size_t)(rbase + row) * HID + kt + part, 16);
            cp16(s2u(s0 + 128 * PAD + off), Bl + (size_t)(rbase + row) * HID + kt + part, 16);
        }
        asm volatile("cp.async.commit_group;" ::: "memory");
    };

    // writes acc (with bias, optional relu) into the smem h buffer as hi/lo
    auto acc_to_smem = [&](const float* __restrict__ bias, bool relu) {
        __nv_bfloat16* hh = sm;
        __nv_bfloat16* hl = sm + HLO_O;
#pragma unroll
        for (int na = 0; na < 4; na++) {
            const int c = wn * 32 + na * 8 + 2 * t;
            const float2 bb = *(const float2*)(bias + c);
#pragma unroll
            for (int ma = 0; ma < 2; ma++) {
                const int r0 = wm * 32 + ma * 16 + g;
                float v0 = acc[ma][na][0] + bb.x;
                float v1 = acc[ma][na][1] + bb.y;
                float v2 = acc[ma][na][2] + bb.x;
                float v3 = acc[ma][na][3] + bb.y;
                if (relu) {
                    v0 = fmaxf(v0, 0.f); v1 = fmaxf(v1, 0.f);
                    v2 = fmaxf(v2, 0.f); v3 = fmaxf(v3, 0.f);
                }
                const __nv_bfloat16 h0 = __float2bfloat16(v0);
                const __nv_bfloat16 h1 = __float2bfloat16(v1);
                const __nv_bfloat16 h2 = __float2bfloat16(v2);
                const __nv_bfloat16 h3 = __float2bfloat16(v3);
                *(__nv_bfloat162*)(hh + r0 * HPAD + c) = __halves2bfloat162(h0, h1);
                *(__nv_bfloat162*)(hl + r0 * HPAD + c) =
                    __halves2bfloat162(__float2bfloat16(v0 - __bfloat162float(h0)),
                                       __float2bfloat16(v1 - __bfloat162float(h1)));
                *(__nv_bfloat162*)(hh + (r0 + 8) * HPAD + c) = __halves2bfloat162(h2, h3);
                *(__nv_bfloat162*)(hl + (r0 + 8) * HPAD + c) =
                    __halves2bfloat162(__float2bfloat16(v2 - __bfloat162float(h2)),
                                       __float2bfloat16(v3 - __bfloat162float(h3)));
            }
        }
    };

    // smem-A x streamed-B mainloop over 4 k-chunks (K = HID = 128)
    auto phaseK128 = [&](const __nv_bfloat16* Bh, const __nv_bfloat16* Bl, int rbase) {
#pragma unroll
        for (int i = 0; i < 2; i++)
#pragma unroll
            for (int j = 0; j < 4; j++)
#pragma unroll
                for (int q = 0; q < 4; q++) acc[i][j][q] = 0.f;

        const __nv_bfloat16* hh = sm;
        const __nv_bfloat16* hl = sm + HLO_O;

        for (int c = 0; c < 4; c++) {
            const int b = c & 1;
            if (c + 1 < 4) {
                fillB(Bh, Bl, rbase, c + 1, b ^ 1);
                asm volatile("cp.async.wait_group 1;" ::: "memory");
            } else {
                asm volatile("cp.async.wait_group 0;" ::: "memory");
            }
            __syncthreads();

            const __nv_bfloat16* Bsh = sm + B2_O + b * S2;
            const __nv_bfloat16* Bsl = Bsh + 128 * PAD;

#pragma unroll
            for (int ka = 0; ka < 2; ka++) {
                const int k0 = ka * 16;
                const int kg = c * 32 + k0;
                uint32_t bhi[4][2], blo[4][2];
#pragma unroll
                for (int na = 0; na < 4; na++) {
                    const int n0 = wn * 32 + na * 8;
                    ldm_x2(bhi[na], s2u(Bsh + (n0 + b_row) * PAD + k0 + b_kof));
                    ldm_x2(blo[na], s2u(Bsl + (n0 + b_row) * PAD + k0 + b_kof));
                }
#pragma unroll
                for (int ma = 0; ma < 2; ma++) {
                    const int m0 = wm * 32 + ma * 16;
                    uint32_t ahi[4], alo[4];
                    ldm_x4(ahi, s2u(hh + (m0 + a_row) * HPAD + kg + a_kof));
                    ldm_x4(alo, s2u(hl + (m0 + a_row) * HPAD + kg + a_kof));
#pragma unroll
                    for (int na = 0; na < 4; na++) {
                        mma_bf16(acc[ma][na], ahi, bhi[na]);
                        mma_bf16(acc[ma][na], alo, bhi[na]);
                        mma_bf16(acc[ma][na], ahi, blo[na]);
                    }
                }
            }
            __syncthreads();
        }
    };

    // ---------------- phase 2: h1 @ W2t ----------------
    fillB(B2hi, B2lo, 0, 0, 0);   // prefetch chunk 0 (region idle post-sync)
    acc_to_smem(b1, true);        // h1 -> smem
    __syncthreads();
    phaseK128(B2hi, B2lo, 0);

    // ---------------- phase 3: h2 @ Wgt, two N=128 halves -----------------------
    fillB(BGhi, BGlo, 0, 0, 0);   // prefetch Wg half 0 chunk 0
    acc_to_smem(b2, false);       // h2 -> smem (overwrites h1, post-sync)
    __syncthreads();

#pragma unroll
    for (int nb = 0; nb < 2; nb++) {
        phaseK128(BGhi, BGlo, nb * 128);
        if (nb == 0) fillB(BGhi, BGlo, 128, 0, 0);   // prefetch half 1 chunk 0

        // epilogue: xg fp32 + fused attention coefficients
        const int h = nb * 2 + (wn >> 1);
        float asv[4][2], adv[4][2];
#pragma unroll
        for (int na = 0; na < 4; na++) {
            const int cc = (wn * 32 + na * 8 + 2 * t) & 63;
            asv[na][0] = __ldg(att_s + h * Cc + cc);
            asv[na][1] = __ldg(att_s + h * Cc + cc + 1);
            adv[na][0] = __ldg(att_d + h * Cc + cc);
            adv[na][1] = __ldg(att_d + h * Cc + cc + 1);
        }
#pragma unroll
        for (int ma = 0; ma < 2; ma++) {
            const int r0 = rowBase + wm * 32 + ma * 16 + g;
            float ps0 = 0.f, pd0 = 0.f, ps1 = 0.f, pd1 = 0.f;
#pragma unroll
            for (int na = 0; na < 4; na++) {
                const int c = nb * 128 + wn * 32 + na * 8 + 2 * t;
                if (r0 < M)
                    *(float2*)(xg + (size_t)r0 * HC + c) =
                        make_float2(acc[ma][na][0], acc[ma][na][1]);
                if (r0 + 8 < M)
                    *(float2*)(xg + (size_t)(r0 + 8) * HC + c) =
                        make_float2(acc[ma][na][2], acc[ma][na][3]);
                ps0 += acc[ma][na][0] * asv[na][0] + acc[ma][na][1] * asv[na][1];
                pd0 += acc[ma][na][0] * adv[na][0] + acc[ma][na][1] * adv[na][1];
                ps1 += acc[ma][na][2] * asv[na][0] + acc[ma][na][3] * asv[na][1];
                pd1 += acc[ma][na][2] * adv[na][0] + acc[ma][na][3] * adv[na][1];
            }
#pragma unroll
            for (int o = 2; o >= 1; o >>= 1) {
                ps0 += __shfl_down_sync(0xffffffffu, ps0, o);
                pd0 += __shfl_down_sync(0xffffffffu, pd0, o);
                ps1 += __shfl_down_sync(0xffffffffu, ps1, o);
                pd1 += __shfl_down_sync(0xffffffffu, pd1, o);
            }
            if (t == 0) {
                if (r0 < M) {
                    atomicAdd(&g_asrc[r0 * Hh + h], ps0);
                    atomicAdd(&g_adst[r0 * Hh + h], pd0);
                }
                if (r0 + 8 < M) {
                    atomicAdd(&g_asrc[(r0 + 8) * Hh + h], ps1);
                    atomicAdd(&g_adst[(r0 + 8) * Hh + h], pd1);
                }
            }
        }
    }
}

// ---------------- split prep (main stream): weight transposes + x split --------
__device__ __forceinline__ void wt_split_one(const float* __restrict__ W,
                                             __nv_bfloat16* __restrict__ thi,
                                             __nv_bfloat16* __restrict__ tlo,
                                             int K, int N, int i) {
    const int n = i / K, k = i % K;
    const float v = W[(size_t)k * N + n];
    const __nv_bfloat16 h = __float2bfloat16(v);
    thi[i] = h;
    tlo[i] = __float2bfloat16(v - __bfloat162float(h));
}

#define PREP_W1  (F_IN * HID)
#define PREP_W2  (HID * OUT)
#define PREP_WG  (OUT * HC)
#define PREP_X4  (Nn * F_IN / 4)
#define SPLIT_TOTAL (PREP_W1 + PREP_W2 + PREP_WG + PREP_X4)

__global__ void split_prep_kernel(const float* __restrict__ W1,
                                  const float* __restrict__ W2,
                                  const float* __restrict__ Wg,
                                  const float* __restrict__ x) {
    int i = blockIdx.x * blockDim.x + threadIdx.x;
    if (i < PREP_W1) { wt_split_one(W1, g_w1thi, g_w1tlo, F_IN, HID, i); return; }
    i -= PREP_W1;
    if (i < PREP_W2) { wt_split_one(W2, g_w2thi, g_w2tlo, HID, OUT, i); return; }
    i -= PREP_W2;
    if (i < PREP_WG) { wt_split_one(Wg, g_wgthi, g_wgtlo, OUT, HC, i); return; }
    i -= PREP_WG;
    if (i < PREP_X4) {
        const float4 v = *(const float4*)(x + (size_t)i * 4);
        const __nv_bfloat16 h0 = __float2bfloat16(v.x), h1 = __float2bfloat16(v.y);
        const __nv_bfloat16 h2 = __float2bfloat16(v.z), h3 = __float2bfloat16(v.w);
        __nv_bfloat162* hp = (__nv_bfloat162*)(g_xhi + (size_t)i * 4);
        hp[0] = __halves2bfloat162(h0, h1);
        hp[1] = __halves2bfloat162(h2, h3);
        __nv_bfloat162* lp = (__nv_bfloat162*)(g_xlo + (size_t)i * 4);
        lp[0] = __halves2bfloat162(__float2bfloat16(v.x - __bfloat162float(h0)),
                                   __float2bfloat16(v.y - __bfloat162float(h1)));
        lp[1] = __halves2bfloat162(__float2bfloat16(v.z - __bfloat162float(h2)),
                                   __float2bfloat16(v.w - __bfloat162float(h3)));
    }
}

// ---------------- CSR build (side stream) --------------------------------------
__global__ void count_kernel(const int* __restrict__ ei) {
    const int e = blockIdx.x * blockDim.x + threadIdx.x;
    if (e < Ee) atomicAdd(&g_cnt[ei[Ee + e]], 1);
}

__global__ __launch_bounds__(1024)
void scan_kernel() {
    __shared__ int part[1024];
    const int t = threadIdx.x;
    const int CH = (Nn + 1023) / 1024;
    const int base = t * CH;
    int s = 0;
    for (int i = 0; i < CH; i++) {
        const int idx = base + i;
        if (idx < Nn) s += g_cnt[idx] + 1;
    }
    part[t] = s;
    __syncthreads();
    for (int off = 1; off < 1024; off <<= 1) {
        int v = 0;
        if (t >= off) v = part[t - off];
        __syncthreads();
        if (t >= off) part[t] += v;
        __syncthreads();
    }
    int run = (t == 0) ? 0 : part[t - 1];
    for (int i = 0; i < CH; i++) {
        const int idx = base + i;
        if (idx < Nn) {
            const int c = g_cnt[idx] + 1;
            g_off[idx] = run;
            g_cur[idx] = run;
            g_cnt[idx] = c;
            run += c;
        }
    }
}

__global__ void scatter_kernel(const int* __restrict__ ei) {
    const int e = blockIdx.x * blockDim.x + threadIdx.x;
    if (e >= TT) return;
    int src, dst;
    if (e < Ee) { src = ei[e]; dst = ei[Ee + e]; }
    else        { src = dst = e - Ee; }
    const int pos = atomicAdd(&g_cur[dst], 1);
    g_csr[pos] = src;
}

// ---------------- fused GAT softmax + aggregation: one warp per dst -----------
__global__ void gat_agg_kernel(float* __restrict__ out,
                               const float* __restrict__ bias_g) {
    const int d    = (blockIdx.x * blockDim.x + threadIdx.x) >> 5;
    const int lane = threadIdx.x & 31;
    if (d >= Nn) return;

    const int start = g_off[d];
    const int deg   = g_cnt[d];

    const float4 ad = *(const float4*)(g_adst + d * 4);

    float4 sum = make_float4(0.f, 0.f, 0.f, 0.f);
    for (int k = lane; k < deg; k += 32) {
        const int s = g_csr[start + k];
        const float4 as = *(const float4*)(g_asrc + s * 4);
        float ex = as.x + ad.x, ey = as.y + ad.y, ez = as.z + ad.z, ew = as.w + ad.w;
        ex = ex > 0.f ? ex : 0.2f * ex;
        ey = ey > 0.f ? ey : 0.2f * ey;
        ez = ez > 0.f ? ez : 0.2f * ez;
        ew = ew > 0.f ? ew : 0.2f * ew;
        const float4 exv = make_float4(__expf(ex), __expf(ey), __expf(ez), __expf(ew));
        *(float4*)(g_alpha + (size_t)(start + k) * 4) = exv;
        sum.x += exv.x; sum.y += exv.y; sum.z += exv.z; sum.w += exv.w;
    }
#pragma unroll
    for (int o = 16; o > 0; o >>= 1) {
        sum.x += __shfl_down_sync(0xffffffffu, sum.x, o);
        sum.y += __shfl_down_sync(0xffffffffu, sum.y, o);
        sum.z += __shfl_down_sync(0xffffffffu, sum.z, o);
        sum.w += __shfl_down_sync(0xffffffffu, sum.w, o);
    }
    const float dx = __shfl_sync(0xffffffffu, sum.x, 0) + 1e-16f;
    const float dy = __shfl_sync(0xffffffffu, sum.y, 0) + 1e-16f;
    const float dz = __shfl_sync(0xffffffffu, sum.z, 0) + 1e-16f;
    const float dw = __shfl_sync(0xffffffffu, sum.w, 0) + 1e-16f;

    const int h = lane >> 3;
    const float denom = (h == 0) ? dx : (h == 1) ? dy : (h == 2) ? dz : dw;
    const float rden  = 1.f / denom;

    float acc[8];
#pragma unroll
    for (int i = 0; i < 8; i++) acc[i] = 0.f;

    const float* al = g_alpha + (size_t)start * 4;
    int k = 0;
    for (; k + 4 <= deg; k += 4) {
        const int s0 = g_csr[start + k];
        const int s1 = g_csr[start + k + 1];
        const int s2 = g_csr[start + k + 2];
        const int s3 = g_csr[start + k + 3];
        const float a0 = al[(k    ) * 4 + h] * rden;
        const float a1 = al[(k + 1) * 4 + h] * rden;
        const float a2 = al[(k + 2) * 4 + h] * rden;
        const float a3 = al[(k + 3) * 4 + h] * rden;
        const float4* x0 = (const float4*)(g_xg + (size_t)s0 * HC + lane * 8);
        const float4* x1 = (const float4*)(g_xg + (size_t)s1 * HC + lane * 8);
        const float4* x2 = (const float4*)(g_xg + (size_t)s2 * HC + lane * 8);
        const float4* x3 = (const float4*)(g_xg + (size_t)s3 * HC + lane * 8);
        const float4 p0 = x0[0], q0 = x0[1];
        const float4 p1 = x1[0], q1 = x1[1];
        const float4 p2 = x2[0], q2 = x2[1];
        const float4 p3 = x3[0], q3 = x3[1];
        acc[0] = fmaf(a0, p0.x, fmaf(a1, p1.x, fmaf(a2, p2.x, fmaf(a3, p3.x, acc[0]))));
        acc[1] = fmaf(a0, p0.y, fmaf(a1, p1.y, fmaf(a2, p2.y, fmaf(a3, p3.y, acc[1]))));
        acc[2] = fmaf(a0, p0.z, fmaf(a1, p1.z, fmaf(a2, p2.z, fmaf(a3, p3.z, acc[2]))));
        acc[3] = fmaf(a0, p0.w, fmaf(a1, p1.w, fmaf(a2, p2.w, fmaf(a3, p3.w, acc[3]))));
        acc[4] = fmaf(a0, q0.x, fmaf(a1, q1.x, fmaf(a2, q2.x, fmaf(a3, q3.x, acc[4]))));
        acc[5] = fmaf(a0, q0.y, fmaf(a1, q1.y, fmaf(a2, q2.y, fmaf(a3, q3.y, acc[5]))));
        acc[6] = fmaf(a0, q0.z, fmaf(a1, q1.z, fmaf(a2, q2.z, fmaf(a3, q3.z, acc[6]))));
        acc[7] = fmaf(a0, q0.w, fmaf(a1, q1.w, fmaf(a2, q2.w, fmaf(a3, q3.w, acc[7]))));
    }
    for (; k < deg; k++) {
        const int s = g_csr[start + k];
        const float a = al[k * 4 + h] * rden;
        const float4* xr = (const float4*)(g_xg + (size_t)s * HC + lane * 8);
        const float4 v0 = xr[0];
        const float4 v1 = xr[1];
        acc[0] = fmaf(a, v0.x, acc[0]);
        acc[1] = fmaf(a, v0.y, acc[1]);
        acc[2] = fmaf(a, v0.z, acc[2]);
        acc[3] = fmaf(a, v0.w, acc[3]);
        acc[4] = fmaf(a, v1.x, acc[4]);
        acc[5] = fmaf(a, v1.y, acc[5]);
        acc[6] = fmaf(a, v1.z, acc[6]);
        acc[7] = fmaf(a, v1.w, acc[7]);
    }

    const float4 bg0 = *(const float4*)(bias_g + lane * 8);
    const float4 bg1 = *(const float4*)(bias_g + lane * 8 + 4);
    float* op = out + (size_t)d * HC + lane * 8;
    *(float4*)op       = make_float4(acc[0] + bg0.x, acc[1] + bg0.y,
                                     acc[2] + bg0.z, acc[3] + bg0.w);
    *(float4*)(op + 4) = make_float4(acc[4] + bg1.x, acc[5] + bg1.y,
                                     acc[6] + bg1.z, acc[7] + bg1.w);
}

// ---------------- launch --------------------------------------------------------
extern "C" void kernel_launch(void* const* d_in, const int* in_sizes, int n_in,
                              void* d_out, int out_size) {
    const float* x   = (const float*)d_in[0];
    const int*   ei  = (const int*)d_in[1];
    const float* W1  = (const float*)d_in[2];
    const float* b1  = (const float*)d_in[3];
    const float* W2  = (const float*)d_in[4];
    const float* b2  = (const float*)d_in[5];
    const float* Wg  = (const float*)d_in[6];
    const float* att_src = (const float*)d_in[7];
    const float* att_dst = (const float*)d_in[8];
    const float* bias_g  = (const float*)d_in[9];
    float* out = (float*)d_out;

    __nv_bfloat16 *xhi, *xlo;
    __nv_bfloat16 *w1thi, *w1tlo, *w2thi, *w2tlo, *wgthi, *wgtlo;
    float *xg, *asrcp, *adstp;
    int* cntp;
    cudaGetSymbolAddress((void**)&xhi,  g_xhi);
    cudaGetSymbolAddress((void**)&xlo,  g_xlo);
    cudaGetSymbolAddress((void**)&w1thi, g_w1thi);
    cudaGetSymbolAddress((void**)&w1tlo, g_w1tlo);
    cudaGetSymbolAddress((void**)&w2thi, g_w2thi);
    cudaGetSymbolAddress((void**)&w2tlo, g_w2tlo);
    cudaGetSymbolAddress((void**)&wgthi, g_wgthi);
    cudaGetSymbolAddress((void**)&wgtlo, g_wgtlo);
    cudaGetSymbolAddress((void**)&xg, g_xg);
    cudaGetSymbolAddress((void**)&asrcp, g_asrc);
    cudaGetSymbolAddress((void**)&adstp, g_adst);
    cudaGetSymbolAddress((void**)&cntp, g_cnt);

    const int SMEM_F = (2 * 64 * 136 + 2 * 128 * 40 * 2) * (int)sizeof(__nv_bfloat16); // 75776
    cudaFuncSetAttribute(gnn_mlp_kernel,
                         cudaFuncAttributeMaxDynamicSharedMemorySize, SMEM_F);

    const int mblk = (Nn + 63) / 64;   // 313

    // ---- fork: CSR build on side stream ----
    cudaEventRecord(g_e1, 0);
    cudaStreamWaitEvent(g_s2, g_e1, 0);
    cudaMemsetAsync(cntp, 0, Nn * sizeof(int), g_s2);
    count_kernel<<<(Ee + 255) / 256, 256, 0, g_s2>>>(ei);
    scan_kernel<<<1, 1024, 0, g_s2>>>();
    scatter_kernel<<<(TT + 255) / 256, 256, 0, g_s2>>>(ei);
    cudaEventRecord(g_e2, g_s2);

    // ---- main stream: att accumulator zero + splits + fully fused MLP+GAT-proj ----
    cudaMemsetAsync(asrcp, 0, Nn * Hh * sizeof(float));
    cudaMemsetAsync(adstp, 0, Nn * Hh * sizeof(float));
    split_prep_kernel<<<(SPLIT_TOTAL + 255) / 256, 256>>>(W1, W2, Wg, x);

    gnn_mlp_kernel<<<mblk, 256, SMEM_F>>>(
        xhi, xlo, w1thi, w1tlo, b1, w2thi, w2tlo, b2,
        wgthi, wgtlo, xg, att_src, att_dst, Nn);

    // ---- join: CSR must be done before aggregation ----
    cudaStreamWaitEvent(0, g_e2, 0);
    gat_agg_kernel<<<(Nn + 7) / 8, 256>>>(out, bias_g);
}